// round 5
// baseline (speedup 1.0000x reference)
#include <cuda_runtime.h>
#include <cuda_fp16.h>
#include <math.h>

namespace {

constexpr int N = 50000;
constexpr int E = 800000;
constexpr float AVG_D_LOG = 2.8332f;
constexpr float EPS_STD = 1e-5f;
constexpr float EPS_BN = 1e-5f;
constexpr float FLT_BIG = 3.402823466e+38f;
constexpr int PITCH = 130;     // k-major Xs pitch for 128-wide tiles

typedef unsigned long long ull;

__device__ __forceinline__ ull fma2(ull a, ull b, ull c) {
    ull d;
    asm("fma.rn.f32x2 %0,%1,%2,%3;" : "=l"(d) : "l"(a), "l"(b), "l"(c));
    return d;
}
__device__ __forceinline__ ull pack2(float x, float y) {
    ull d;
    asm("mov.b64 %0,{%1,%2};" : "=l"(d) : "f"(x), "f"(y));
    return d;
}
__device__ __forceinline__ float2 unpack2(ull v) {
    float2 r;
    asm("mov.b64 {%0,%1},%2;" : "=f"(r.x), "=f"(r.y) : "l"(v));
    return r;
}

// ---- scratch (device globals: allocation-free contract) ----
__device__ int g_deg[N];
__device__ int g_offs[N + 1];
__device__ int g_cursor[N];
__device__ int g_perm[E];
__device__ int g_srcs[E];
__device__ __align__(16) float g_A[(size_t)N * 128];     // [h@W1 | p@P1]
__device__ __align__(16) float g_B[(size_t)N * 128];     // [h@W2 | p@P2]
__device__ __align__(16) __half g_ce[(size_t)E * 128];   // [e@W3+bh | e@P3+bp] fp16, sorted
__device__ __align__(16) float g_aggh[(size_t)N * 256];  // [mean|max|min|std]
__device__ __align__(16) float g_aggp[(size_t)N * 256];
__device__ float g_amp[N];
__device__ float g_att[N];
__device__ float g_bnsum[64];
__device__ float g_bnsq[64];

// ---------------- init ----------------
__global__ void k_init() {
    int i = blockIdx.x * blockDim.x + threadIdx.x;
    if (i < N) g_deg[i] = 0;
    if (i < 64) { g_bnsum[i] = 0.f; g_bnsq[i] = 0.f; }
}

// ---------------- degree histogram ----------------
__global__ void k_hist(const int* __restrict__ dst) {
    int e = blockIdx.x * blockDim.x + threadIdx.x;
    if (e < E) atomicAdd(&g_deg[dst[e]], 1);
}

// ---------------- exclusive scan (single block) ----------------
__global__ void k_scan() {
    __shared__ int s[1024];
    int t = threadIdx.x;
    int carry = 0;
    for (int base = 0; base < N; base += 1024) {
        int v = (base + t < N) ? g_deg[base + t] : 0;
        s[t] = v;
        __syncthreads();
        for (int off = 1; off < 1024; off <<= 1) {
            int add = (t >= off) ? s[t - off] : 0;
            __syncthreads();
            s[t] += add;
            __syncthreads();
        }
        int incl = s[t];
        if (base + t < N) {
            int ex = carry + incl - v;
            g_offs[base + t] = ex;
            g_cursor[base + t] = ex;
        }
        carry += s[1023];
        __syncthreads();
    }
    if (t == 0) g_offs[N] = carry;
}

// ---------------- scatter: counting sort by dst ----------------
__global__ void k_scatter(const int* __restrict__ dst, const int* __restrict__ src) {
    int e = blockIdx.x * blockDim.x + threadIdx.x;
    if (e < E) {
        int pos = atomicAdd(&g_cursor[dst[e]], 1);
        g_perm[pos] = e;
        g_srcs[pos] = src[e];
    }
}

// ---------------- node pre-GEMMs: g_A=[h@W1|p@P1], g_B=[h@W2|p@P2] --------------
__global__ void __launch_bounds__(256) k_nodepre(
    const float* __restrict__ h, const float* __restrict__ p,
    const float* __restrict__ Wh, const float* __restrict__ Wp)
{
    __shared__ __align__(16) float Xs[32 * PITCH];
    __shared__ __align__(16) float Ws[32 * 128];

    int tid = threadIdx.x;
    int base = blockIdx.x * 128;

    int tx = tid & 15;
    int te = tid >> 4;
    int le = tid & 127;
    int lh = (tid >> 7) * 16;
    int wkk = tid >> 3;
    int woc = (tid & 7) * 16;

    int nl = base + le;
    bool okl = nl < N;

    ull acca[4][4], accb[4][4];

    // ===== h phase =====
#pragma unroll
    for (int i = 0; i < 4; i++)
#pragma unroll
        for (int j = 0; j < 4; j++) { acca[i][j] = 0ull; accb[i][j] = 0ull; }

    for (int t = 0; t < 4; t++) {
        int k0 = t * 32;
        const float* rowp = h + (size_t)nl * 128 + k0;
#pragma unroll
        for (int q = 0; q < 4; q++) {
            float4 a = okl ? *(const float4*)(rowp + lh + q * 4)
                           : make_float4(0.f, 0.f, 0.f, 0.f);
            Xs[(lh + q * 4 + 0) * PITCH + le] = a.x;
            Xs[(lh + q * 4 + 1) * PITCH + le] = a.y;
            Xs[(lh + q * 4 + 2) * PITCH + le] = a.z;
            Xs[(lh + q * 4 + 3) * PITCH + le] = a.w;
        }
        {
            const float* wr = (woc < 64) ? (Wh + (size_t)(k0 + wkk) * 64 + woc)
                                         : (Wh + (size_t)(128 + k0 + wkk) * 64 + (woc - 64));
#pragma unroll
            for (int q = 0; q < 4; q++)
                *(float4*)&Ws[wkk * 128 + woc + q * 4] = *(const float4*)(wr + q * 4);
        }
        __syncthreads();
#pragma unroll 16
        for (int kk = 0; kk < 32; kk++) {
            float4 wa = *(const float4*)&Ws[kk * 128 + tx * 4];
            float4 wb = *(const float4*)&Ws[kk * 128 + 64 + tx * 4];
            ull a0 = pack2(wa.x, wa.x), a1 = pack2(wa.y, wa.y);
            ull a2 = pack2(wa.z, wa.z), a3 = pack2(wa.w, wa.w);
            ull b0 = pack2(wb.x, wb.x), b1 = pack2(wb.y, wb.y);
            ull b2 = pack2(wb.z, wb.z), b3 = pack2(wb.w, wb.w);
            const ull* xp = (const ull*)&Xs[kk * PITCH + te * 8];
#pragma unroll
            for (int i = 0; i < 4; i++) {
                ull x = xp[i];
                acca[i][0] = fma2(x, a0, acca[i][0]);
                acca[i][1] = fma2(x, a1, acca[i][1]);
                acca[i][2] = fma2(x, a2, acca[i][2]);
                acca[i][3] = fma2(x, a3, acca[i][3]);
                accb[i][0] = fma2(x, b0, accb[i][0]);
                accb[i][1] = fma2(x, b1, accb[i][1]);
                accb[i][2] = fma2(x, b2, accb[i][2]);
                accb[i][3] = fma2(x, b3, accb[i][3]);
            }
        }
        __syncthreads();
    }
#pragma unroll
    for (int i = 0; i < 4; i++) {
        float2 a0 = unpack2(acca[i][0]), a1 = unpack2(acca[i][1]);
        float2 a2 = unpack2(acca[i][2]), a3 = unpack2(acca[i][3]);
        float2 b0 = unpack2(accb[i][0]), b1 = unpack2(accb[i][1]);
        float2 b2 = unpack2(accb[i][2]), b3 = unpack2(accb[i][3]);
        int n0 = base + te * 8 + 2 * i;
        if (n0 < N) {
            *(float4*)&g_A[(size_t)n0 * 128 + tx * 4] = make_float4(a0.x, a1.x, a2.x, a3.x);
            *(float4*)&g_B[(size_t)n0 * 128 + tx * 4] = make_float4(b0.x, b1.x, b2.x, b3.x);
        }
        if (n0 + 1 < N) {
            *(float4*)&g_A[(size_t)(n0 + 1) * 128 + tx * 4] = make_float4(a0.y, a1.y, a2.y, a3.y);
            *(float4*)&g_B[(size_t)(n0 + 1) * 128 + tx * 4] = make_float4(b0.y, b1.y, b2.y, b3.y);
        }
    }

    // ===== p phase =====
#pragma unroll
    for (int i = 0; i < 4; i++)
#pragma unroll
        for (int j = 0; j < 4; j++) { acca[i][j] = 0ull; accb[i][j] = 0ull; }

    for (int t = 0; t < 2; t++) {
        int k0 = t * 32;
        const float* rowp = p + (size_t)nl * 64 + k0;
#pragma unroll
        for (int q = 0; q < 4; q++) {
            float4 a = okl ? *(const float4*)(rowp + lh + q * 4)
                           : make_float4(0.f, 0.f, 0.f, 0.f);
            Xs[(lh + q * 4 + 0) * PITCH + le] = a.x;
            Xs[(lh + q * 4 + 1) * PITCH + le] = a.y;
            Xs[(lh + q * 4 + 2) * PITCH + le] = a.z;
            Xs[(lh + q * 4 + 3) * PITCH + le] = a.w;
        }
        {
            const float* wr = (woc < 64) ? (Wp + (size_t)(k0 + wkk) * 64 + woc)
                                         : (Wp + (size_t)(64 + k0 + wkk) * 64 + (woc - 64));
#pragma unroll
            for (int q = 0; q < 4; q++)
                *(float4*)&Ws[wkk * 128 + woc + q * 4] = *(const float4*)(wr + q * 4);
        }
        __syncthreads();
#pragma unroll 16
        for (int kk = 0; kk < 32; kk++) {
            float4 wa = *(const float4*)&Ws[kk * 128 + tx * 4];
            float4 wb = *(const float4*)&Ws[kk * 128 + 64 + tx * 4];
            ull a0 = pack2(wa.x, wa.x), a1 = pack2(wa.y, wa.y);
            ull a2 = pack2(wa.z, wa.z), a3 = pack2(wa.w, wa.w);
            ull b0 = pack2(wb.x, wb.x), b1 = pack2(wb.y, wb.y);
            ull b2 = pack2(wb.z, wb.z), b3 = pack2(wb.w, wb.w);
            const ull* xp = (const ull*)&Xs[kk * PITCH + te * 8];
#pragma unroll
            for (int i = 0; i < 4; i++) {
                ull x = xp[i];
                acca[i][0] = fma2(x, a0, acca[i][0]);
                acca[i][1] = fma2(x, a1, acca[i][1]);
                acca[i][2] = fma2(x, a2, acca[i][2]);
                acca[i][3] = fma2(x, a3, acca[i][3]);
                accb[i][0] = fma2(x, b0, accb[i][0]);
                accb[i][1] = fma2(x, b1, accb[i][1]);
                accb[i][2] = fma2(x, b2, accb[i][2]);
                accb[i][3] = fma2(x, b3, accb[i][3]);
            }
        }
        __syncthreads();
    }
#pragma unroll
    for (int i = 0; i < 4; i++) {
        float2 a0 = unpack2(acca[i][0]), a1 = unpack2(acca[i][1]);
        float2 a2 = unpack2(acca[i][2]), a3 = unpack2(acca[i][3]);
        float2 b0 = unpack2(accb[i][0]), b1 = unpack2(accb[i][1]);
        float2 b2 = unpack2(accb[i][2]), b3 = unpack2(accb[i][3]);
        int n0 = base + te * 8 + 2 * i;
        if (n0 < N) {
            *(float4*)&g_A[(size_t)n0 * 128 + 64 + tx * 4] = make_float4(a0.x, a1.x, a2.x, a3.x);
            *(float4*)&g_B[(size_t)n0 * 128 + 64 + tx * 4] = make_float4(b0.x, b1.x, b2.x, b3.x);
        }
        if (n0 + 1 < N) {
            *(float4*)&g_A[(size_t)(n0 + 1) * 128 + 64 + tx * 4] = make_float4(a0.y, a1.y, a2.y, a3.y);
            *(float4*)&g_B[(size_t)(n0 + 1) * 128 + 64 + tx * 4] = make_float4(b0.y, b1.y, b2.y, b3.y);
        }
    }
}

// ---------------- edge-feature GEMM -> fp16 interleaved messages ----------------
__global__ void __launch_bounds__(256) k_edgeE(
    const float* __restrict__ ef,
    const float* __restrict__ Wh, const float* __restrict__ bh,
    const float* __restrict__ Wp, const float* __restrict__ bp)
{
    __shared__ __align__(16) float Xs[32 * PITCH];
    __shared__ __align__(16) float Ws[32 * 128];
    __shared__ int s_eid[128];

    int tid = threadIdx.x;
    int base = blockIdx.x * 128;

    for (int j = tid; j < 128; j += 256) s_eid[j] = g_perm[base + j];

    int tx = tid & 15;
    int te = tid >> 4;
    int le = tid & 127;
    int lh = (tid >> 7) * 16;
    int wkk = tid >> 3;
    int woc = (tid & 7) * 16;

    {
        const float* wr = (woc < 64) ? (Wh + (size_t)(256 + wkk) * 64 + woc)
                                     : (Wp + (size_t)(128 + wkk) * 64 + (woc - 64));
#pragma unroll
        for (int q = 0; q < 4; q++)
            *(float4*)&Ws[wkk * 128 + woc + q * 4] = *(const float4*)(wr + q * 4);
    }
    __syncthreads();
    {
        const float* rowp = ef + (size_t)s_eid[le] * 32;
#pragma unroll
        for (int q = 0; q < 4; q++) {
            float4 a = *(const float4*)(rowp + lh + q * 4);
            Xs[(lh + q * 4 + 0) * PITCH + le] = a.x;
            Xs[(lh + q * 4 + 1) * PITCH + le] = a.y;
            Xs[(lh + q * 4 + 2) * PITCH + le] = a.z;
            Xs[(lh + q * 4 + 3) * PITCH + le] = a.w;
        }
    }
    __syncthreads();

    ull acca[4][4], accb[4][4];
#pragma unroll
    for (int i = 0; i < 4; i++)
#pragma unroll
        for (int j = 0; j < 4; j++) { acca[i][j] = 0ull; accb[i][j] = 0ull; }

#pragma unroll 16
    for (int kk = 0; kk < 32; kk++) {
        float4 wa = *(const float4*)&Ws[kk * 128 + tx * 4];
        float4 wb = *(const float4*)&Ws[kk * 128 + 64 + tx * 4];
        ull a0 = pack2(wa.x, wa.x), a1 = pack2(wa.y, wa.y);
        ull a2 = pack2(wa.z, wa.z), a3 = pack2(wa.w, wa.w);
        ull b0 = pack2(wb.x, wb.x), b1 = pack2(wb.y, wb.y);
        ull b2 = pack2(wb.z, wb.z), b3 = pack2(wb.w, wb.w);
        const ull* xp = (const ull*)&Xs[kk * PITCH + te * 8];
#pragma unroll
        for (int i = 0; i < 4; i++) {
            ull x = xp[i];
            acca[i][0] = fma2(x, a0, acca[i][0]);
            acca[i][1] = fma2(x, a1, acca[i][1]);
            acca[i][2] = fma2(x, a2, acca[i][2]);
            acca[i][3] = fma2(x, a3, acca[i][3]);
            accb[i][0] = fma2(x, b0, accb[i][0]);
            accb[i][1] = fma2(x, b1, accb[i][1]);
            accb[i][2] = fma2(x, b2, accb[i][2]);
            accb[i][3] = fma2(x, b3, accb[i][3]);
        }
    }

    float4 biash = *(const float4*)&bh[tx * 4];
    float4 biasp = *(const float4*)&bp[tx * 4];
#pragma unroll
    for (int i = 0; i < 4; i++) {
        float2 a0 = unpack2(acca[i][0]), a1 = unpack2(acca[i][1]);
        float2 a2 = unpack2(acca[i][2]), a3 = unpack2(acca[i][3]);
        float2 b0 = unpack2(accb[i][0]), b1 = unpack2(accb[i][1]);
        float2 b2 = unpack2(accb[i][2]), b3 = unpack2(accb[i][3]);
        int pos = base + te * 8 + 2 * i;
        __half* r0 = g_ce + (size_t)pos * 128;
        __half* r1 = g_ce + (size_t)(pos + 1) * 128;
        {
            __half2 lo = __floats2half2_rn(a0.x + biash.x, a1.x + biash.y);
            __half2 hi = __floats2half2_rn(a2.x + biash.z, a3.x + biash.w);
            *(__half2*)(r0 + tx * 4) = lo; *(__half2*)(r0 + tx * 4 + 2) = hi;
            lo = __floats2half2_rn(a0.y + biash.x, a1.y + biash.y);
            hi = __floats2half2_rn(a2.y + biash.z, a3.y + biash.w);
            *(__half2*)(r1 + tx * 4) = lo; *(__half2*)(r1 + tx * 4 + 2) = hi;
        }
        {
            __half2 lo = __floats2half2_rn(b0.x + biasp.x, b1.x + biasp.y);
            __half2 hi = __floats2half2_rn(b2.x + biasp.z, b3.x + biasp.w);
            *(__half2*)(r0 + 64 + tx * 4) = lo; *(__half2*)(r0 + 64 + tx * 4 + 2) = hi;
            lo = __floats2half2_rn(b0.y + biasp.x, b1.y + biasp.y);
            hi = __floats2half2_rn(b2.y + biasp.z, b3.y + biasp.w);
            *(__half2*)(r1 + 64 + tx * 4) = lo; *(__half2*)(r1 + 64 + tx * 4 + 2) = hi;
        }
    }
}

// ---------------- fused message + PNA aggregation (warp per node) -------------
__global__ void k_agg() {
    int warp = (blockIdx.x * blockDim.x + threadIdx.x) >> 5;
    int l = threadIdx.x & 31;
    if (warp >= N) return;
    int n = warp;
    int s0 = g_offs[n];
    int s1 = g_offs[n + 1];
    int d = s1 - s0;

    const float* brow = g_B + (size_t)n * 128;
    float bh0 = brow[l];
    float bh1 = brow[l + 32];
    float bp0 = brow[l + 64];
    float bp1 = brow[l + 96];

    float sm[4] = {0.f, 0.f, 0.f, 0.f};
    float sq[4] = {0.f, 0.f, 0.f, 0.f};
    float mx[4] = {-FLT_BIG, -FLT_BIG, -FLT_BIG, -FLT_BIG};
    float mn[4] = {FLT_BIG, FLT_BIG, FLT_BIG, FLT_BIG};

    for (int i = s0; i < s1; i++) {
        int s = g_srcs[i];
        const float* a = g_A + (size_t)s * 128;
        const __half* c = g_ce + (size_t)i * 128;
        float v0 = __half2float(c[l])      + a[l]      + bh0;
        float v1 = __half2float(c[l + 32]) + a[l + 32] + bh1;
        float v2 = __half2float(c[l + 64]) + a[l + 64] + bp0;
        float v3 = __half2float(c[l + 96]) + a[l + 96] + bp1;
        sm[0] += v0; sq[0] += v0 * v0; mx[0] = fmaxf(mx[0], v0); mn[0] = fminf(mn[0], v0);
        sm[1] += v1; sq[1] += v1 * v1; mx[1] = fmaxf(mx[1], v1); mn[1] = fminf(mn[1], v1);
        sm[2] += v2; sq[2] += v2 * v2; mx[2] = fmaxf(mx[2], v2); mn[2] = fminf(mn[2], v2);
        sm[3] += v3; sq[3] += v3 * v3; mx[3] = fmaxf(mx[3], v3); mn[3] = fminf(mn[3], v3);
    }

    float degc = fmaxf((float)d, 1.f);
    float inv = 1.f / degc;
    bool has = d > 0;
    float logd = has ? logf((float)d + 1.f) : 1.f;
    float amp = logd / AVG_D_LOG;
    float att = AVG_D_LOG / logd;
    if (l == 0) { g_amp[n] = amp; g_att[n] = att; }

    float* outh = g_aggh + (size_t)n * 256;
    float* outp = g_aggp + (size_t)n * 256;

#pragma unroll
    for (int c = 0; c < 4; c++) {
        float mean = sm[c] * inv;
        float var = fmaxf(sq[c] * inv - mean * mean, 0.f);
        float sd = sqrtf(var + EPS_STD);
        float MX = has ? mx[c] : 0.f;
        float MN = has ? mn[c] : 0.f;
        float* o = (c < 2) ? outh : outp;
        int f = l + ((c & 1) ? 32 : 0);
        o[f] = mean; o[64 + f] = MX; o[128 + f] = MN; o[192 + f] = sd;
    }
}

// ---------------- node GEMMs: packed smem weights, 3 rails, fused BN stats --------
// dynamic smem: WsI|WsA|WsT (2048 ull each) + Xs (2048 f) + sbn/sbq (512 f each)
constexpr int SMEM_NG = 3 * 2048 * 8 + 2048 * 4 + 2 * 512 * 4;

__global__ void __launch_bounds__(256) k_nodegemm(
    const float* __restrict__ h, const float* __restrict__ p,
    const float* __restrict__ snorm,
    const float* __restrict__ Woh, const float* __restrict__ boh,
    const float* __restrict__ Wop, const float* __restrict__ bop,
    float* __restrict__ out)
{
    extern __shared__ __align__(16) char smraw[];
    ull* WsI = (ull*)smraw;
    ull* WsA = WsI + 2048;
    ull* WsT = WsA + 2048;
    float* Xs = (float*)(WsT + 2048);
    float* sbn = Xs + 2048;
    float* sbq = sbn + 512;

    int tid = threadIdx.x;
    int base = blockIdx.x * 64;

    int tx = tid & 31;          // outs 2tx, 2tx+1
    int te = tid >> 5;          // nodes te*8 .. te*8+7
    int le = tid & 63;
    int lh = (tid >> 6) * 8;
    int wkk = tid >> 3;
    int woc = (tid & 7) * 8;

    int nl = base + le;
    bool okl = nl < N;

    ull accI[4][2], accA[4][2], accT[4][2];

    // =================== phase H: base K=128 (4 tiles) + agg K=256 (8 tiles) =========
#pragma unroll
    for (int i = 0; i < 4; i++)
#pragma unroll
        for (int j = 0; j < 2; j++) { accI[i][j] = 0ull; accA[i][j] = 0ull; accT[i][j] = 0ull; }

    for (int t = 0; t < 12; t++) {
        int k0 = t * 32;
        bool isAgg = (t >= 4);
        const float* rowp = isAgg ? (g_aggh + (size_t)nl * 256 + (k0 - 128))
                                  : (h + (size_t)nl * 128 + k0);
#pragma unroll
        for (int q = 0; q < 2; q++) {
            float4 a = okl ? *(const float4*)(rowp + lh + q * 4)
                           : make_float4(0.f, 0.f, 0.f, 0.f);
            Xs[(lh + q * 4 + 0) * 64 + le] = a.x;
            Xs[(lh + q * 4 + 1) * 64 + le] = a.y;
            Xs[(lh + q * 4 + 2) * 64 + le] = a.z;
            Xs[(lh + q * 4 + 3) * 64 + le] = a.w;
        }
        if (isAgg) {
            int aggk = k0 - 128;
            const float* wI = Woh + (size_t)(128 + aggk + wkk) * 64 + woc;
            const float* wA = Woh + (size_t)(384 + aggk + wkk) * 64 + woc;
            const float* wT = Woh + (size_t)(640 + aggk + wkk) * 64 + woc;
            float4 u = *(const float4*)(wI), v = *(const float4*)(wI + 4);
            WsI[wkk * 64 + woc + 0] = pack2(u.x, u.x); WsI[wkk * 64 + woc + 1] = pack2(u.y, u.y);
            WsI[wkk * 64 + woc + 2] = pack2(u.z, u.z); WsI[wkk * 64 + woc + 3] = pack2(u.w, u.w);
            WsI[wkk * 64 + woc + 4] = pack2(v.x, v.x); WsI[wkk * 64 + woc + 5] = pack2(v.y, v.y);
            WsI[wkk * 64 + woc + 6] = pack2(v.z, v.z); WsI[wkk * 64 + woc + 7] = pack2(v.w, v.w);
            u = *(const float4*)(wA); v = *(const float4*)(wA + 4);
            WsA[wkk * 64 + woc + 0] = pack2(u.x, u.x); WsA[wkk * 64 + woc + 1] = pack2(u.y, u.y);
            WsA[wkk * 64 + woc + 2] = pack2(u.z, u.z); WsA[wkk * 64 + woc + 3] = pack2(u.w, u.w);
            WsA[wkk * 64 + woc + 4] = pack2(v.x, v.x); WsA[wkk * 64 + woc + 5] = pack2(v.y, v.y);
            WsA[wkk * 64 + woc + 6] = pack2(v.z, v.z); WsA[wkk * 64 + woc + 7] = pack2(v.w, v.w);
            u = *(const float4*)(wT); v = *(const float4*)(wT + 4);
            WsT[wkk * 64 + woc + 0] = pack2(u.x, u.x); WsT[wkk * 64 + woc + 1] = pack2(u.y, u.y);
            WsT[wkk * 64 + woc + 2] = pack2(u.z, u.z); WsT[wkk * 64 + woc + 3] = pack2(u.w, u.w);
            WsT[wkk * 64 + woc + 4] = pack2(v.x, v.x); WsT[wkk * 64 + woc + 5] = pack2(v.y, v.y);
            WsT[wkk * 64 + woc + 6] = pack2(v.z, v.z); WsT[wkk * 64 + woc + 7] = pack2(v.w, v.w);
        } else {
            const float* wI = Woh + (size_t)(k0 + wkk) * 64 + woc;
            float4 u = *(const float4*)(wI), v = *(const float4*)(wI + 4);
            WsI[wkk * 64 + woc + 0] = pack2(u.x, u.x); WsI[wkk * 64 + woc + 1] = pack2(u.y, u.y);
            WsI[wkk * 64 + woc + 2] = pack2(u.z, u.z); WsI[wkk * 64 + woc + 3] = pack2(u.w, u.w);
            WsI[wkk * 64 + woc + 4] = pack2(v.x, v.x); WsI[wkk * 64 + woc + 5] = pack2(v.y, v.y);
            WsI[wkk * 64 + woc + 6] = pack2(v.z, v.z); WsI[wkk * 64 + woc + 7] = pack2(v.w, v.w);
        }
        __syncthreads();
        if (isAgg) {
#pragma unroll 8
            for (int kk = 0; kk < 32; kk++) {
                ulonglong2 wi = *(const ulonglong2*)&WsI[kk * 64 + tx * 2];
                ulonglong2 wa = *(const ulonglong2*)&WsA[kk * 64 + tx * 2];
                ulonglong2 wt = *(const ulonglong2*)&WsT[kk * 64 + tx * 2];
                const ull* xp = (const ull*)&Xs[kk * 64 + te * 8];
#pragma unroll
                for (int i = 0; i < 4; i++) {
                    ull x = xp[i];
                    accI[i][0] = fma2(x, wi.x, accI[i][0]);
                    accI[i][1] = fma2(x, wi.y, accI[i][1]);
                    accA[i][0] = fma2(x, wa.x, accA[i][0]);
                    accA[i][1] = fma2(x, wa.y, accA[i][1]);
                    accT[i][0] = fma2(x, wt.x, accT[i][0]);
                    accT[i][1] = fma2(x, wt.y, accT[i][1]);
                }
            }
        } else {
#pragma unroll 8
            for (int kk = 0; kk < 32; kk++) {
                ulonglong2 wi = *(const ulonglong2*)&WsI[kk * 64 + tx * 2];
                const ull* xp = (const ull*)&Xs[kk * 64 + te * 8];
#pragma unroll
                for (int i = 0; i < 4; i++) {
                    ull x = xp[i];
                    accI[i][0] = fma2(x, wi.x, accI[i][0]);
                    accI[i][1] = fma2(x, wi.y, accI[i][1]);
                }
            }
        }
        __syncthreads();
    }
    {
        float2 bias = *(const float2*)&boh[tx * 2];
        float s0 = 0.f, q0 = 0.f, s1 = 0.f, q1 = 0.f;
#pragma unroll
        for (int i = 0; i < 4; i++) {
            int n0 = base + te * 8 + 2 * i;
            float am0 = (n0 < N) ? g_amp[n0] : 0.f;
            float am1 = (n0 + 1 < N) ? g_amp[n0 + 1] : 0.f;
            float at0 = (n0 < N) ? g_att[n0] : 0.f;
            float at1 = (n0 + 1 < N) ? g_att[n0 + 1] : 0.f;
            ull ampP = pack2(am0, am1), attP = pack2(at0, at1);
            ull y0 = fma2(attP, accT[i][0], fma2(ampP, accA[i][0], accI[i][0]));
            ull y1 = fma2(attP, accT[i][1], fma2(ampP, accA[i][1], accI[i][1]));
            float2 u0 = unpack2(y0), u1 = unpack2(y1);
            if (n0 < N) {
                float sn = snorm[n0];
                float o0 = (u0.x + bias.x) * sn, o1 = (u1.x + bias.y) * sn;
                *(float2*)&out[(size_t)n0 * 64 + tx * 2] = make_float2(o0, o1);
                s0 += o0; q0 += o0 * o0; s1 += o1; q1 += o1 * o1;
            }
            if (n0 + 1 < N) {
                float sn = snorm[n0 + 1];
                float o0 = (u0.y + bias.x) * sn, o1 = (u1.y + bias.y) * sn;
                *(float2*)&out[(size_t)(n0 + 1) * 64 + tx * 2] = make_float2(o0, o1);
                s0 += o0; q0 += o0 * o0; s1 += o1; q1 += o1 * o1;
            }
        }
        sbn[te * 64 + 2 * tx] = s0; sbn[te * 64 + 2 * tx + 1] = s1;
        sbq[te * 64 + 2 * tx] = q0; sbq[te * 64 + 2 * tx + 1] = q1;
        __syncthreads();
        if (tid < 64) {
            float S = 0.f, Q = 0.f;
#pragma unroll
            for (int r = 0; r < 8; r++) { S += sbn[r * 64 + tid]; Q += sbq[r * 64 + tid]; }
            atomicAdd(&g_bnsum[tid], S);
            atomicAdd(&g_bnsq[tid], Q);
        }
        __syncthreads();
    }

    // =================== phase P: base K=64 (2 tiles) + agg K=256 (8 tiles) ==========
#pragma unroll
    for (int i = 0; i < 4; i++)
#pragma unroll
        for (int j = 0; j < 2; j++) { accI[i][j] = 0ull; accA[i][j] = 0ull; accT[i][j] = 0ull; }

    for (int t = 0; t < 10; t++) {
        int k0 = t * 32;
        bool isAgg = (t >= 2);
        const float* rowp = isAgg ? (g_aggp + (size_t)nl * 256 + (k0 - 64))
                                  : (p + (size_t)nl * 64 + k0);
#pragma unroll
        for (int q = 0; q < 2; q++) {
            float4 a = okl ? *(const float4*)(rowp + lh + q * 4)
                           : make_float4(0.f, 0.f, 0.f, 0.f);
            Xs[(lh + q * 4 + 0) * 64 + le] = a.x;
            Xs[(lh + q * 4 + 1) * 64 + le] = a.y;
            Xs[(lh + q * 4 + 2) * 64 + le] = a.z;
            Xs[(lh + q * 4 + 3) * 64 + le] = a.w;
        }
        if (isAgg) {
            int aggk = k0 - 64;
            const float* wI = Wop + (size_t)(64 + aggk + wkk) * 64 + woc;
            const float* wA = Wop + (size_t)(320 + aggk + wkk) * 64 + woc;
            const float* wT = Wop + (size_t)(576 + aggk + wkk) * 64 + woc;
            float4 u = *(const float4*)(wI), v = *(const float4*)(wI + 4);
            WsI[wkk * 64 + woc + 0] = pack2(u.x, u.x); WsI[wkk * 64 + woc + 1] = pack2(u.y, u.y);
            WsI[wkk * 64 + woc + 2] = pack2(u.z, u.z); WsI[wkk * 64 + woc + 3] = pack2(u.w, u.w);
            WsI[wkk * 64 + woc + 4] = pack2(v.x, v.x); WsI[wkk * 64 + woc + 5] = pack2(v.y, v.y);
            WsI[wkk * 64 + woc + 6] = pack2(v.z, v.z); WsI[wkk * 64 + woc + 7] = pack2(v.w, v.w);
            u = *(const float4*)(wA); v = *(const float4*)(wA + 4);
            WsA[wkk * 64 + woc + 0] = pack2(u.x, u.x); WsA[wkk * 64 + woc + 1] = pack2(u.y, u.y);
            WsA[wkk * 64 + woc + 2] = pack2(u.z, u.z); WsA[wkk * 64 + woc + 3] = pack2(u.w, u.w);
            WsA[wkk * 64 + woc + 4] = pack2(v.x, v.x); WsA[wkk * 64 + woc + 5] = pack2(v.y, v.y);
            WsA[wkk * 64 + woc + 6] = pack2(v.z, v.z); WsA[wkk * 64 + woc + 7] = pack2(v.w, v.w);
            u = *(const float4*)(wT); v = *(const float4*)(wT + 4);
            WsT[wkk * 64 + woc + 0] = pack2(u.x, u.x); WsT[wkk * 64 + woc + 1] = pack2(u.y, u.y);
            WsT[wkk * 64 + woc + 2] = pack2(u.z, u.z); WsT[wkk * 64 + woc + 3] = pack2(u.w, u.w);
            WsT[wkk * 64 + woc + 4] = pack2(v.x, v.x); WsT[wkk * 64 + woc + 5] = pack2(v.y, v.y);
            WsT[wkk * 64 + woc + 6] = pack2(v.z, v.z); WsT[wkk * 64 + woc + 7] = pack2(v.w, v.w);
        } else {
            const float* wI = Wop + (size_t)(k0 + wkk) * 64 + woc;
            float4 u = *(const float4*)(wI), v = *(const float4*)(wI + 4);
            WsI[wkk * 64 + woc + 0] = pack2(u.x, u.x); WsI[wkk * 64 + woc + 1] = pack2(u.y, u.y);
            WsI[wkk * 64 + woc + 2] = pack2(u.z, u.z); WsI[wkk * 64 + woc + 3] = pack2(u.w, u.w);
            WsI[wkk * 64 + woc + 4] = pack2(v.x, v.x); WsI[wkk * 64 + woc + 5] = pack2(v.y, v.y);
            WsI[wkk * 64 + woc + 6] = pack2(v.z, v.z); WsI[wkk * 64 + woc + 7] = pack2(v.w, v.w);
        }
        __syncthreads();
        if (isAgg) {
#pragma unroll 8
            for (int kk = 0; kk < 32; kk++) {
                ulonglong2 wi = *(const ulonglong2*)&WsI[kk * 64 + tx * 2];
                ulonglong2 wa = *(const ulonglong2*)&WsA[kk * 64 + tx * 2];
                ulonglong2 wt = *(const ulonglong2*)&WsT[kk * 64 + tx * 2];
                const ull* xp = (const ull*)&Xs[kk * 64 + te * 8];
#pragma unroll
                for (int i = 0; i < 4; i++) {
                    ull x = xp[i];
                    accI[i][0] = fma2(x, wi.x, accI[i][0]);
                    accI[i][1] = fma2(x, wi.y, accI[i][1]);
                    accA[i][0] = fma2(x, wa.x, accA[i][0]);
                    accA[i][1] = fma2(x, wa.y, accA[i][1]);
                    accT[i][0] = fma2(x, wt.x, accT[i][0]);
                    accT[i][1] = fma2(x, wt.y, accT[i][1]);
                }
            }
        } else {
#pragma unroll 8
            for (int kk = 0; kk < 32; kk++) {
                ulonglong2 wi = *(const ulonglong2*)&WsI[kk * 64 + tx * 2];
                const ull* xp = (const ull*)&Xs[kk * 64 + te * 8];
#pragma unroll
                for (int i = 0; i < 4; i++) {
                    ull x = xp[i];
                    accI[i][0] = fma2(x, wi.x, accI[i][0]);
                    accI[i][1] = fma2(x, wi.y, accI[i][1]);
                }
            }
        }
        __syncthreads();
    }
    {
        float2 bias = *(const float2*)&bop[tx * 2];
        float* outp = out + (size_t)N * 64;
#pragma unroll
        for (int i = 0; i < 4; i++) {
            int n0 = base + te * 8 + 2 * i;
            float am0 = (n0 < N) ? g_amp[n0] : 0.f;
            float am1 = (n0 + 1 < N) ? g_amp[n0 + 1] : 0.f;
            float at0 = (n0 < N) ? g_att[n0] : 0.f;
            float at1 = (n0 + 1 < N) ? g_att[n0 + 1] : 0.f;
            ull ampP = pack2(am0, am1), attP = pack2(at0, at1);
            ull y0 = fma2(attP, accT[i][0], fma2(ampP, accA[i][0], accI[i][0]));
            ull y1 = fma2(attP, accT[i][1], fma2(ampP, accA[i][1], accI[i][1]));
            float2 u0 = unpack2(y0), u1 = unpack2(y1);
            if (n0 < N)
                *(float2*)&outp[(size_t)n0 * 64 + tx * 2] =
                    make_float2(u0.x + bias.x, u1.x + bias.y);
            if (n0 + 1 < N)
                *(float2*)&outp[(size_t)(n0 + 1) * 64 + tx * 2] =
                    make_float2(u0.y + bias.x, u1.y + bias.y);
        }
    }
}

// ---------------- batchnorm apply ----------------
__global__ void k_bnapply(float* __restrict__ out,
                          const float* __restrict__ gamma,
                          const float* __restrict__ beta) {
    int i = blockIdx.x * blockDim.x + threadIdx.x;
    if (i >= N * 64) return;
    int f = i & 63;
    const float invN = 1.f / (float)N;
    float mu = g_bnsum[f] * invN;
    float var = g_bnsq[f] * invN - mu * mu;
    float x = out[i];
    out[i] = (x - mu) * rsqrtf(var + EPS_BN) * gamma[f] + beta[f];
}

} // namespace

extern "C" void kernel_launch(void* const* d_in, const int* in_sizes, int n_in,
                              void* d_out, int out_size) {
    const float* h     = (const float*)d_in[0];
    const float* p     = (const float*)d_in[1];
    const float* e     = (const float*)d_in[2];
    const int*   src   = (const int*)d_in[3];
    const int*   dst   = (const int*)d_in[4];
    const float* snorm = (const float*)d_in[5];
    const float* Wph   = (const float*)d_in[6];
    const float* bph   = (const float*)d_in[7];
    const float* Wpp   = (const float*)d_in[8];
    const float* bpp   = (const float*)d_in[9];
    const float* Woh   = (const float*)d_in[10];
    const float* boh   = (const float*)d_in[11];
    const float* Wop   = (const float*)d_in[12];
    const float* bop   = (const float*)d_in[13];
    const float* gamma = (const float*)d_in[14];
    const float* beta  = (const float*)d_in[15];
    float* out = (float*)d_out;

    static bool attr_set = false;
    if (!attr_set) {
        cudaFuncSetAttribute(k_nodegemm, cudaFuncAttributeMaxDynamicSharedMemorySize, SMEM_NG);
        attr_set = true;
    }

    k_init<<<(N + 255) / 256, 256>>>();
    k_hist<<<(E + 255) / 256, 256>>>(dst);
    k_scan<<<1, 1024>>>();
    k_scatter<<<(E + 255) / 256, 256>>>(dst, src);
    k_nodepre<<<(N + 127) / 128, 256>>>(h, p, Wph, Wpp);
    k_edgeE<<<E / 128, 256>>>(e, Wph, bph, Wpp, bpp);
    k_agg<<<(N * 32 + 255) / 256, 256>>>();
    k_nodegemm<<<(N + 63) / 64, 256, SMEM_NG>>>(h, p, snorm, Woh, boh, Wop, bop, out);
    k_bnapply<<<(N * 64 + 255) / 256, 256>>>(out, gamma, beta);
}

// round 6
// speedup vs baseline: 1.1765x; 1.1765x over previous
#include <cuda_runtime.h>
#include <cuda_fp16.h>
#include <math.h>

namespace {

constexpr int N = 50000;
constexpr int E = 800000;
constexpr float AVG_D_LOG = 2.8332f;
constexpr float EPS_STD = 1e-5f;
constexpr float EPS_BN = 1e-5f;
constexpr float FLT_BIG = 3.402823466e+38f;
constexpr int PITCH = 130;     // k-major Xs pitch for 128-wide tiles

typedef unsigned long long ull;

__device__ __forceinline__ ull fma2(ull a, ull b, ull c) {
    ull d;
    asm("fma.rn.f32x2 %0,%1,%2,%3;" : "=l"(d) : "l"(a), "l"(b), "l"(c));
    return d;
}
__device__ __forceinline__ ull pack2(float x, float y) {
    ull d;
    asm("mov.b64 %0,{%1,%2};" : "=l"(d) : "f"(x), "f"(y));
    return d;
}
__device__ __forceinline__ float2 unpack2(ull v) {
    float2 r;
    asm("mov.b64 {%0,%1},%2;" : "=f"(r.x), "=f"(r.y) : "l"(v));
    return r;
}

// ---- scratch (device globals: allocation-free contract) ----
__device__ int g_deg[N];
__device__ int g_offs[N + 1];
__device__ int g_cursor[N];
__device__ int g_perm[E];
__device__ int g_srcs[E];
__device__ __align__(16) float g_A[(size_t)N * 128];     // [h@W1 | p@P1]
__device__ __align__(16) float g_B[(size_t)N * 128];     // [h@W2 | p@P2]
__device__ __align__(16) __half g_ce[(size_t)E * 128];   // [e@W3+bh | e@P3+bp] fp16, sorted
__device__ __align__(16) float g_aggh[(size_t)N * 256];  // [mean|max|min|std]
__device__ __align__(16) float g_aggp[(size_t)N * 256];
__device__ float g_amp[N];
__device__ float g_att[N];
__device__ float g_bnsum[64];
__device__ float g_bnsq[64];

// ---------------- init ----------------
__global__ void k_init() {
    int i = blockIdx.x * blockDim.x + threadIdx.x;
    if (i < N) g_deg[i] = 0;
    if (i < 64) { g_bnsum[i] = 0.f; g_bnsq[i] = 0.f; }
}

// ---------------- degree histogram ----------------
__global__ void k_hist(const int* __restrict__ dst) {
    int e = blockIdx.x * blockDim.x + threadIdx.x;
    if (e < E) atomicAdd(&g_deg[dst[e]], 1);
}

// ---------------- exclusive scan (single block) ----------------
__global__ void k_scan() {
    __shared__ int s[1024];
    int t = threadIdx.x;
    int carry = 0;
    for (int base = 0; base < N; base += 1024) {
        int v = (base + t < N) ? g_deg[base + t] : 0;
        s[t] = v;
        __syncthreads();
        for (int off = 1; off < 1024; off <<= 1) {
            int add = (t >= off) ? s[t - off] : 0;
            __syncthreads();
            s[t] += add;
            __syncthreads();
        }
        int incl = s[t];
        if (base + t < N) {
            int ex = carry + incl - v;
            g_offs[base + t] = ex;
            g_cursor[base + t] = ex;
        }
        carry += s[1023];
        __syncthreads();
    }
    if (t == 0) g_offs[N] = carry;
}

// ---------------- scatter: counting sort by dst ----------------
__global__ void k_scatter(const int* __restrict__ dst, const int* __restrict__ src) {
    int e = blockIdx.x * blockDim.x + threadIdx.x;
    if (e < E) {
        int pos = atomicAdd(&g_cursor[dst[e]], 1);
        g_perm[pos] = e;
        g_srcs[pos] = src[e];
    }
}

// ---------------- node pre-GEMMs: g_A=[h@W1|p@P1], g_B=[h@W2|p@P2] --------------
__global__ void __launch_bounds__(256) k_nodepre(
    const float* __restrict__ h, const float* __restrict__ p,
    const float* __restrict__ Wh, const float* __restrict__ Wp)
{
    __shared__ __align__(16) float Xs[32 * PITCH];
    __shared__ __align__(16) float Ws[32 * 128];

    int tid = threadIdx.x;
    int base = blockIdx.x * 128;

    int tx = tid & 15;
    int te = tid >> 4;
    int le = tid & 127;
    int lh = (tid >> 7) * 16;
    int wkk = tid >> 3;
    int woc = (tid & 7) * 16;

    int nl = base + le;
    bool okl = nl < N;

    ull acca[4][4], accb[4][4];

    // ===== h phase =====
#pragma unroll
    for (int i = 0; i < 4; i++)
#pragma unroll
        for (int j = 0; j < 4; j++) { acca[i][j] = 0ull; accb[i][j] = 0ull; }

    for (int t = 0; t < 4; t++) {
        int k0 = t * 32;
        const float* rowp = h + (size_t)nl * 128 + k0;
#pragma unroll
        for (int q = 0; q < 4; q++) {
            float4 a = okl ? *(const float4*)(rowp + lh + q * 4)
                           : make_float4(0.f, 0.f, 0.f, 0.f);
            Xs[(lh + q * 4 + 0) * PITCH + le] = a.x;
            Xs[(lh + q * 4 + 1) * PITCH + le] = a.y;
            Xs[(lh + q * 4 + 2) * PITCH + le] = a.z;
            Xs[(lh + q * 4 + 3) * PITCH + le] = a.w;
        }
        {
            const float* wr = (woc < 64) ? (Wh + (size_t)(k0 + wkk) * 64 + woc)
                                         : (Wh + (size_t)(128 + k0 + wkk) * 64 + (woc - 64));
#pragma unroll
            for (int q = 0; q < 4; q++)
                *(float4*)&Ws[wkk * 128 + woc + q * 4] = *(const float4*)(wr + q * 4);
        }
        __syncthreads();
#pragma unroll 16
        for (int kk = 0; kk < 32; kk++) {
            float4 wa = *(const float4*)&Ws[kk * 128 + tx * 4];
            float4 wb = *(const float4*)&Ws[kk * 128 + 64 + tx * 4];
            ull a0 = pack2(wa.x, wa.x), a1 = pack2(wa.y, wa.y);
            ull a2 = pack2(wa.z, wa.z), a3 = pack2(wa.w, wa.w);
            ull b0 = pack2(wb.x, wb.x), b1 = pack2(wb.y, wb.y);
            ull b2 = pack2(wb.z, wb.z), b3 = pack2(wb.w, wb.w);
            const ull* xp = (const ull*)&Xs[kk * PITCH + te * 8];
#pragma unroll
            for (int i = 0; i < 4; i++) {
                ull x = xp[i];
                acca[i][0] = fma2(x, a0, acca[i][0]);
                acca[i][1] = fma2(x, a1, acca[i][1]);
                acca[i][2] = fma2(x, a2, acca[i][2]);
                acca[i][3] = fma2(x, a3, acca[i][3]);
                accb[i][0] = fma2(x, b0, accb[i][0]);
                accb[i][1] = fma2(x, b1, accb[i][1]);
                accb[i][2] = fma2(x, b2, accb[i][2]);
                accb[i][3] = fma2(x, b3, accb[i][3]);
            }
        }
        __syncthreads();
    }
#pragma unroll
    for (int i = 0; i < 4; i++) {
        float2 a0 = unpack2(acca[i][0]), a1 = unpack2(acca[i][1]);
        float2 a2 = unpack2(acca[i][2]), a3 = unpack2(acca[i][3]);
        float2 b0 = unpack2(accb[i][0]), b1 = unpack2(accb[i][1]);
        float2 b2 = unpack2(accb[i][2]), b3 = unpack2(accb[i][3]);
        int n0 = base + te * 8 + 2 * i;
        if (n0 < N) {
            *(float4*)&g_A[(size_t)n0 * 128 + tx * 4] = make_float4(a0.x, a1.x, a2.x, a3.x);
            *(float4*)&g_B[(size_t)n0 * 128 + tx * 4] = make_float4(b0.x, b1.x, b2.x, b3.x);
        }
        if (n0 + 1 < N) {
            *(float4*)&g_A[(size_t)(n0 + 1) * 128 + tx * 4] = make_float4(a0.y, a1.y, a2.y, a3.y);
            *(float4*)&g_B[(size_t)(n0 + 1) * 128 + tx * 4] = make_float4(b0.y, b1.y, b2.y, b3.y);
        }
    }

    // ===== p phase =====
#pragma unroll
    for (int i = 0; i < 4; i++)
#pragma unroll
        for (int j = 0; j < 4; j++) { acca[i][j] = 0ull; accb[i][j] = 0ull; }

    for (int t = 0; t < 2; t++) {
        int k0 = t * 32;
        const float* rowp = p + (size_t)nl * 64 + k0;
#pragma unroll
        for (int q = 0; q < 4; q++) {
            float4 a = okl ? *(const float4*)(rowp + lh + q * 4)
                           : make_float4(0.f, 0.f, 0.f, 0.f);
            Xs[(lh + q * 4 + 0) * PITCH + le] = a.x;
            Xs[(lh + q * 4 + 1) * PITCH + le] = a.y;
            Xs[(lh + q * 4 + 2) * PITCH + le] = a.z;
            Xs[(lh + q * 4 + 3) * PITCH + le] = a.w;
        }
        {
            const float* wr = (woc < 64) ? (Wp + (size_t)(k0 + wkk) * 64 + woc)
                                         : (Wp + (size_t)(64 + k0 + wkk) * 64 + (woc - 64));
#pragma unroll
            for (int q = 0; q < 4; q++)
                *(float4*)&Ws[wkk * 128 + woc + q * 4] = *(const float4*)(wr + q * 4);
        }
        __syncthreads();
#pragma unroll 16
        for (int kk = 0; kk < 32; kk++) {
            float4 wa = *(const float4*)&Ws[kk * 128 + tx * 4];
            float4 wb = *(const float4*)&Ws[kk * 128 + 64 + tx * 4];
            ull a0 = pack2(wa.x, wa.x), a1 = pack2(wa.y, wa.y);
            ull a2 = pack2(wa.z, wa.z), a3 = pack2(wa.w, wa.w);
            ull b0 = pack2(wb.x, wb.x), b1 = pack2(wb.y, wb.y);
            ull b2 = pack2(wb.z, wb.z), b3 = pack2(wb.w, wb.w);
            const ull* xp = (const ull*)&Xs[kk * PITCH + te * 8];
#pragma unroll
            for (int i = 0; i < 4; i++) {
                ull x = xp[i];
                acca[i][0] = fma2(x, a0, acca[i][0]);
                acca[i][1] = fma2(x, a1, acca[i][1]);
                acca[i][2] = fma2(x, a2, acca[i][2]);
                acca[i][3] = fma2(x, a3, acca[i][3]);
                accb[i][0] = fma2(x, b0, accb[i][0]);
                accb[i][1] = fma2(x, b1, accb[i][1]);
                accb[i][2] = fma2(x, b2, accb[i][2]);
                accb[i][3] = fma2(x, b3, accb[i][3]);
            }
        }
        __syncthreads();
    }
#pragma unroll
    for (int i = 0; i < 4; i++) {
        float2 a0 = unpack2(acca[i][0]), a1 = unpack2(acca[i][1]);
        float2 a2 = unpack2(acca[i][2]), a3 = unpack2(acca[i][3]);
        float2 b0 = unpack2(accb[i][0]), b1 = unpack2(accb[i][1]);
        float2 b2 = unpack2(accb[i][2]), b3 = unpack2(accb[i][3]);
        int n0 = base + te * 8 + 2 * i;
        if (n0 < N) {
            *(float4*)&g_A[(size_t)n0 * 128 + 64 + tx * 4] = make_float4(a0.x, a1.x, a2.x, a3.x);
            *(float4*)&g_B[(size_t)n0 * 128 + 64 + tx * 4] = make_float4(b0.x, b1.x, b2.x, b3.x);
        }
        if (n0 + 1 < N) {
            *(float4*)&g_A[(size_t)(n0 + 1) * 128 + 64 + tx * 4] = make_float4(a0.y, a1.y, a2.y, a3.y);
            *(float4*)&g_B[(size_t)(n0 + 1) * 128 + 64 + tx * 4] = make_float4(b0.y, b1.y, b2.y, b3.y);
        }
    }
}

// ---------------- edge-feature GEMM -> fp16 interleaved messages ----------------
__global__ void __launch_bounds__(256) k_edgeE(
    const float* __restrict__ ef,
    const float* __restrict__ Wh, const float* __restrict__ bh,
    const float* __restrict__ Wp, const float* __restrict__ bp)
{
    __shared__ __align__(16) float Xs[32 * PITCH];
    __shared__ __align__(16) float Ws[32 * 128];
    __shared__ int s_eid[128];

    int tid = threadIdx.x;
    int base = blockIdx.x * 128;

    for (int j = tid; j < 128; j += 256) s_eid[j] = g_perm[base + j];

    int tx = tid & 15;
    int te = tid >> 4;
    int le = tid & 127;
    int lh = (tid >> 7) * 16;
    int wkk = tid >> 3;
    int woc = (tid & 7) * 16;

    {
        const float* wr = (woc < 64) ? (Wh + (size_t)(256 + wkk) * 64 + woc)
                                     : (Wp + (size_t)(128 + wkk) * 64 + (woc - 64));
#pragma unroll
        for (int q = 0; q < 4; q++)
            *(float4*)&Ws[wkk * 128 + woc + q * 4] = *(const float4*)(wr + q * 4);
    }
    __syncthreads();
    {
        const float* rowp = ef + (size_t)s_eid[le] * 32;
#pragma unroll
        for (int q = 0; q < 4; q++) {
            float4 a = *(const float4*)(rowp + lh + q * 4);
            Xs[(lh + q * 4 + 0) * PITCH + le] = a.x;
            Xs[(lh + q * 4 + 1) * PITCH + le] = a.y;
            Xs[(lh + q * 4 + 2) * PITCH + le] = a.z;
            Xs[(lh + q * 4 + 3) * PITCH + le] = a.w;
        }
    }
    __syncthreads();

    ull acca[4][4], accb[4][4];
#pragma unroll
    for (int i = 0; i < 4; i++)
#pragma unroll
        for (int j = 0; j < 4; j++) { acca[i][j] = 0ull; accb[i][j] = 0ull; }

#pragma unroll 16
    for (int kk = 0; kk < 32; kk++) {
        float4 wa = *(const float4*)&Ws[kk * 128 + tx * 4];
        float4 wb = *(const float4*)&Ws[kk * 128 + 64 + tx * 4];
        ull a0 = pack2(wa.x, wa.x), a1 = pack2(wa.y, wa.y);
        ull a2 = pack2(wa.z, wa.z), a3 = pack2(wa.w, wa.w);
        ull b0 = pack2(wb.x, wb.x), b1 = pack2(wb.y, wb.y);
        ull b2 = pack2(wb.z, wb.z), b3 = pack2(wb.w, wb.w);
        const ull* xp = (const ull*)&Xs[kk * PITCH + te * 8];
#pragma unroll
        for (int i = 0; i < 4; i++) {
            ull x = xp[i];
            acca[i][0] = fma2(x, a0, acca[i][0]);
            acca[i][1] = fma2(x, a1, acca[i][1]);
            acca[i][2] = fma2(x, a2, acca[i][2]);
            acca[i][3] = fma2(x, a3, acca[i][3]);
            accb[i][0] = fma2(x, b0, accb[i][0]);
            accb[i][1] = fma2(x, b1, accb[i][1]);
            accb[i][2] = fma2(x, b2, accb[i][2]);
            accb[i][3] = fma2(x, b3, accb[i][3]);
        }
    }

    float4 biash = *(const float4*)&bh[tx * 4];
    float4 biasp = *(const float4*)&bp[tx * 4];
#pragma unroll
    for (int i = 0; i < 4; i++) {
        float2 a0 = unpack2(acca[i][0]), a1 = unpack2(acca[i][1]);
        float2 a2 = unpack2(acca[i][2]), a3 = unpack2(acca[i][3]);
        float2 b0 = unpack2(accb[i][0]), b1 = unpack2(accb[i][1]);
        float2 b2 = unpack2(accb[i][2]), b3 = unpack2(accb[i][3]);
        int pos = base + te * 8 + 2 * i;
        __half* r0 = g_ce + (size_t)pos * 128;
        __half* r1 = g_ce + (size_t)(pos + 1) * 128;
        {
            __half2 lo = __floats2half2_rn(a0.x + biash.x, a1.x + biash.y);
            __half2 hi = __floats2half2_rn(a2.x + biash.z, a3.x + biash.w);
            *(__half2*)(r0 + tx * 4) = lo; *(__half2*)(r0 + tx * 4 + 2) = hi;
            lo = __floats2half2_rn(a0.y + biash.x, a1.y + biash.y);
            hi = __floats2half2_rn(a2.y + biash.z, a3.y + biash.w);
            *(__half2*)(r1 + tx * 4) = lo; *(__half2*)(r1 + tx * 4 + 2) = hi;
        }
        {
            __half2 lo = __floats2half2_rn(b0.x + biasp.x, b1.x + biasp.y);
            __half2 hi = __floats2half2_rn(b2.x + biasp.z, b3.x + biasp.w);
            *(__half2*)(r0 + 64 + tx * 4) = lo; *(__half2*)(r0 + 64 + tx * 4 + 2) = hi;
            lo = __floats2half2_rn(b0.y + biasp.x, b1.y + biasp.y);
            hi = __floats2half2_rn(b2.y + biasp.z, b3.y + biasp.w);
            *(__half2*)(r1 + 64 + tx * 4) = lo; *(__half2*)(r1 + 64 + tx * 4 + 2) = hi;
        }
    }
}

// ---------------- fused message + PNA aggregation (warp per node, paired lanes) ------
// Lane l owns features h:(2l,2l+1) and p:(2l,2l+1) -> all accesses vectorized x2.
__global__ void k_agg() {
    int warp = (blockIdx.x * blockDim.x + threadIdx.x) >> 5;
    int l = threadIdx.x & 31;
    if (warp >= N) return;
    int n = warp;
    int s0 = g_offs[n];
    int s1 = g_offs[n + 1];
    int d = s1 - s0;

    const float* brow = g_B + (size_t)n * 128;
    float2 bh = *(const float2*)(brow + 2 * l);
    float2 bp = *(const float2*)(brow + 64 + 2 * l);

    float2 smh = make_float2(0.f, 0.f), smp = make_float2(0.f, 0.f);
    float2 sqh = make_float2(0.f, 0.f), sqp = make_float2(0.f, 0.f);
    float2 mxh = make_float2(-FLT_BIG, -FLT_BIG), mxp = make_float2(-FLT_BIG, -FLT_BIG);
    float2 mnh = make_float2(FLT_BIG, FLT_BIG), mnp = make_float2(FLT_BIG, FLT_BIG);

    for (int i = s0; i < s1; i++) {
        int s = g_srcs[i];
        const float* a = g_A + (size_t)s * 128;
        const __half* c = g_ce + (size_t)i * 128;
        float2 ch = __half22float2(*(const __half2*)(c + 2 * l));
        float2 cp = __half22float2(*(const __half2*)(c + 64 + 2 * l));
        float2 ah = *(const float2*)(a + 2 * l);
        float2 ap = *(const float2*)(a + 64 + 2 * l);
        float v0 = ch.x + ah.x + bh.x;
        float v1 = ch.y + ah.y + bh.y;
        float v2 = cp.x + ap.x + bp.x;
        float v3 = cp.y + ap.y + bp.y;
        smh.x += v0; sqh.x += v0 * v0; mxh.x = fmaxf(mxh.x, v0); mnh.x = fminf(mnh.x, v0);
        smh.y += v1; sqh.y += v1 * v1; mxh.y = fmaxf(mxh.y, v1); mnh.y = fminf(mnh.y, v1);
        smp.x += v2; sqp.x += v2 * v2; mxp.x = fmaxf(mxp.x, v2); mnp.x = fminf(mnp.x, v2);
        smp.y += v3; sqp.y += v3 * v3; mxp.y = fmaxf(mxp.y, v3); mnp.y = fminf(mnp.y, v3);
    }

    float degc = fmaxf((float)d, 1.f);
    float inv = 1.f / degc;
    bool has = d > 0;
    float logd = has ? logf((float)d + 1.f) : 1.f;
    float amp = logd / AVG_D_LOG;
    float att = AVG_D_LOG / logd;
    if (l == 0) { g_amp[n] = amp; g_att[n] = att; }

    float* outh = g_aggh + (size_t)n * 256;
    float* outp = g_aggp + (size_t)n * 256;

    {
        float2 mean = make_float2(smh.x * inv, smh.y * inv);
        float2 var = make_float2(fmaxf(sqh.x * inv - mean.x * mean.x, 0.f),
                                 fmaxf(sqh.y * inv - mean.y * mean.y, 0.f));
        float2 sd = make_float2(sqrtf(var.x + EPS_STD), sqrtf(var.y + EPS_STD));
        float2 MX = has ? mxh : make_float2(0.f, 0.f);
        float2 MN = has ? mnh : make_float2(0.f, 0.f);
        *(float2*)(outh + 2 * l) = mean;
        *(float2*)(outh + 64 + 2 * l) = MX;
        *(float2*)(outh + 128 + 2 * l) = MN;
        *(float2*)(outh + 192 + 2 * l) = sd;
    }
    {
        float2 mean = make_float2(smp.x * inv, smp.y * inv);
        float2 var = make_float2(fmaxf(sqp.x * inv - mean.x * mean.x, 0.f),
                                 fmaxf(sqp.y * inv - mean.y * mean.y, 0.f));
        float2 sd = make_float2(sqrtf(var.x + EPS_STD), sqrtf(var.y + EPS_STD));
        float2 MX = has ? mxp : make_float2(0.f, 0.f);
        float2 MN = has ? mnp : make_float2(0.f, 0.f);
        *(float2*)(outp + 2 * l) = mean;
        *(float2*)(outp + 64 + 2 * l) = MX;
        *(float2*)(outp + 128 + 2 * l) = MN;
        *(float2*)(outp + 192 + 2 * l) = sd;
    }
}

// ---------------- node GEMMs with factored scalers (3 rails) — round-4 version -------
__global__ void __launch_bounds__(256) k_nodegemm(
    const float* __restrict__ h, const float* __restrict__ p,
    const float* __restrict__ snorm,
    const float* __restrict__ Woh, const float* __restrict__ boh,
    const float* __restrict__ Wop, const float* __restrict__ bop,
    float* __restrict__ out)
{
    __shared__ __align__(16) float Xs[32 * 64];
    __shared__ __align__(16) float Ws[3 * 32 * 64];

    int tid = threadIdx.x;
    int base = blockIdx.x * 64;

    int tx = tid & 31;
    int te = tid >> 5;
    int le = tid & 63;
    int lh = (tid >> 6) * 8;
    int wkk = tid >> 3;
    int woc = (tid & 7) * 8;

    int nl = base + le;
    bool okl = nl < N;

    ull accI[4][2], accA[4][2], accT[4][2];

    // =================== phase H =========
#pragma unroll
    for (int i = 0; i < 4; i++)
#pragma unroll
        for (int j = 0; j < 2; j++) { accI[i][j] = 0ull; accA[i][j] = 0ull; accT[i][j] = 0ull; }

    for (int t = 0; t < 12; t++) {
        int k0 = t * 32;
        bool isAgg = (t >= 4);
        const float* rowp = isAgg ? (g_aggh + (size_t)nl * 256 + (k0 - 128))
                                  : (h + (size_t)nl * 128 + k0);
#pragma unroll
        for (int q = 0; q < 2; q++) {
            float4 a = okl ? *(const float4*)(rowp + lh + q * 4)
                           : make_float4(0.f, 0.f, 0.f, 0.f);
            Xs[(lh + q * 4 + 0) * 64 + le] = a.x;
            Xs[(lh + q * 4 + 1) * 64 + le] = a.y;
            Xs[(lh + q * 4 + 2) * 64 + le] = a.z;
            Xs[(lh + q * 4 + 3) * 64 + le] = a.w;
        }
        if (isAgg) {
            int aggk = k0 - 128;
            const float* wI = Woh + (size_t)(128 + aggk + wkk) * 64 + woc;
            const float* wA = Woh + (size_t)(384 + aggk + wkk) * 64 + woc;
            const float* wT = Woh + (size_t)(640 + aggk + wkk) * 64 + woc;
            *(float4*)&Ws[wkk * 64 + woc]              = *(const float4*)(wI);
            *(float4*)&Ws[wkk * 64 + woc + 4]          = *(const float4*)(wI + 4);
            *(float4*)&Ws[2048 + wkk * 64 + woc]       = *(const float4*)(wA);
            *(float4*)&Ws[2048 + wkk * 64 + woc + 4]   = *(const float4*)(wA + 4);
            *(float4*)&Ws[4096 + wkk * 64 + woc]       = *(const float4*)(wT);
            *(float4*)&Ws[4096 + wkk * 64 + woc + 4]   = *(const float4*)(wT + 4);
        } else {
            const float* wI = Woh + (size_t)(k0 + wkk) * 64 + woc;
            *(float4*)&Ws[wkk * 64 + woc]     = *(const float4*)(wI);
            *(float4*)&Ws[wkk * 64 + woc + 4] = *(const float4*)(wI + 4);
        }
        __syncthreads();
        if (isAgg) {
#pragma unroll 8
            for (int kk = 0; kk < 32; kk++) {
                float2 wi = *(const float2*)&Ws[kk * 64 + tx * 2];
                float2 wa = *(const float2*)&Ws[2048 + kk * 64 + tx * 2];
                float2 wt = *(const float2*)&Ws[4096 + kk * 64 + tx * 2];
                ull i0 = pack2(wi.x, wi.x), i1 = pack2(wi.y, wi.y);
                ull a0 = pack2(wa.x, wa.x), a1 = pack2(wa.y, wa.y);
                ull t0 = pack2(wt.x, wt.x), t1 = pack2(wt.y, wt.y);
                const ull* xp = (const ull*)&Xs[kk * 64 + te * 8];
#pragma unroll
                for (int i = 0; i < 4; i++) {
                    ull x = xp[i];
                    accI[i][0] = fma2(x, i0, accI[i][0]);
                    accI[i][1] = fma2(x, i1, accI[i][1]);
                    accA[i][0] = fma2(x, a0, accA[i][0]);
                    accA[i][1] = fma2(x, a1, accA[i][1]);
                    accT[i][0] = fma2(x, t0, accT[i][0]);
                    accT[i][1] = fma2(x, t1, accT[i][1]);
                }
            }
        } else {
#pragma unroll 8
            for (int kk = 0; kk < 32; kk++) {
                float2 wi = *(const float2*)&Ws[kk * 64 + tx * 2];
                ull i0 = pack2(wi.x, wi.x), i1 = pack2(wi.y, wi.y);
                const ull* xp = (const ull*)&Xs[kk * 64 + te * 8];
#pragma unroll
                for (int i = 0; i < 4; i++) {
                    ull x = xp[i];
                    accI[i][0] = fma2(x, i0, accI[i][0]);
                    accI[i][1] = fma2(x, i1, accI[i][1]);
                }
            }
        }
        __syncthreads();
    }
    {
        float2 bias = *(const float2*)&boh[tx * 2];
#pragma unroll
        for (int i = 0; i < 4; i++) {
            int n0 = base + te * 8 + 2 * i;
            float am0 = (n0 < N) ? g_amp[n0] : 0.f;
            float am1 = (n0 + 1 < N) ? g_amp[n0 + 1] : 0.f;
            float at0 = (n0 < N) ? g_att[n0] : 0.f;
            float at1 = (n0 + 1 < N) ? g_att[n0 + 1] : 0.f;
            ull ampP = pack2(am0, am1), attP = pack2(at0, at1);
            ull y0 = fma2(attP, accT[i][0], fma2(ampP, accA[i][0], accI[i][0]));
            ull y1 = fma2(attP, accT[i][1], fma2(ampP, accA[i][1], accI[i][1]));
            float2 u0 = unpack2(y0), u1 = unpack2(y1);
            if (n0 < N) {
                float sn = snorm[n0];
                *(float2*)&out[(size_t)n0 * 64 + tx * 2] =
                    make_float2((u0.x + bias.x) * sn, (u1.x + bias.y) * sn);
            }
            if (n0 + 1 < N) {
                float sn = snorm[n0 + 1];
                *(float2*)&out[(size_t)(n0 + 1) * 64 + tx * 2] =
                    make_float2((u0.y + bias.x) * sn, (u1.y + bias.y) * sn);
            }
        }
    }

    // =================== phase P ==========
#pragma unroll
    for (int i = 0; i < 4; i++)
#pragma unroll
        for (int j = 0; j < 2; j++) { accI[i][j] = 0ull; accA[i][j] = 0ull; accT[i][j] = 0ull; }

    for (int t = 0; t < 10; t++) {
        int k0 = t * 32;
        bool isAgg = (t >= 2);
        const float* rowp = isAgg ? (g_aggp + (size_t)nl * 256 + (k0 - 64))
                                  : (p + (size_t)nl * 64 + k0);
#pragma unroll
        for (int q = 0; q < 2; q++) {
            float4 a = okl ? *(const float4*)(rowp + lh + q * 4)
                           : make_float4(0.f, 0.f, 0.f, 0.f);
            Xs[(lh + q * 4 + 0) * 64 + le] = a.x;
            Xs[(lh + q * 4 + 1) * 64 + le] = a.y;
            Xs[(lh + q * 4 + 2) * 64 + le] = a.z;
            Xs[(lh + q * 4 + 3) * 64 + le] = a.w;
        }
        if (isAgg) {
            int aggk = k0 - 64;
            const float* wI = Wop + (size_t)(64 + aggk + wkk) * 64 + woc;
            const float* wA = Wop + (size_t)(320 + aggk + wkk) * 64 + woc;
            const float* wT = Wop + (size_t)(576 + aggk + wkk) * 64 + woc;
            *(float4*)&Ws[wkk * 64 + woc]              = *(const float4*)(wI);
            *(float4*)&Ws[wkk * 64 + woc + 4]          = *(const float4*)(wI + 4);
            *(float4*)&Ws[2048 + wkk * 64 + woc]       = *(const float4*)(wA);
            *(float4*)&Ws[2048 + wkk * 64 + woc + 4]   = *(const float4*)(wA + 4);
            *(float4*)&Ws[4096 + wkk * 64 + woc]       = *(const float4*)(wT);
            *(float4*)&Ws[4096 + wkk * 64 + woc + 4]   = *(const float4*)(wT + 4);
        } else {
            const float* wI = Wop + (size_t)(k0 + wkk) * 64 + woc;
            *(float4*)&Ws[wkk * 64 + woc]     = *(const float4*)(wI);
            *(float4*)&Ws[wkk * 64 + woc + 4] = *(const float4*)(wI + 4);
        }
        __syncthreads();
        if (isAgg) {
#pragma unroll 8
            for (int kk = 0; kk < 32; kk++) {
                float2 wi = *(const float2*)&Ws[kk * 64 + tx * 2];
                float2 wa = *(const float2*)&Ws[2048 + kk * 64 + tx * 2];
                float2 wt = *(const float2*)&Ws[4096 + kk * 64 + tx * 2];
                ull i0 = pack2(wi.x, wi.x), i1 = pack2(wi.y, wi.y);
                ull a0 = pack2(wa.x, wa.x), a1 = pack2(wa.y, wa.y);
                ull t0 = pack2(wt.x, wt.x), t1 = pack2(wt.y, wt.y);
                const ull* xp = (const ull*)&Xs[kk * 64 + te * 8];
#pragma unroll
                for (int i = 0; i < 4; i++) {
                    ull x = xp[i];
                    accI[i][0] = fma2(x, i0, accI[i][0]);
                    accI[i][1] = fma2(x, i1, accI[i][1]);
                    accA[i][0] = fma2(x, a0, accA[i][0]);
                    accA[i][1] = fma2(x, a1, accA[i][1]);
                    accT[i][0] = fma2(x, t0, accT[i][0]);
                    accT[i][1] = fma2(x, t1, accT[i][1]);
                }
            }
        } else {
#pragma unroll 8
            for (int kk = 0; kk < 32; kk++) {
                float2 wi = *(const float2*)&Ws[kk * 64 + tx * 2];
                ull i0 = pack2(wi.x, wi.x), i1 = pack2(wi.y, wi.y);
                const ull* xp = (const ull*)&Xs[kk * 64 + te * 8];
#pragma unroll
                for (int i = 0; i < 4; i++) {
                    ull x = xp[i];
                    accI[i][0] = fma2(x, i0, accI[i][0]);
                    accI[i][1] = fma2(x, i1, accI[i][1]);
                }
            }
        }
        __syncthreads();
    }
    {
        float2 bias = *(const float2*)&bop[tx * 2];
        float* outp = out + (size_t)N * 64;
#pragma unroll
        for (int i = 0; i < 4; i++) {
            int n0 = base + te * 8 + 2 * i;
            float am0 = (n0 < N) ? g_amp[n0] : 0.f;
            float am1 = (n0 + 1 < N) ? g_amp[n0 + 1] : 0.f;
            float at0 = (n0 < N) ? g_att[n0] : 0.f;
            float at1 = (n0 + 1 < N) ? g_att[n0 + 1] : 0.f;
            ull ampP = pack2(am0, am1), attP = pack2(at0, at1);
            ull y0 = fma2(attP, accT[i][0], fma2(ampP, accA[i][0], accI[i][0]));
            ull y1 = fma2(attP, accT[i][1], fma2(ampP, accA[i][1], accI[i][1]));
            float2 u0 = unpack2(y0), u1 = unpack2(y1);
            if (n0 < N)
                *(float2*)&outp[(size_t)n0 * 64 + tx * 2] =
                    make_float2(u0.x + bias.x, u1.x + bias.y);
            if (n0 + 1 < N)
                *(float2*)&outp[(size_t)(n0 + 1) * 64 + tx * 2] =
                    make_float2(u0.y + bias.x, u1.y + bias.y);
        }
    }
}

// ---------------- batchnorm stats ----------------
__global__ void k_bnstats(const float* __restrict__ out) {
    __shared__ float ss[4][64];
    __shared__ float sqv[4][64];
    int f = threadIdx.x & 63;
    int rg = threadIdx.x >> 6;
    int r0 = blockIdx.x * 128;
    int rend = r0 + 128;
    if (rend > N) rend = N;
    float s = 0.f, q = 0.f;
    for (int r = r0 + rg; r < rend; r += 4) {
        float x = out[(size_t)r * 64 + f];
        s += x; q += x * x;
    }
    ss[rg][f] = s; sqv[rg][f] = q;
    __syncthreads();
    if (threadIdx.x < 64) {
        float S = ss[0][f] + ss[1][f] + ss[2][f] + ss[3][f];
        float Q = sqv[0][f] + sqv[1][f] + sqv[2][f] + sqv[3][f];
        atomicAdd(&g_bnsum[f], S);
        atomicAdd(&g_bnsq[f], Q);
    }
}

// ---------------- batchnorm apply ----------------
__global__ void k_bnapply(float* __restrict__ out,
                          const float* __restrict__ gamma,
                          const float* __restrict__ beta) {
    int i = blockIdx.x * blockDim.x + threadIdx.x;
    if (i >= N * 64) return;
    int f = i & 63;
    const float invN = 1.f / (float)N;
    float mu = g_bnsum[f] * invN;
    float var = g_bnsq[f] * invN - mu * mu;
    float x = out[i];
    out[i] = (x - mu) * rsqrtf(var + EPS_BN) * gamma[f] + beta[f];
}

} // namespace

extern "C" void kernel_launch(void* const* d_in, const int* in_sizes, int n_in,
                              void* d_out, int out_size) {
    const float* h     = (const float*)d_in[0];
    const float* p     = (const float*)d_in[1];
    const float* e     = (const float*)d_in[2];
    const int*   src   = (const int*)d_in[3];
    const int*   dst   = (const int*)d_in[4];
    const float* snorm = (const float*)d_in[5];
    const float* Wph   = (const float*)d_in[6];
    const float* bph   = (const float*)d_in[7];
    const float* Wpp   = (const float*)d_in[8];
    const float* bpp   = (const float*)d_in[9];
    const float* Woh   = (const float*)d_in[10];
    const float* boh   = (const float*)d_in[11];
    const float* Wop   = (const float*)d_in[12];
    const float* bop   = (const float*)d_in[13];
    const float* gamma = (const float*)d_in[14];
    const float* beta  = (const float*)d_in[15];
    float* out = (float*)d_out;

    k_init<<<(N + 255) / 256, 256>>>();
    k_hist<<<(E + 255) / 256, 256>>>(dst);
    k_scan<<<1, 1024>>>();
    k_scatter<<<(E + 255) / 256, 256>>>(dst, src);
    k_nodepre<<<(N + 127) / 128, 256>>>(h, p, Wph, Wpp);
    k_edgeE<<<E / 128, 256>>>(e, Wph, bph, Wpp, bpp);
    k_agg<<<(N * 32 + 255) / 256, 256>>>();
    k_nodegemm<<<(N + 63) / 64, 256>>>(h, p, snorm, Woh, boh, Wop, bop, out);
    k_bnstats<<<(N + 127) / 128, 256>>>(out);
    k_bnapply<<<(N * 64 + 255) / 256, 256>>>(out, gamma, beta);
}

// round 7
// speedup vs baseline: 1.2287x; 1.0444x over previous
#include <cuda_runtime.h>
#include <cuda_fp16.h>
#include <math.h>

namespace {

constexpr int N = 50000;
constexpr int E = 800000;
constexpr float AVG_D_LOG = 2.8332f;
constexpr float EPS_STD = 1e-5f;
constexpr float EPS_BN = 1e-5f;
constexpr float FLT_BIG = 3.402823466e+38f;
constexpr int PITCH = 130;

typedef unsigned long long ull;

__device__ __forceinline__ ull fma2(ull a, ull b, ull c) {
    ull d;
    asm("fma.rn.f32x2 %0,%1,%2,%3;" : "=l"(d) : "l"(a), "l"(b), "l"(c));
    return d;
}
__device__ __forceinline__ ull pack2(float x, float y) {
    ull d;
    asm("mov.b64 %0,{%1,%2};" : "=l"(d) : "f"(x), "f"(y));
    return d;
}
__device__ __forceinline__ float2 unpack2(ull v) {
    float2 r;
    asm("mov.b64 {%0,%1},%2;" : "=f"(r.x), "=f"(r.y) : "l"(v));
    return r;
}

// ---- scratch (device globals: allocation-free contract) ----
__device__ int g_deg[N];
__device__ int g_offs[N + 1];
__device__ int g_cursor[N];
__device__ int g_perm[E];
__device__ int g_srcs[E];
__device__ __align__(16) __half g_A[(size_t)N * 128];    // [h@W1 | p@P1] fp16
__device__ __align__(16) __half g_B[(size_t)N * 128];    // [h@W2 | p@P2] fp16
__device__ __align__(16) __half g_ce[(size_t)E * 128];   // [e@W3+bh | e@P3+bp] fp16, sorted
__device__ __align__(16) float g_aggh[(size_t)N * 256];  // [mean|max|min|std]
__device__ __align__(16) float g_aggp[(size_t)N * 256];
__device__ float g_amp[N];
__device__ float g_att[N];
__device__ float g_bnsum[64];
__device__ float g_bnsq[64];

// ---------------- init ----------------
__global__ void k_init() {
    int i = blockIdx.x * blockDim.x + threadIdx.x;
    if (i < N) g_deg[i] = 0;
    if (i < 64) { g_bnsum[i] = 0.f; g_bnsq[i] = 0.f; }
}

// ---------------- degree histogram ----------------
__global__ void k_hist(const int* __restrict__ dst) {
    int e = blockIdx.x * blockDim.x + threadIdx.x;
    if (e < E) atomicAdd(&g_deg[dst[e]], 1);
}

// ---------------- exclusive scan (single block, shfl-based) ----------------
__global__ void k_scan() {
    __shared__ int ws[32];
    __shared__ int carry_s;
    int t = threadIdx.x;
    int lane = t & 31, w = t >> 5;
    if (t == 0) carry_s = 0;
    __syncthreads();
    for (int base = 0; base < N; base += 1024) {
        int v = (base + t < N) ? g_deg[base + t] : 0;
        int x = v;
#pragma unroll
        for (int off = 1; off < 32; off <<= 1) {
            int y = __shfl_up_sync(0xffffffffu, x, off);
            if (lane >= off) x += y;
        }
        if (lane == 31) ws[w] = x;
        __syncthreads();
        if (w == 0) {
            int s = ws[lane];
#pragma unroll
            for (int off = 1; off < 32; off <<= 1) {
                int y = __shfl_up_sync(0xffffffffu, s, off);
                if (lane >= off) s += y;
            }
            ws[lane] = s;
        }
        __syncthreads();
        int carry = carry_s;
        int incl = x + (w > 0 ? ws[w - 1] : 0);
        if (base + t < N) {
            int ex = carry + incl - v;
            g_offs[base + t] = ex;
            g_cursor[base + t] = ex;
        }
        __syncthreads();
        if (t == 0) carry_s = carry + ws[31];
        __syncthreads();
    }
    if (t == 0) g_offs[N] = carry_s;
}

// ---------------- scatter: counting sort by dst ----------------
__global__ void k_scatter(const int* __restrict__ dst, const int* __restrict__ src) {
    int e = blockIdx.x * blockDim.x + threadIdx.x;
    if (e < E) {
        int pos = atomicAdd(&g_cursor[dst[e]], 1);
        g_perm[pos] = e;
        g_srcs[pos] = src[e];
    }
}

// ---------------- node pre-GEMMs -> fp16 g_A, g_B --------------
__global__ void __launch_bounds__(256) k_nodepre(
    const float* __restrict__ h, const float* __restrict__ p,
    const float* __restrict__ Wh, const float* __restrict__ Wp)
{
    __shared__ __align__(16) float Xs[32 * PITCH];
    __shared__ __align__(16) float Ws[32 * 128];

    int tid = threadIdx.x;
    int base = blockIdx.x * 128;

    int tx = tid & 15;
    int te = tid >> 4;
    int le = tid & 127;
    int lh = (tid >> 7) * 16;
    int wkk = tid >> 3;
    int woc = (tid & 7) * 16;

    int nl = base + le;
    bool okl = nl < N;

    ull acca[4][4], accb[4][4];

    // ===== h phase =====
#pragma unroll
    for (int i = 0; i < 4; i++)
#pragma unroll
        for (int j = 0; j < 4; j++) { acca[i][j] = 0ull; accb[i][j] = 0ull; }

    for (int t = 0; t < 4; t++) {
        int k0 = t * 32;
        const float* rowp = h + (size_t)nl * 128 + k0;
#pragma unroll
        for (int q = 0; q < 4; q++) {
            float4 a = okl ? *(const float4*)(rowp + lh + q * 4)
                           : make_float4(0.f, 0.f, 0.f, 0.f);
            Xs[(lh + q * 4 + 0) * PITCH + le] = a.x;
            Xs[(lh + q * 4 + 1) * PITCH + le] = a.y;
            Xs[(lh + q * 4 + 2) * PITCH + le] = a.z;
            Xs[(lh + q * 4 + 3) * PITCH + le] = a.w;
        }
        {
            const float* wr = (woc < 64) ? (Wh + (size_t)(k0 + wkk) * 64 + woc)
                                         : (Wh + (size_t)(128 + k0 + wkk) * 64 + (woc - 64));
#pragma unroll
            for (int q = 0; q < 4; q++)
                *(float4*)&Ws[wkk * 128 + woc + q * 4] = *(const float4*)(wr + q * 4);
        }
        __syncthreads();
#pragma unroll 16
        for (int kk = 0; kk < 32; kk++) {
            float4 wa = *(const float4*)&Ws[kk * 128 + tx * 4];
            float4 wb = *(const float4*)&Ws[kk * 128 + 64 + tx * 4];
            ull a0 = pack2(wa.x, wa.x), a1 = pack2(wa.y, wa.y);
            ull a2 = pack2(wa.z, wa.z), a3 = pack2(wa.w, wa.w);
            ull b0 = pack2(wb.x, wb.x), b1 = pack2(wb.y, wb.y);
            ull b2 = pack2(wb.z, wb.z), b3 = pack2(wb.w, wb.w);
            const ull* xp = (const ull*)&Xs[kk * PITCH + te * 8];
#pragma unroll
            for (int i = 0; i < 4; i++) {
                ull x = xp[i];
                acca[i][0] = fma2(x, a0, acca[i][0]);
                acca[i][1] = fma2(x, a1, acca[i][1]);
                acca[i][2] = fma2(x, a2, acca[i][2]);
                acca[i][3] = fma2(x, a3, acca[i][3]);
                accb[i][0] = fma2(x, b0, accb[i][0]);
                accb[i][1] = fma2(x, b1, accb[i][1]);
                accb[i][2] = fma2(x, b2, accb[i][2]);
                accb[i][3] = fma2(x, b3, accb[i][3]);
            }
        }
        __syncthreads();
    }
#pragma unroll
    for (int i = 0; i < 4; i++) {
        float2 a0 = unpack2(acca[i][0]), a1 = unpack2(acca[i][1]);
        float2 a2 = unpack2(acca[i][2]), a3 = unpack2(acca[i][3]);
        float2 b0 = unpack2(accb[i][0]), b1 = unpack2(accb[i][1]);
        float2 b2 = unpack2(accb[i][2]), b3 = unpack2(accb[i][3]);
        int n0 = base + te * 8 + 2 * i;
        if (n0 < N) {
            __half* Ar = g_A + (size_t)n0 * 128 + tx * 4;
            __half* Br = g_B + (size_t)n0 * 128 + tx * 4;
            *(__half2*)Ar = __floats2half2_rn(a0.x, a1.x);
            *(__half2*)(Ar + 2) = __floats2half2_rn(a2.x, a3.x);
            *(__half2*)Br = __floats2half2_rn(b0.x, b1.x);
            *(__half2*)(Br + 2) = __floats2half2_rn(b2.x, b3.x);
        }
        if (n0 + 1 < N) {
            __half* Ar = g_A + (size_t)(n0 + 1) * 128 + tx * 4;
            __half* Br = g_B + (size_t)(n0 + 1) * 128 + tx * 4;
            *(__half2*)Ar = __floats2half2_rn(a0.y, a1.y);
            *(__half2*)(Ar + 2) = __floats2half2_rn(a2.y, a3.y);
            *(__half2*)Br = __floats2half2_rn(b0.y, b1.y);
            *(__half2*)(Br + 2) = __floats2half2_rn(b2.y, b3.y);
        }
    }

    // ===== p phase =====
#pragma unroll
    for (int i = 0; i < 4; i++)
#pragma unroll
        for (int j = 0; j < 4; j++) { acca[i][j] = 0ull; accb[i][j] = 0ull; }

    for (int t = 0; t < 2; t++) {
        int k0 = t * 32;
        const float* rowp = p + (size_t)nl * 64 + k0;
#pragma unroll
        for (int q = 0; q < 4; q++) {
            float4 a = okl ? *(const float4*)(rowp + lh + q * 4)
                           : make_float4(0.f, 0.f, 0.f, 0.f);
            Xs[(lh + q * 4 + 0) * PITCH + le] = a.x;
            Xs[(lh + q * 4 + 1) * PITCH + le] = a.y;
            Xs[(lh + q * 4 + 2) * PITCH + le] = a.z;
            Xs[(lh + q * 4 + 3) * PITCH + le] = a.w;
        }
        {
            const float* wr = (woc < 64) ? (Wp + (size_t)(k0 + wkk) * 64 + woc)
                                         : (Wp + (size_t)(64 + k0 + wkk) * 64 + (woc - 64));
#pragma unroll
            for (int q = 0; q < 4; q++)
                *(float4*)&Ws[wkk * 128 + woc + q * 4] = *(const float4*)(wr + q * 4);
        }
        __syncthreads();
#pragma unroll 16
        for (int kk = 0; kk < 32; kk++) {
            float4 wa = *(const float4*)&Ws[kk * 128 + tx * 4];
            float4 wb = *(const float4*)&Ws[kk * 128 + 64 + tx * 4];
            ull a0 = pack2(wa.x, wa.x), a1 = pack2(wa.y, wa.y);
            ull a2 = pack2(wa.z, wa.z), a3 = pack2(wa.w, wa.w);
            ull b0 = pack2(wb.x, wb.x), b1 = pack2(wb.y, wb.y);
            ull b2 = pack2(wb.z, wb.z), b3 = pack2(wb.w, wb.w);
            const ull* xp = (const ull*)&Xs[kk * PITCH + te * 8];
#pragma unroll
            for (int i = 0; i < 4; i++) {
                ull x = xp[i];
                acca[i][0] = fma2(x, a0, acca[i][0]);
                acca[i][1] = fma2(x, a1, acca[i][1]);
                acca[i][2] = fma2(x, a2, acca[i][2]);
                acca[i][3] = fma2(x, a3, acca[i][3]);
                accb[i][0] = fma2(x, b0, accb[i][0]);
                accb[i][1] = fma2(x, b1, accb[i][1]);
                accb[i][2] = fma2(x, b2, accb[i][2]);
                accb[i][3] = fma2(x, b3, accb[i][3]);
            }
        }
        __syncthreads();
    }
#pragma unroll
    for (int i = 0; i < 4; i++) {
        float2 a0 = unpack2(acca[i][0]), a1 = unpack2(acca[i][1]);
        float2 a2 = unpack2(acca[i][2]), a3 = unpack2(acca[i][3]);
        float2 b0 = unpack2(accb[i][0]), b1 = unpack2(accb[i][1]);
        float2 b2 = unpack2(accb[i][2]), b3 = unpack2(accb[i][3]);
        int n0 = base + te * 8 + 2 * i;
        if (n0 < N) {
            __half* Ar = g_A + (size_t)n0 * 128 + 64 + tx * 4;
            __half* Br = g_B + (size_t)n0 * 128 + 64 + tx * 4;
            *(__half2*)Ar = __floats2half2_rn(a0.x, a1.x);
            *(__half2*)(Ar + 2) = __floats2half2_rn(a2.x, a3.x);
            *(__half2*)Br = __floats2half2_rn(b0.x, b1.x);
            *(__half2*)(Br + 2) = __floats2half2_rn(b2.x, b3.x);
        }
        if (n0 + 1 < N) {
            __half* Ar = g_A + (size_t)(n0 + 1) * 128 + 64 + tx * 4;
            __half* Br = g_B + (size_t)(n0 + 1) * 128 + 64 + tx * 4;
            *(__half2*)Ar = __floats2half2_rn(a0.y, a1.y);
            *(__half2*)(Ar + 2) = __floats2half2_rn(a2.y, a3.y);
            *(__half2*)Br = __floats2half2_rn(b0.y, b1.y);
            *(__half2*)(Br + 2) = __floats2half2_rn(b2.y, b3.y);
        }
    }
}

// ---------------- edge-feature GEMM -> fp16 interleaved messages ----------------
__global__ void __launch_bounds__(256) k_edgeE(
    const float* __restrict__ ef,
    const float* __restrict__ Wh, const float* __restrict__ bh,
    const float* __restrict__ Wp, const float* __restrict__ bp)
{
    __shared__ __align__(16) float Xs[32 * PITCH];
    __shared__ __align__(16) float Ws[32 * 128];
    __shared__ int s_eid[128];

    int tid = threadIdx.x;
    int base = blockIdx.x * 128;

    for (int j = tid; j < 128; j += 256) s_eid[j] = g_perm[base + j];

    int tx = tid & 15;
    int te = tid >> 4;
    int le = tid & 127;
    int lh = (tid >> 7) * 16;
    int wkk = tid >> 3;
    int woc = (tid & 7) * 16;

    {
        const float* wr = (woc < 64) ? (Wh + (size_t)(256 + wkk) * 64 + woc)
                                     : (Wp + (size_t)(128 + wkk) * 64 + (woc - 64));
#pragma unroll
        for (int q = 0; q < 4; q++)
            *(float4*)&Ws[wkk * 128 + woc + q * 4] = *(const float4*)(wr + q * 4);
    }
    __syncthreads();
    {
        const float* rowp = ef + (size_t)s_eid[le] * 32;
#pragma unroll
        for (int q = 0; q < 4; q++) {
            float4 a = *(const float4*)(rowp + lh + q * 4);
            Xs[(lh + q * 4 + 0) * PITCH + le] = a.x;
            Xs[(lh + q * 4 + 1) * PITCH + le] = a.y;
            Xs[(lh + q * 4 + 2) * PITCH + le] = a.z;
            Xs[(lh + q * 4 + 3) * PITCH + le] = a.w;
        }
    }
    __syncthreads();

    ull acca[4][4], accb[4][4];
#pragma unroll
    for (int i = 0; i < 4; i++)
#pragma unroll
        for (int j = 0; j < 4; j++) { acca[i][j] = 0ull; accb[i][j] = 0ull; }

#pragma unroll 16
    for (int kk = 0; kk < 32; kk++) {
        float4 wa = *(const float4*)&Ws[kk * 128 + tx * 4];
        float4 wb = *(const float4*)&Ws[kk * 128 + 64 + tx * 4];
        ull a0 = pack2(wa.x, wa.x), a1 = pack2(wa.y, wa.y);
        ull a2 = pack2(wa.z, wa.z), a3 = pack2(wa.w, wa.w);
        ull b0 = pack2(wb.x, wb.x), b1 = pack2(wb.y, wb.y);
        ull b2 = pack2(wb.z, wb.z), b3 = pack2(wb.w, wb.w);
        const ull* xp = (const ull*)&Xs[kk * PITCH + te * 8];
#pragma unroll
        for (int i = 0; i < 4; i++) {
            ull x = xp[i];
            acca[i][0] = fma2(x, a0, acca[i][0]);
            acca[i][1] = fma2(x, a1, acca[i][1]);
            acca[i][2] = fma2(x, a2, acca[i][2]);
            acca[i][3] = fma2(x, a3, acca[i][3]);
            accb[i][0] = fma2(x, b0, accb[i][0]);
            accb[i][1] = fma2(x, b1, accb[i][1]);
            accb[i][2] = fma2(x, b2, accb[i][2]);
            accb[i][3] = fma2(x, b3, accb[i][3]);
        }
    }

    float4 biash = *(const float4*)&bh[tx * 4];
    float4 biasp = *(const float4*)&bp[tx * 4];
#pragma unroll
    for (int i = 0; i < 4; i++) {
        float2 a0 = unpack2(acca[i][0]), a1 = unpack2(acca[i][1]);
        float2 a2 = unpack2(acca[i][2]), a3 = unpack2(acca[i][3]);
        float2 b0 = unpack2(accb[i][0]), b1 = unpack2(accb[i][1]);
        float2 b2 = unpack2(accb[i][2]), b3 = unpack2(accb[i][3]);
        int pos = base + te * 8 + 2 * i;
        __half* r0 = g_ce + (size_t)pos * 128;
        __half* r1 = g_ce + (size_t)(pos + 1) * 128;
        {
            __half2 lo = __floats2half2_rn(a0.x + biash.x, a1.x + biash.y);
            __half2 hi = __floats2half2_rn(a2.x + biash.z, a3.x + biash.w);
            *(__half2*)(r0 + tx * 4) = lo; *(__half2*)(r0 + tx * 4 + 2) = hi;
            lo = __floats2half2_rn(a0.y + biash.x, a1.y + biash.y);
            hi = __floats2half2_rn(a2.y + biash.z, a3.y + biash.w);
            *(__half2*)(r1 + tx * 4) = lo; *(__half2*)(r1 + tx * 4 + 2) = hi;
        }
        {
            __half2 lo = __floats2half2_rn(b0.x + biasp.x, b1.x + biasp.y);
            __half2 hi = __floats2half2_rn(b2.x + biasp.z, b3.x + biasp.w);
            *(__half2*)(r0 + 64 + tx * 4) = lo; *(__half2*)(r0 + 64 + tx * 4 + 2) = hi;
            lo = __floats2half2_rn(b0.y + biasp.x, b1.y + biasp.y);
            hi = __floats2half2_rn(b2.y + biasp.z, b3.y + biasp.w);
            *(__half2*)(r1 + 64 + tx * 4) = lo; *(__half2*)(r1 + 64 + tx * 4 + 2) = hi;
        }
    }
}

// ---------------- fused message + PNA aggregation (warp per node, paired lanes) ------
__global__ void k_agg() {
    int warp = (blockIdx.x * blockDim.x + threadIdx.x) >> 5;
    int l = threadIdx.x & 31;
    if (warp >= N) return;
    int n = warp;
    int s0 = g_offs[n];
    int s1 = g_offs[n + 1];
    int d = s1 - s0;

    const __half* brow = g_B + (size_t)n * 128;
    float2 bh = __half22float2(*(const __half2*)(brow + 2 * l));
    float2 bp = __half22float2(*(const __half2*)(brow + 64 + 2 * l));

    float2 smh = make_float2(0.f, 0.f), smp = make_float2(0.f, 0.f);
    float2 sqh = make_float2(0.f, 0.f), sqp = make_float2(0.f, 0.f);
    float2 mxh = make_float2(-FLT_BIG, -FLT_BIG), mxp = make_float2(-FLT_BIG, -FLT_BIG);
    float2 mnh = make_float2(FLT_BIG, FLT_BIG), mnp = make_float2(FLT_BIG, FLT_BIG);

    for (int i = s0; i < s1; i++) {
        int s = g_srcs[i];
        const __half* a = g_A + (size_t)s * 128;
        const __half* c = g_ce + (size_t)i * 128;
        float2 ch = __half22float2(*(const __half2*)(c + 2 * l));
        float2 cp = __half22float2(*(const __half2*)(c + 64 + 2 * l));
        float2 ah = __half22float2(*(const __half2*)(a + 2 * l));
        float2 ap = __half22float2(*(const __half2*)(a + 64 + 2 * l));
        float v0 = ch.x + ah.x + bh.x;
        float v1 = ch.y + ah.y + bh.y;
        float v2 = cp.x + ap.x + bp.x;
        float v3 = cp.y + ap.y + bp.y;
        smh.x += v0; sqh.x += v0 * v0; mxh.x = fmaxf(mxh.x, v0); mnh.x = fminf(mnh.x, v0);
        smh.y += v1; sqh.y += v1 * v1; mxh.y = fmaxf(mxh.y, v1); mnh.y = fminf(mnh.y, v1);
        smp.x += v2; sqp.x += v2 * v2; mxp.x = fmaxf(mxp.x, v2); mnp.x = fminf(mnp.x, v2);
        smp.y += v3; sqp.y += v3 * v3; mxp.y = fmaxf(mxp.y, v3); mnp.y = fminf(mnp.y, v3);
    }

    float degc = fmaxf((float)d, 1.f);
    float inv = 1.f / degc;
    bool has = d > 0;
    float logd = has ? logf((float)d + 1.f) : 1.f;
    float amp = logd / AVG_D_LOG;
    float att = AVG_D_LOG / logd;
    if (l == 0) { g_amp[n] = amp; g_att[n] = att; }

    float* outh = g_aggh + (size_t)n * 256;
    float* outp = g_aggp + (size_t)n * 256;

    {
        float2 mean = make_float2(smh.x * inv, smh.y * inv);
        float2 var = make_float2(fmaxf(sqh.x * inv - mean.x * mean.x, 0.f),
                                 fmaxf(sqh.y * inv - mean.y * mean.y, 0.f));
        float2 sd = make_float2(sqrtf(var.x + EPS_STD), sqrtf(var.y + EPS_STD));
        float2 MX = has ? mxh : make_float2(0.f, 0.f);
        float2 MN = has ? mnh : make_float2(0.f, 0.f);
        *(float2*)(outh + 2 * l) = mean;
        *(float2*)(outh + 64 + 2 * l) = MX;
        *(float2*)(outh + 128 + 2 * l) = MN;
        *(float2*)(outh + 192 + 2 * l) = sd;
    }
    {
        float2 mean = make_float2(smp.x * inv, smp.y * inv);
        float2 var = make_float2(fmaxf(sqp.x * inv - mean.x * mean.x, 0.f),
                                 fmaxf(sqp.y * inv - mean.y * mean.y, 0.f));
        float2 sd = make_float2(sqrtf(var.x + EPS_STD), sqrtf(var.y + EPS_STD));
        float2 MX = has ? mxp : make_float2(0.f, 0.f);
        float2 MN = has ? mnp : make_float2(0.f, 0.f);
        *(float2*)(outp + 2 * l) = mean;
        *(float2*)(outp + 64 + 2 * l) = MX;
        *(float2*)(outp + 128 + 2 * l) = MN;
        *(float2*)(outp + 192 + 2 * l) = sd;
    }
}

// ---------------- node GEMMs with factored scalers (3 rails) ----------
__global__ void __launch_bounds__(256) k_nodegemm(
    const float* __restrict__ h, const float* __restrict__ p,
    const float* __restrict__ snorm,
    const float* __restrict__ Woh, const float* __restrict__ boh,
    const float* __restrict__ Wop, const float* __restrict__ bop,
    float* __restrict__ out)
{
    __shared__ __align__(16) float Xs[32 * 64];
    __shared__ __align__(16) float Ws[3 * 32 * 64];

    int tid = threadIdx.x;
    int base = blockIdx.x * 64;

    int tx = tid & 31;
    int te = tid >> 5;
    int le = tid & 63;
    int lh = (tid >> 6) * 8;
    int wkk = tid >> 3;
    int woc = (tid & 7) * 8;

    int nl = base + le;
    bool okl = nl < N;

    ull accI[4][2], accA[4][2], accT[4][2];

    // =================== phase H =========
#pragma unroll
    for (int i = 0; i < 4; i++)
#pragma unroll
        for (int j = 0; j < 2; j++) { accI[i][j] = 0ull; accA[i][j] = 0ull; accT[i][j] = 0ull; }

    for (int t = 0; t < 12; t++) {
        int k0 = t * 32;
        bool isAgg = (t >= 4);
        const float* rowp = isAgg ? (g_aggh + (size_t)nl * 256 + (k0 - 128))
                                  : (h + (size_t)nl * 128 + k0);
#pragma unroll
        for (int q = 0; q < 2; q++) {
            float4 a = okl ? *(const float4*)(rowp + lh + q * 4)
                           : make_float4(0.f, 0.f, 0.f, 0.f);
            Xs[(lh + q * 4 + 0) * 64 + le] = a.x;
            Xs[(lh + q * 4 + 1) * 64 + le] = a.y;
            Xs[(lh + q * 4 + 2) * 64 + le] = a.z;
            Xs[(lh + q * 4 + 3) * 64 + le] = a.w;
        }
        if (isAgg) {
            int aggk = k0 - 128;
            const float* wI = Woh + (size_t)(128 + aggk + wkk) * 64 + woc;
            const float* wA = Woh + (size_t)(384 + aggk + wkk) * 64 + woc;
            const float* wT = Woh + (size_t)(640 + aggk + wkk) * 64 + woc;
            *(float4*)&Ws[wkk * 64 + woc]              = *(const float4*)(wI);
            *(float4*)&Ws[wkk * 64 + woc + 4]          = *(const float4*)(wI + 4);
            *(float4*)&Ws[2048 + wkk * 64 + woc]       = *(const float4*)(wA);
            *(float4*)&Ws[2048 + wkk * 64 + woc + 4]   = *(const float4*)(wA + 4);
            *(float4*)&Ws[4096 + wkk * 64 + woc]       = *(const float4*)(wT);
            *(float4*)&Ws[4096 + wkk * 64 + woc + 4]   = *(const float4*)(wT + 4);
        } else {
            const float* wI = Woh + (size_t)(k0 + wkk) * 64 + woc;
            *(float4*)&Ws[wkk * 64 + woc]     = *(const float4*)(wI);
            *(float4*)&Ws[wkk * 64 + woc + 4] = *(const float4*)(wI + 4);
        }
        __syncthreads();
        if (isAgg) {
#pragma unroll 8
            for (int kk = 0; kk < 32; kk++) {
                float2 wi = *(const float2*)&Ws[kk * 64 + tx * 2];
                float2 wa = *(const float2*)&Ws[2048 + kk * 64 + tx * 2];
                float2 wt = *(const float2*)&Ws[4096 + kk * 64 + tx * 2];
                ull i0 = pack2(wi.x, wi.x), i1 = pack2(wi.y, wi.y);
                ull a0 = pack2(wa.x, wa.x), a1 = pack2(wa.y, wa.y);
                ull t0 = pack2(wt.x, wt.x), t1 = pack2(wt.y, wt.y);
                const ull* xp = (const ull*)&Xs[kk * 64 + te * 8];
#pragma unroll
                for (int i = 0; i < 4; i++) {
                    ull x = xp[i];
                    accI[i][0] = fma2(x, i0, accI[i][0]);
                    accI[i][1] = fma2(x, i1, accI[i][1]);
                    accA[i][0] = fma2(x, a0, accA[i][0]);
                    accA[i][1] = fma2(x, a1, accA[i][1]);
                    accT[i][0] = fma2(x, t0, accT[i][0]);
                    accT[i][1] = fma2(x, t1, accT[i][1]);
                }
            }
        } else {
#pragma unroll 8
            for (int kk = 0; kk < 32; kk++) {
                float2 wi = *(const float2*)&Ws[kk * 64 + tx * 2];
                ull i0 = pack2(wi.x, wi.x), i1 = pack2(wi.y, wi.y);
                const ull* xp = (const ull*)&Xs[kk * 64 + te * 8];
#pragma unroll
                for (int i = 0; i < 4; i++) {
                    ull x = xp[i];
                    accI[i][0] = fma2(x, i0, accI[i][0]);
                    accI[i][1] = fma2(x, i1, accI[i][1]);
                }
            }
        }
        __syncthreads();
    }
    {
        float2 bias = *(const float2*)&boh[tx * 2];
#pragma unroll
        for (int i = 0; i < 4; i++) {
            int n0 = base + te * 8 + 2 * i;
            float am0 = (n0 < N) ? g_amp[n0] : 0.f;
            float am1 = (n0 + 1 < N) ? g_amp[n0 + 1] : 0.f;
            float at0 = (n0 < N) ? g_att[n0] : 0.f;
            float at1 = (n0 + 1 < N) ? g_att[n0 + 1] : 0.f;
            ull ampP = pack2(am0, am1), attP = pack2(at0, at1);
            ull y0 = fma2(attP, accT[i][0], fma2(ampP, accA[i][0], accI[i][0]));
            ull y1 = fma2(attP, accT[i][1], fma2(ampP, accA[i][1], accI[i][1]));
            float2 u0 = unpack2(y0), u1 = unpack2(y1);
            if (n0 < N) {
                float sn = snorm[n0];
                *(float2*)&out[(size_t)n0 * 64 + tx * 2] =
                    make_float2((u0.x + bias.x) * sn, (u1.x + bias.y) * sn);
            }
            if (n0 + 1 < N) {
                float sn = snorm[n0 + 1];
                *(float2*)&out[(size_t)(n0 + 1) * 64 + tx * 2] =
                    make_float2((u0.y + bias.x) * sn, (u1.y + bias.y) * sn);
            }
        }
    }

    // =================== phase P ==========
#pragma unroll
    for (int i = 0; i < 4; i++)
#pragma unroll
        for (int j = 0; j < 2; j++) { accI[i][j] = 0ull; accA[i][j] = 0ull; accT[i][j] = 0ull; }

    for (int t = 0; t < 10; t++) {
        int k0 = t * 32;
        bool isAgg = (t >= 2);
        const float* rowp = isAgg ? (g_aggp + (size_t)nl * 256 + (k0 - 64))
                                  : (p + (size_t)nl * 64 + k0);
#pragma unroll
        for (int q = 0; q < 2; q++) {
            float4 a = okl ? *(const float4*)(rowp + lh + q * 4)
                           : make_float4(0.f, 0.f, 0.f, 0.f);
            Xs[(lh + q * 4 + 0) * 64 + le] = a.x;
            Xs[(lh + q * 4 + 1) * 64 + le] = a.y;
            Xs[(lh + q * 4 + 2) * 64 + le] = a.z;
            Xs[(lh + q * 4 + 3) * 64 + le] = a.w;
        }
        if (isAgg) {
            int aggk = k0 - 64;
            const float* wI = Wop + (size_t)(64 + aggk + wkk) * 64 + woc;
            const float* wA = Wop + (size_t)(320 + aggk + wkk) * 64 + woc;
            const float* wT = Wop + (size_t)(576 + aggk + wkk) * 64 + woc;
            *(float4*)&Ws[wkk * 64 + woc]              = *(const float4*)(wI);
            *(float4*)&Ws[wkk * 64 + woc + 4]          = *(const float4*)(wI + 4);
            *(float4*)&Ws[2048 + wkk * 64 + woc]       = *(const float4*)(wA);
            *(float4*)&Ws[2048 + wkk * 64 + woc + 4]   = *(const float4*)(wA + 4);
            *(float4*)&Ws[4096 + wkk * 64 + woc]       = *(const float4*)(wT);
            *(float4*)&Ws[4096 + wkk * 64 + woc + 4]   = *(const float4*)(wT + 4);
        } else {
            const float* wI = Wop + (size_t)(k0 + wkk) * 64 + woc;
            *(float4*)&Ws[wkk * 64 + woc]     = *(const float4*)(wI);
            *(float4*)&Ws[wkk * 64 + woc + 4] = *(const float4*)(wI + 4);
        }
        __syncthreads();
        if (isAgg) {
#pragma unroll 8
            for (int kk = 0; kk < 32; kk++) {
                float2 wi = *(const float2*)&Ws[kk * 64 + tx * 2];
                float2 wa = *(const float2*)&Ws[2048 + kk * 64 + tx * 2];
                float2 wt = *(const float2*)&Ws[4096 + kk * 64 + tx * 2];
                ull i0 = pack2(wi.x, wi.x), i1 = pack2(wi.y, wi.y);
                ull a0 = pack2(wa.x, wa.x), a1 = pack2(wa.y, wa.y);
                ull t0 = pack2(wt.x, wt.x), t1 = pack2(wt.y, wt.y);
                const ull* xp = (const ull*)&Xs[kk * 64 + te * 8];
#pragma unroll
                for (int i = 0; i < 4; i++) {
                    ull x = xp[i];
                    accI[i][0] = fma2(x, i0, accI[i][0]);
                    accI[i][1] = fma2(x, i1, accI[i][1]);
                    accA[i][0] = fma2(x, a0, accA[i][0]);
                    accA[i][1] = fma2(x, a1, accA[i][1]);
                    accT[i][0] = fma2(x, t0, accT[i][0]);
                    accT[i][1] = fma2(x, t1, accT[i][1]);
                }
            }
        } else {
#pragma unroll 8
            for (int kk = 0; kk < 32; kk++) {
                float2 wi = *(const float2*)&Ws[kk * 64 + tx * 2];
                ull i0 = pack2(wi.x, wi.x), i1 = pack2(wi.y, wi.y);
                const ull* xp = (const ull*)&Xs[kk * 64 + te * 8];
#pragma unroll
                for (int i = 0; i < 4; i++) {
                    ull x = xp[i];
                    accI[i][0] = fma2(x, i0, accI[i][0]);
                    accI[i][1] = fma2(x, i1, accI[i][1]);
                }
            }
        }
        __syncthreads();
    }
    {
        float2 bias = *(const float2*)&bop[tx * 2];
        float* outp = out + (size_t)N * 64;
#pragma unroll
        for (int i = 0; i < 4; i++) {
            int n0 = base + te * 8 + 2 * i;
            float am0 = (n0 < N) ? g_amp[n0] : 0.f;
            float am1 = (n0 + 1 < N) ? g_amp[n0 + 1] : 0.f;
            float at0 = (n0 < N) ? g_att[n0] : 0.f;
            float at1 = (n0 + 1 < N) ? g_att[n0 + 1] : 0.f;
            ull ampP = pack2(am0, am1), attP = pack2(at0, at1);
            ull y0 = fma2(attP, accT[i][0], fma2(ampP, accA[i][0], accI[i][0]));
            ull y1 = fma2(attP, accT[i][1], fma2(ampP, accA[i][1], accI[i][1]));
            float2 u0 = unpack2(y0), u1 = unpack2(y1);
            if (n0 < N)
                *(float2*)&outp[(size_t)n0 * 64 + tx * 2] =
                    make_float2(u0.x + bias.x, u1.x + bias.y);
            if (n0 + 1 < N)
                *(float2*)&outp[(size_t)(n0 + 1) * 64 + tx * 2] =
                    make_float2(u0.y + bias.x, u1.y + bias.y);
        }
    }
}

// ---------------- batchnorm stats ----------------
__global__ void k_bnstats(const float* __restrict__ out) {
    __shared__ float ss[4][64];
    __shared__ float sqv[4][64];
    int f = threadIdx.x & 63;
    int rg = threadIdx.x >> 6;
    int r0 = blockIdx.x * 128;
    int rend = r0 + 128;
    if (rend > N) rend = N;
    float s = 0.f, q = 0.f;
    for (int r = r0 + rg; r < rend; r += 4) {
        float x = out[(size_t)r * 64 + f];
        s += x; q += x * x;
    }
    ss[rg][f] = s; sqv[rg][f] = q;
    __syncthreads();
    if (threadIdx.x < 64) {
        float S = ss[0][f] + ss[1][f] + ss[2][f] + ss[3][f];
        float Q = sqv[0][f] + sqv[1][f] + sqv[2][f] + sqv[3][f];
        atomicAdd(&g_bnsum[f], S);
        atomicAdd(&g_bnsq[f], Q);
    }
}

// ---------------- batchnorm apply ----------------
__global__ void k_bnapply(float* __restrict__ out,
                          const float* __restrict__ gamma,
                          const float* __restrict__ beta) {
    int i = blockIdx.x * blockDim.x + threadIdx.x;
    if (i >= N * 64) return;
    int f = i & 63;
    const float invN = 1.f / (float)N;
    float mu = g_bnsum[f] * invN;
    float var = g_bnsq[f] * invN - mu * mu;
    float x = out[i];
    out[i] = (x - mu) * rsqrtf(var + EPS_BN) * gamma[f] + beta[f];
}

} // namespace

extern "C" void kernel_launch(void* const* d_in, const int* in_sizes, int n_in,
                              void* d_out, int out_size) {
    const float* h     = (const float*)d_in[0];
    const float* p     = (const float*)d_in[1];
    const float* e     = (const float*)d_in[2];
    const int*   src   = (const int*)d_in[3];
    const int*   dst   = (const int*)d_in[4];
    const float* snorm = (const float*)d_in[5];
    const float* Wph   = (const float*)d_in[6];
    const float* bph   = (const float*)d_in[7];
    const float* Wpp   = (const float*)d_in[8];
    const float* bpp   = (const float*)d_in[9];
    const float* Woh   = (const float*)d_in[10];
    const float* boh   = (const float*)d_in[11];
    const float* Wop   = (const float*)d_in[12];
    const float* bop   = (const float*)d_in[13];
    const float* gamma = (const float*)d_in[14];
    const float* beta  = (const float*)d_in[15];
    float* out = (float*)d_out;

    static cudaStream_t s_side = nullptr;
    static cudaEvent_t ev_fork = nullptr, ev_join = nullptr;
    if (s_side == nullptr) {
        cudaStreamCreateWithFlags(&s_side, cudaStreamNonBlocking);
        cudaEventCreateWithFlags(&ev_fork, cudaEventDisableTiming);
        cudaEventCreateWithFlags(&ev_join, cudaEventDisableTiming);
    }

    // fork: nodepre is independent of the hist/scan/scatter/edgeE chain
    cudaEventRecord(ev_fork, 0);
    cudaStreamWaitEvent(s_side, ev_fork, 0);
    k_nodepre<<<(N + 127) / 128, 256, 0, s_side>>>(h, p, Wph, Wpp);
    cudaEventRecord(ev_join, s_side);

    k_init<<<(N + 255) / 256, 256>>>();
    k_hist<<<(E + 255) / 256, 256>>>(dst);
    k_scan<<<1, 1024>>>();
    k_scatter<<<(E + 255) / 256, 256>>>(dst, src);
    k_edgeE<<<E / 128, 256>>>(e, Wph, bph, Wpp, bpp);

    cudaStreamWaitEvent(0, ev_join, 0);   // join before agg (needs g_A/g_B)
    k_agg<<<(N * 32 + 255) / 256, 256>>>();
    k_nodegemm<<<(N + 63) / 64, 256>>>(h, p, snorm, Woh, boh, Wop, bop, out);
    k_bnstats<<<(N + 127) / 128, 256>>>(out);
    k_bnapply<<<(N * 64 + 255) / 256, 256>>>(out, gamma, beta);
}

// round 8
// speedup vs baseline: 1.3407x; 1.0912x over previous
#include <cuda_runtime.h>
#include <cuda_fp16.h>
#include <math.h>

namespace {

constexpr int N = 50000;
constexpr int E = 800000;
constexpr float AVG_D_LOG = 2.8332f;
constexpr float EPS_STD = 1e-5f;
constexpr float EPS_BN = 1e-5f;
constexpr float FLT_BIG = 3.402823466e+38f;
constexpr int PITCH = 130;
constexpr int SCAN_BLOCKS = (N + 1023) / 1024;   // 49

typedef unsigned long long ull;

__device__ __forceinline__ ull fma2(ull a, ull b, ull c) {
    ull d;
    asm("fma.rn.f32x2 %0,%1,%2,%3;" : "=l"(d) : "l"(a), "l"(b), "l"(c));
    return d;
}
__device__ __forceinline__ ull pack2(float x, float y) {
    ull d;
    asm("mov.b64 %0,{%1,%2};" : "=l"(d) : "f"(x), "f"(y));
    return d;
}
__device__ __forceinline__ float2 unpack2(ull v) {
    float2 r;
    asm("mov.b64 {%0,%1},%2;" : "=f"(r.x), "=f"(r.y) : "l"(v));
    return r;
}

// ---- scratch (device globals: allocation-free contract) ----
__device__ int g_deg[N];
__device__ int g_offs[N + 1];
__device__ int g_cursor[N];
__device__ int g_perm[E];
__device__ int g_srcs[E];
__device__ int g_btot[SCAN_BLOCKS];
__device__ int g_boff[SCAN_BLOCKS];
__device__ __align__(16) __half g_A[(size_t)N * 128];    // [h@W1 | p@P1] fp16
__device__ __align__(16) __half g_B[(size_t)N * 128];    // [h@W2 | p@P2] fp16
__device__ __align__(16) __half g_ce[(size_t)E * 128];   // [e@W3+bh | e@P3+bp] fp16, ORIGINAL order
__device__ __align__(16) float g_aggh[(size_t)N * 256];  // [mean|max|min|std]
__device__ __align__(16) float g_aggp[(size_t)N * 256];
__device__ float g_amp[N];
__device__ float g_att[N];
__device__ float g_bnsum[64];
__device__ float g_bnsq[64];

// ---------------- init ----------------
__global__ void k_init() {
    int i = blockIdx.x * blockDim.x + threadIdx.x;
    if (i < N) g_deg[i] = 0;
    if (i < 64) { g_bnsum[i] = 0.f; g_bnsq[i] = 0.f; }
}

// ---------------- degree histogram ----------------
__global__ void k_hist(const int* __restrict__ dst) {
    int e = blockIdx.x * blockDim.x + threadIdx.x;
    if (e < E) atomicAdd(&g_deg[dst[e]], 1);
}

// ---------------- multi-block exclusive scan ----------------
__global__ void k_scan1() {
    __shared__ int ws[32];
    int t = threadIdx.x;
    int lane = t & 31, w = t >> 5;
    int base = blockIdx.x * 1024;
    int v = (base + t < N) ? g_deg[base + t] : 0;
    int x = v;
#pragma unroll
    for (int off = 1; off < 32; off <<= 1) {
        int y = __shfl_up_sync(0xffffffffu, x, off);
        if (lane >= off) x += y;
    }
    if (lane == 31) ws[w] = x;
    __syncthreads();
    if (w == 0) {
        int s = ws[lane];
#pragma unroll
        for (int off = 1; off < 32; off <<= 1) {
            int y = __shfl_up_sync(0xffffffffu, s, off);
            if (lane >= off) s += y;
        }
        ws[lane] = s;
    }
    __syncthreads();
    int incl = x + (w > 0 ? ws[w - 1] : 0);
    if (base + t < N) g_offs[base + t] = incl - v;     // chunk-local exclusive
    if (t == 1023) g_btot[blockIdx.x] = incl;          // chunk total
}

__global__ void k_scan2() {
    if (threadIdx.x == 0) {
        int acc = 0;
        for (int i = 0; i < SCAN_BLOCKS; i++) {
            g_boff[i] = acc;
            acc += g_btot[i];
        }
    }
}

__global__ void k_scan3() {
    int t = threadIdx.x;
    int base = blockIdx.x * 1024;
    int off = g_boff[blockIdx.x];
    if (base + t < N) {
        int v = g_offs[base + t] + off;
        g_offs[base + t] = v;
        g_cursor[base + t] = v;
    }
    if (blockIdx.x == 0 && t == 0) g_offs[N] = E;
}

// ---------------- scatter: counting sort by dst ----------------
__global__ void k_scatter(const int* __restrict__ dst, const int* __restrict__ src) {
    int e = blockIdx.x * blockDim.x + threadIdx.x;
    if (e < E) {
        int pos = atomicAdd(&g_cursor[dst[e]], 1);
        g_perm[pos] = e;
        g_srcs[pos] = src[e];
    }
}

// ---------------- node pre-GEMMs -> fp16 g_A, g_B --------------
__global__ void __launch_bounds__(256) k_nodepre(
    const float* __restrict__ h, const float* __restrict__ p,
    const float* __restrict__ Wh, const float* __restrict__ Wp)
{
    __shared__ __align__(16) float Xs[32 * PITCH];
    __shared__ __align__(16) float Ws[32 * 128];

    int tid = threadIdx.x;
    int base = blockIdx.x * 128;

    int tx = tid & 15;
    int te = tid >> 4;
    int le = tid & 127;
    int lh = (tid >> 7) * 16;
    int wkk = tid >> 3;
    int woc = (tid & 7) * 16;

    int nl = base + le;
    bool okl = nl < N;

    ull acca[4][4], accb[4][4];

    // ===== h phase =====
#pragma unroll
    for (int i = 0; i < 4; i++)
#pragma unroll
        for (int j = 0; j < 4; j++) { acca[i][j] = 0ull; accb[i][j] = 0ull; }

    for (int t = 0; t < 4; t++) {
        int k0 = t * 32;
        const float* rowp = h + (size_t)nl * 128 + k0;
#pragma unroll
        for (int q = 0; q < 4; q++) {
            float4 a = okl ? *(const float4*)(rowp + lh + q * 4)
                           : make_float4(0.f, 0.f, 0.f, 0.f);
            Xs[(lh + q * 4 + 0) * PITCH + le] = a.x;
            Xs[(lh + q * 4 + 1) * PITCH + le] = a.y;
            Xs[(lh + q * 4 + 2) * PITCH + le] = a.z;
            Xs[(lh + q * 4 + 3) * PITCH + le] = a.w;
        }
        {
            const float* wr = (woc < 64) ? (Wh + (size_t)(k0 + wkk) * 64 + woc)
                                         : (Wh + (size_t)(128 + k0 + wkk) * 64 + (woc - 64));
#pragma unroll
            for (int q = 0; q < 4; q++)
                *(float4*)&Ws[wkk * 128 + woc + q * 4] = *(const float4*)(wr + q * 4);
        }
        __syncthreads();
#pragma unroll 16
        for (int kk = 0; kk < 32; kk++) {
            float4 wa = *(const float4*)&Ws[kk * 128 + tx * 4];
            float4 wb = *(const float4*)&Ws[kk * 128 + 64 + tx * 4];
            ull a0 = pack2(wa.x, wa.x), a1 = pack2(wa.y, wa.y);
            ull a2 = pack2(wa.z, wa.z), a3 = pack2(wa.w, wa.w);
            ull b0 = pack2(wb.x, wb.x), b1 = pack2(wb.y, wb.y);
            ull b2 = pack2(wb.z, wb.z), b3 = pack2(wb.w, wb.w);
            const ull* xp = (const ull*)&Xs[kk * PITCH + te * 8];
#pragma unroll
            for (int i = 0; i < 4; i++) {
                ull x = xp[i];
                acca[i][0] = fma2(x, a0, acca[i][0]);
                acca[i][1] = fma2(x, a1, acca[i][1]);
                acca[i][2] = fma2(x, a2, acca[i][2]);
                acca[i][3] = fma2(x, a3, acca[i][3]);
                accb[i][0] = fma2(x, b0, accb[i][0]);
                accb[i][1] = fma2(x, b1, accb[i][1]);
                accb[i][2] = fma2(x, b2, accb[i][2]);
                accb[i][3] = fma2(x, b3, accb[i][3]);
            }
        }
        __syncthreads();
    }
#pragma unroll
    for (int i = 0; i < 4; i++) {
        float2 a0 = unpack2(acca[i][0]), a1 = unpack2(acca[i][1]);
        float2 a2 = unpack2(acca[i][2]), a3 = unpack2(acca[i][3]);
        float2 b0 = unpack2(accb[i][0]), b1 = unpack2(accb[i][1]);
        float2 b2 = unpack2(accb[i][2]), b3 = unpack2(accb[i][3]);
        int n0 = base + te * 8 + 2 * i;
        if (n0 < N) {
            __half* Ar = g_A + (size_t)n0 * 128 + tx * 4;
            __half* Br = g_B + (size_t)n0 * 128 + tx * 4;
            *(__half2*)Ar = __floats2half2_rn(a0.x, a1.x);
            *(__half2*)(Ar + 2) = __floats2half2_rn(a2.x, a3.x);
            *(__half2*)Br = __floats2half2_rn(b0.x, b1.x);
            *(__half2*)(Br + 2) = __floats2half2_rn(b2.x, b3.x);
        }
        if (n0 + 1 < N) {
            __half* Ar = g_A + (size_t)(n0 + 1) * 128 + tx * 4;
            __half* Br = g_B + (size_t)(n0 + 1) * 128 + tx * 4;
            *(__half2*)Ar = __floats2half2_rn(a0.y, a1.y);
            *(__half2*)(Ar + 2) = __floats2half2_rn(a2.y, a3.y);
            *(__half2*)Br = __floats2half2_rn(b0.y, b1.y);
            *(__half2*)(Br + 2) = __floats2half2_rn(b2.y, b3.y);
        }
    }

    // ===== p phase =====
#pragma unroll
    for (int i = 0; i < 4; i++)
#pragma unroll
        for (int j = 0; j < 4; j++) { acca[i][j] = 0ull; accb[i][j] = 0ull; }

    for (int t = 0; t < 2; t++) {
        int k0 = t * 32;
        const float* rowp = p + (size_t)nl * 64 + k0;
#pragma unroll
        for (int q = 0; q < 4; q++) {
            float4 a = okl ? *(const float4*)(rowp + lh + q * 4)
                           : make_float4(0.f, 0.f, 0.f, 0.f);
            Xs[(lh + q * 4 + 0) * PITCH + le] = a.x;
            Xs[(lh + q * 4 + 1) * PITCH + le] = a.y;
            Xs[(lh + q * 4 + 2) * PITCH + le] = a.z;
            Xs[(lh + q * 4 + 3) * PITCH + le] = a.w;
        }
        {
            const float* wr = (woc < 64) ? (Wp + (size_t)(k0 + wkk) * 64 + woc)
                                         : (Wp + (size_t)(64 + k0 + wkk) * 64 + (woc - 64));
#pragma unroll
            for (int q = 0; q < 4; q++)
                *(float4*)&Ws[wkk * 128 + woc + q * 4] = *(const float4*)(wr + q * 4);
        }
        __syncthreads();
#pragma unroll 16
        for (int kk = 0; kk < 32; kk++) {
            float4 wa = *(const float4*)&Ws[kk * 128 + tx * 4];
            float4 wb = *(const float4*)&Ws[kk * 128 + 64 + tx * 4];
            ull a0 = pack2(wa.x, wa.x), a1 = pack2(wa.y, wa.y);
            ull a2 = pack2(wa.z, wa.z), a3 = pack2(wa.w, wa.w);
            ull b0 = pack2(wb.x, wb.x), b1 = pack2(wb.y, wb.y);
            ull b2 = pack2(wb.z, wb.z), b3 = pack2(wb.w, wb.w);
            const ull* xp = (const ull*)&Xs[kk * PITCH + te * 8];
#pragma unroll
            for (int i = 0; i < 4; i++) {
                ull x = xp[i];
                acca[i][0] = fma2(x, a0, acca[i][0]);
                acca[i][1] = fma2(x, a1, acca[i][1]);
                acca[i][2] = fma2(x, a2, acca[i][2]);
                acca[i][3] = fma2(x, a3, acca[i][3]);
                accb[i][0] = fma2(x, b0, accb[i][0]);
                accb[i][1] = fma2(x, b1, accb[i][1]);
                accb[i][2] = fma2(x, b2, accb[i][2]);
                accb[i][3] = fma2(x, b3, accb[i][3]);
            }
        }
        __syncthreads();
    }
#pragma unroll
    for (int i = 0; i < 4; i++) {
        float2 a0 = unpack2(acca[i][0]), a1 = unpack2(acca[i][1]);
        float2 a2 = unpack2(acca[i][2]), a3 = unpack2(acca[i][3]);
        float2 b0 = unpack2(accb[i][0]), b1 = unpack2(accb[i][1]);
        float2 b2 = unpack2(accb[i][2]), b3 = unpack2(accb[i][3]);
        int n0 = base + te * 8 + 2 * i;
        if (n0 < N) {
            __half* Ar = g_A + (size_t)n0 * 128 + 64 + tx * 4;
            __half* Br = g_B + (size_t)n0 * 128 + 64 + tx * 4;
            *(__half2*)Ar = __floats2half2_rn(a0.x, a1.x);
            *(__half2*)(Ar + 2) = __floats2half2_rn(a2.x, a3.x);
            *(__half2*)Br = __floats2half2_rn(b0.x, b1.x);
            *(__half2*)(Br + 2) = __floats2half2_rn(b2.x, b3.x);
        }
        if (n0 + 1 < N) {
            __half* Ar = g_A + (size_t)(n0 + 1) * 128 + 64 + tx * 4;
            __half* Br = g_B + (size_t)(n0 + 1) * 128 + 64 + tx * 4;
            *(__half2*)Ar = __floats2half2_rn(a0.y, a1.y);
            *(__half2*)(Ar + 2) = __floats2half2_rn(a2.y, a3.y);
            *(__half2*)Br = __floats2half2_rn(b0.y, b1.y);
            *(__half2*)(Br + 2) = __floats2half2_rn(b2.y, b3.y);
        }
    }
}

// ---------------- edge-feature GEMM -> fp16 messages, ORIGINAL edge order ------------
__global__ void __launch_bounds__(256) k_edgeE(
    const float* __restrict__ ef,
    const float* __restrict__ Wh, const float* __restrict__ bh,
    const float* __restrict__ Wp, const float* __restrict__ bp)
{
    __shared__ __align__(16) float Xs[32 * PITCH];
    __shared__ __align__(16) float Ws[32 * 128];

    int tid = threadIdx.x;
    int base = blockIdx.x * 128;

    int tx = tid & 15;
    int te = tid >> 4;
    int le = tid & 127;
    int lh = (tid >> 7) * 16;
    int wkk = tid >> 3;
    int woc = (tid & 7) * 16;

    {
        const float* wr = (woc < 64) ? (Wh + (size_t)(256 + wkk) * 64 + woc)
                                     : (Wp + (size_t)(128 + wkk) * 64 + (woc - 64));
#pragma unroll
        for (int q = 0; q < 4; q++)
            *(float4*)&Ws[wkk * 128 + woc + q * 4] = *(const float4*)(wr + q * 4);
    }
    __syncthreads();
    {
        const float* rowp = ef + (size_t)(base + le) * 32;
#pragma unroll
        for (int q = 0; q < 4; q++) {
            float4 a = *(const float4*)(rowp + lh + q * 4);
            Xs[(lh + q * 4 + 0) * PITCH + le] = a.x;
            Xs[(lh + q * 4 + 1) * PITCH + le] = a.y;
            Xs[(lh + q * 4 + 2) * PITCH + le] = a.z;
            Xs[(lh + q * 4 + 3) * PITCH + le] = a.w;
        }
    }
    __syncthreads();

    ull acca[4][4], accb[4][4];
#pragma unroll
    for (int i = 0; i < 4; i++)
#pragma unroll
        for (int j = 0; j < 4; j++) { acca[i][j] = 0ull; accb[i][j] = 0ull; }

#pragma unroll 16
    for (int kk = 0; kk < 32; kk++) {
        float4 wa = *(const float4*)&Ws[kk * 128 + tx * 4];
        float4 wb = *(const float4*)&Ws[kk * 128 + 64 + tx * 4];
        ull a0 = pack2(wa.x, wa.x), a1 = pack2(wa.y, wa.y);
        ull a2 = pack2(wa.z, wa.z), a3 = pack2(wa.w, wa.w);
        ull b0 = pack2(wb.x, wb.x), b1 = pack2(wb.y, wb.y);
        ull b2 = pack2(wb.z, wb.z), b3 = pack2(wb.w, wb.w);
        const ull* xp = (const ull*)&Xs[kk * PITCH + te * 8];
#pragma unroll
        for (int i = 0; i < 4; i++) {
            ull x = xp[i];
            acca[i][0] = fma2(x, a0, acca[i][0]);
            acca[i][1] = fma2(x, a1, acca[i][1]);
            acca[i][2] = fma2(x, a2, acca[i][2]);
            acca[i][3] = fma2(x, a3, acca[i][3]);
            accb[i][0] = fma2(x, b0, accb[i][0]);
            accb[i][1] = fma2(x, b1, accb[i][1]);
            accb[i][2] = fma2(x, b2, accb[i][2]);
            accb[i][3] = fma2(x, b3, accb[i][3]);
        }
    }

    float4 biash = *(const float4*)&bh[tx * 4];
    float4 biasp = *(const float4*)&bp[tx * 4];
#pragma unroll
    for (int i = 0; i < 4; i++) {
        float2 a0 = unpack2(acca[i][0]), a1 = unpack2(acca[i][1]);
        float2 a2 = unpack2(acca[i][2]), a3 = unpack2(acca[i][3]);
        float2 b0 = unpack2(accb[i][0]), b1 = unpack2(accb[i][1]);
        float2 b2 = unpack2(accb[i][2]), b3 = unpack2(accb[i][3]);
        int pos = base + te * 8 + 2 * i;
        __half* r0 = g_ce + (size_t)pos * 128;
        __half* r1 = g_ce + (size_t)(pos + 1) * 128;
        {
            __half2 lo = __floats2half2_rn(a0.x + biash.x, a1.x + biash.y);
            __half2 hi = __floats2half2_rn(a2.x + biash.z, a3.x + biash.w);
            *(__half2*)(r0 + tx * 4) = lo; *(__half2*)(r0 + tx * 4 + 2) = hi;
            lo = __floats2half2_rn(a0.y + biash.x, a1.y + biash.y);
            hi = __floats2half2_rn(a2.y + biash.z, a3.y + biash.w);
            *(__half2*)(r1 + tx * 4) = lo; *(__half2*)(r1 + tx * 4 + 2) = hi;
        }
        {
            __half2 lo = __floats2half2_rn(b0.x + biasp.x, b1.x + biasp.y);
            __half2 hi = __floats2half2_rn(b2.x + biasp.z, b3.x + biasp.w);
            *(__half2*)(r0 + 64 + tx * 4) = lo; *(__half2*)(r0 + 64 + tx * 4 + 2) = hi;
            lo = __floats2half2_rn(b0.y + biasp.x, b1.y + biasp.y);
            hi = __floats2half2_rn(b2.y + biasp.z, b3.y + biasp.w);
            *(__half2*)(r1 + 64 + tx * 4) = lo; *(__half2*)(r1 + 64 + tx * 4 + 2) = hi;
        }
    }
}

// ---------------- fused message + PNA aggregation (warp per node, paired lanes) ------
__global__ void k_agg() {
    int warp = (blockIdx.x * blockDim.x + threadIdx.x) >> 5;
    int l = threadIdx.x & 31;
    if (warp >= N) return;
    int n = warp;
    int s0 = g_offs[n];
    int s1 = g_offs[n + 1];
    int d = s1 - s0;

    const __half* brow = g_B + (size_t)n * 128;
    float2 bh = __half22float2(*(const __half2*)(brow + 2 * l));
    float2 bp = __half22float2(*(const __half2*)(brow + 64 + 2 * l));

    float2 smh = make_float2(0.f, 0.f), smp = make_float2(0.f, 0.f);
    float2 sqh = make_float2(0.f, 0.f), sqp = make_float2(0.f, 0.f);
    float2 mxh = make_float2(-FLT_BIG, -FLT_BIG), mxp = make_float2(-FLT_BIG, -FLT_BIG);
    float2 mnh = make_float2(FLT_BIG, FLT_BIG), mnp = make_float2(FLT_BIG, FLT_BIG);

    for (int i = s0; i < s1; i++) {
        int s = g_srcs[i];
        int eid = g_perm[i];
        const __half* a = g_A + (size_t)s * 128;
        const __half* c = g_ce + (size_t)eid * 128;
        float2 ch = __half22float2(*(const __half2*)(c + 2 * l));
        float2 cp = __half22float2(*(const __half2*)(c + 64 + 2 * l));
        float2 ah = __half22float2(*(const __half2*)(a + 2 * l));
        float2 ap = __half22float2(*(const __half2*)(a + 64 + 2 * l));
        float v0 = ch.x + ah.x + bh.x;
        float v1 = ch.y + ah.y + bh.y;
        float v2 = cp.x + ap.x + bp.x;
        float v3 = cp.y + ap.y + bp.y;
        smh.x += v0; sqh.x += v0 * v0; mxh.x = fmaxf(mxh.x, v0); mnh.x = fminf(mnh.x, v0);
        smh.y += v1; sqh.y += v1 * v1; mxh.y = fmaxf(mxh.y, v1); mnh.y = fminf(mnh.y, v1);
        smp.x += v2; sqp.x += v2 * v2; mxp.x = fmaxf(mxp.x, v2); mnp.x = fminf(mnp.x, v2);
        smp.y += v3; sqp.y += v3 * v3; mxp.y = fmaxf(mxp.y, v3); mnp.y = fminf(mnp.y, v3);
    }

    float degc = fmaxf((float)d, 1.f);
    float inv = 1.f / degc;
    bool has = d > 0;
    float logd = has ? logf((float)d + 1.f) : 1.f;
    float amp = logd / AVG_D_LOG;
    float att = AVG_D_LOG / logd;
    if (l == 0) { g_amp[n] = amp; g_att[n] = att; }

    float* outh = g_aggh + (size_t)n * 256;
    float* outp = g_aggp + (size_t)n * 256;

    {
        float2 mean = make_float2(smh.x * inv, smh.y * inv);
        float2 var = make_float2(fmaxf(sqh.x * inv - mean.x * mean.x, 0.f),
                                 fmaxf(sqh.y * inv - mean.y * mean.y, 0.f));
        float2 sd = make_float2(sqrtf(var.x + EPS_STD), sqrtf(var.y + EPS_STD));
        float2 MX = has ? mxh : make_float2(0.f, 0.f);
        float2 MN = has ? mnh : make_float2(0.f, 0.f);
        *(float2*)(outh + 2 * l) = mean;
        *(float2*)(outh + 64 + 2 * l) = MX;
        *(float2*)(outh + 128 + 2 * l) = MN;
        *(float2*)(outh + 192 + 2 * l) = sd;
    }
    {
        float2 mean = make_float2(smp.x * inv, smp.y * inv);
        float2 var = make_float2(fmaxf(sqp.x * inv - mean.x * mean.x, 0.f),
                                 fmaxf(sqp.y * inv - mean.y * mean.y, 0.f));
        float2 sd = make_float2(sqrtf(var.x + EPS_STD), sqrtf(var.y + EPS_STD));
        float2 MX = has ? mxp : make_float2(0.f, 0.f);
        float2 MN = has ? mnp : make_float2(0.f, 0.f);
        *(float2*)(outp + 2 * l) = mean;
        *(float2*)(outp + 64 + 2 * l) = MX;
        *(float2*)(outp + 128 + 2 * l) = MN;
        *(float2*)(outp + 192 + 2 * l) = sd;
    }
}

// ---------------- node GEMMs with factored scalers (3 rails) ----------
__global__ void __launch_bounds__(256) k_nodegemm(
    const float* __restrict__ h, const float* __restrict__ p,
    const float* __restrict__ snorm,
    const float* __restrict__ Woh, const float* __restrict__ boh,
    const float* __restrict__ Wop, const float* __restrict__ bop,
    float* __restrict__ out)
{
    __shared__ __align__(16) float Xs[32 * 64];
    __shared__ __align__(16) float Ws[3 * 32 * 64];

    int tid = threadIdx.x;
    int base = blockIdx.x * 64;

    int tx = tid & 31;
    int te = tid >> 5;
    int le = tid & 63;
    int lh = (tid >> 6) * 8;
    int wkk = tid >> 3;
    int woc = (tid & 7) * 8;

    int nl = base + le;
    bool okl = nl < N;

    ull accI[4][2], accA[4][2], accT[4][2];

    // =================== phase H =========
#pragma unroll
    for (int i = 0; i < 4; i++)
#pragma unroll
        for (int j = 0; j < 2; j++) { accI[i][j] = 0ull; accA[i][j] = 0ull; accT[i][j] = 0ull; }

    for (int t = 0; t < 12; t++) {
        int k0 = t * 32;
        bool isAgg = (t >= 4);
        const float* rowp = isAgg ? (g_aggh + (size_t)nl * 256 + (k0 - 128))
                                  : (h + (size_t)nl * 128 + k0);
#pragma unroll
        for (int q = 0; q < 2; q++) {
            float4 a = okl ? *(const float4*)(rowp + lh + q * 4)
                           : make_float4(0.f, 0.f, 0.f, 0.f);
            Xs[(lh + q * 4 + 0) * 64 + le] = a.x;
            Xs[(lh + q * 4 + 1) * 64 + le] = a.y;
            Xs[(lh + q * 4 + 2) * 64 + le] = a.z;
            Xs[(lh + q * 4 + 3) * 64 + le] = a.w;
        }
        if (isAgg) {
            int aggk = k0 - 128;
            const float* wI = Woh + (size_t)(128 + aggk + wkk) * 64 + woc;
            const float* wA = Woh + (size_t)(384 + aggk + wkk) * 64 + woc;
            const float* wT = Woh + (size_t)(640 + aggk + wkk) * 64 + woc;
            *(float4*)&Ws[wkk * 64 + woc]              = *(const float4*)(wI);
            *(float4*)&Ws[wkk * 64 + woc + 4]          = *(const float4*)(wI + 4);
            *(float4*)&Ws[2048 + wkk * 64 + woc]       = *(const float4*)(wA);
            *(float4*)&Ws[2048 + wkk * 64 + woc + 4]   = *(const float4*)(wA + 4);
            *(float4*)&Ws[4096 + wkk * 64 + woc]       = *(const float4*)(wT);
            *(float4*)&Ws[4096 + wkk * 64 + woc + 4]   = *(const float4*)(wT + 4);
        } else {
            const float* wI = Woh + (size_t)(k0 + wkk) * 64 + woc;
            *(float4*)&Ws[wkk * 64 + woc]     = *(const float4*)(wI);
            *(float4*)&Ws[wkk * 64 + woc + 4] = *(const float4*)(wI + 4);
        }
        __syncthreads();
        if (isAgg) {
#pragma unroll 8
            for (int kk = 0; kk < 32; kk++) {
                float2 wi = *(const float2*)&Ws[kk * 64 + tx * 2];
                float2 wa = *(const float2*)&Ws[2048 + kk * 64 + tx * 2];
                float2 wt = *(const float2*)&Ws[4096 + kk * 64 + tx * 2];
                ull i0 = pack2(wi.x, wi.x), i1 = pack2(wi.y, wi.y);
                ull a0 = pack2(wa.x, wa.x), a1 = pack2(wa.y, wa.y);
                ull t0 = pack2(wt.x, wt.x), t1 = pack2(wt.y, wt.y);
                const ull* xp = (const ull*)&Xs[kk * 64 + te * 8];
#pragma unroll
                for (int i = 0; i < 4; i++) {
                    ull x = xp[i];
                    accI[i][0] = fma2(x, i0, accI[i][0]);
                    accI[i][1] = fma2(x, i1, accI[i][1]);
                    accA[i][0] = fma2(x, a0, accA[i][0]);
                    accA[i][1] = fma2(x, a1, accA[i][1]);
                    accT[i][0] = fma2(x, t0, accT[i][0]);
                    accT[i][1] = fma2(x, t1, accT[i][1]);
                }
            }
        } else {
#pragma unroll 8
            for (int kk = 0; kk < 32; kk++) {
                float2 wi = *(const float2*)&Ws[kk * 64 + tx * 2];
                ull i0 = pack2(wi.x, wi.x), i1 = pack2(wi.y, wi.y);
                const ull* xp = (const ull*)&Xs[kk * 64 + te * 8];
#pragma unroll
                for (int i = 0; i < 4; i++) {
                    ull x = xp[i];
                    accI[i][0] = fma2(x, i0, accI[i][0]);
                    accI[i][1] = fma2(x, i1, accI[i][1]);
                }
            }
        }
        __syncthreads();
    }
    {
        float2 bias = *(const float2*)&boh[tx * 2];
#pragma unroll
        for (int i = 0; i < 4; i++) {
            int n0 = base + te * 8 + 2 * i;
            float am0 = (n0 < N) ? g_amp[n0] : 0.f;
            float am1 = (n0 + 1 < N) ? g_amp[n0 + 1] : 0.f;
            float at0 = (n0 < N) ? g_att[n0] : 0.f;
            float at1 = (n0 + 1 < N) ? g_att[n0 + 1] : 0.f;
            ull ampP = pack2(am0, am1), attP = pack2(at0, at1);
            ull y0 = fma2(attP, accT[i][0], fma2(ampP, accA[i][0], accI[i][0]));
            ull y1 = fma2(attP, accT[i][1], fma2(ampP, accA[i][1], accI[i][1]));
            float2 u0 = unpack2(y0), u1 = unpack2(y1);
            if (n0 < N) {
                float sn = snorm[n0];
                *(float2*)&out[(size_t)n0 * 64 + tx * 2] =
                    make_float2((u0.x + bias.x) * sn, (u1.x + bias.y) * sn);
            }
            if (n0 + 1 < N) {
                float sn = snorm[n0 + 1];
                *(float2*)&out[(size_t)(n0 + 1) * 64 + tx * 2] =
                    make_float2((u0.y + bias.x) * sn, (u1.y + bias.y) * sn);
            }
        }
    }

    // =================== phase P ==========
#pragma unroll
    for (int i = 0; i < 4; i++)
#pragma unroll
        for (int j = 0; j < 2; j++) { accI[i][j] = 0ull; accA[i][j] = 0ull; accT[i][j] = 0ull; }

    for (int t = 0; t < 10; t++) {
        int k0 = t * 32;
        bool isAgg = (t >= 2);
        const float* rowp = isAgg ? (g_aggp + (size_t)nl * 256 + (k0 - 64))
                                  : (p + (size_t)nl * 64 + k0);
#pragma unroll
        for (int q = 0; q < 2; q++) {
            float4 a = okl ? *(const float4*)(rowp + lh + q * 4)
                           : make_float4(0.f, 0.f, 0.f, 0.f);
            Xs[(lh + q * 4 + 0) * 64 + le] = a.x;
            Xs[(lh + q * 4 + 1) * 64 + le] = a.y;
            Xs[(lh + q * 4 + 2) * 64 + le] = a.z;
            Xs[(lh + q * 4 + 3) * 64 + le] = a.w;
        }
        if (isAgg) {
            int aggk = k0 - 64;
            const float* wI = Wop + (size_t)(64 + aggk + wkk) * 64 + woc;
            const float* wA = Wop + (size_t)(320 + aggk + wkk) * 64 + woc;
            const float* wT = Wop + (size_t)(576 + aggk + wkk) * 64 + woc;
            *(float4*)&Ws[wkk * 64 + woc]              = *(const float4*)(wI);
            *(float4*)&Ws[wkk * 64 + woc + 4]          = *(const float4*)(wI + 4);
            *(float4*)&Ws[2048 + wkk * 64 + woc]       = *(const float4*)(wA);
            *(float4*)&Ws[2048 + wkk * 64 + woc + 4]   = *(const float4*)(wA + 4);
            *(float4*)&Ws[4096 + wkk * 64 + woc]       = *(const float4*)(wT);
            *(float4*)&Ws[4096 + wkk * 64 + woc + 4]   = *(const float4*)(wT + 4);
        } else {
            const float* wI = Wop + (size_t)(k0 + wkk) * 64 + woc;
            *(float4*)&Ws[wkk * 64 + woc]     = *(const float4*)(wI);
            *(float4*)&Ws[wkk * 64 + woc + 4] = *(const float4*)(wI + 4);
        }
        __syncthreads();
        if (isAgg) {
#pragma unroll 8
            for (int kk = 0; kk < 32; kk++) {
                float2 wi = *(const float2*)&Ws[kk * 64 + tx * 2];
                float2 wa = *(const float2*)&Ws[2048 + kk * 64 + tx * 2];
                float2 wt = *(const float2*)&Ws[4096 + kk * 64 + tx * 2];
                ull i0 = pack2(wi.x, wi.x), i1 = pack2(wi.y, wi.y);
                ull a0 = pack2(wa.x, wa.x), a1 = pack2(wa.y, wa.y);
                ull t0 = pack2(wt.x, wt.x), t1 = pack2(wt.y, wt.y);
                const ull* xp = (const ull*)&Xs[kk * 64 + te * 8];
#pragma unroll
                for (int i = 0; i < 4; i++) {
                    ull x = xp[i];
                    accI[i][0] = fma2(x, i0, accI[i][0]);
                    accI[i][1] = fma2(x, i1, accI[i][1]);
                    accA[i][0] = fma2(x, a0, accA[i][0]);
                    accA[i][1] = fma2(x, a1, accA[i][1]);
                    accT[i][0] = fma2(x, t0, accT[i][0]);
                    accT[i][1] = fma2(x, t1, accT[i][1]);
                }
            }
        } else {
#pragma unroll 8
            for (int kk = 0; kk < 32; kk++) {
                float2 wi = *(const float2*)&Ws[kk * 64 + tx * 2];
                ull i0 = pack2(wi.x, wi.x), i1 = pack2(wi.y, wi.y);
                const ull* xp = (const ull*)&Xs[kk * 64 + te * 8];
#pragma unroll
                for (int i = 0; i < 4; i++) {
                    ull x = xp[i];
                    accI[i][0] = fma2(x, i0, accI[i][0]);
                    accI[i][1] = fma2(x, i1, accI[i][1]);
                }
            }
        }
        __syncthreads();
    }
    {
        float2 bias = *(const float2*)&bop[tx * 2];
        float* outp = out + (size_t)N * 64;
#pragma unroll
        for (int i = 0; i < 4; i++) {
            int n0 = base + te * 8 + 2 * i;
            float am0 = (n0 < N) ? g_amp[n0] : 0.f;
            float am1 = (n0 + 1 < N) ? g_amp[n0 + 1] : 0.f;
            float at0 = (n0 < N) ? g_att[n0] : 0.f;
            float at1 = (n0 + 1 < N) ? g_att[n0 + 1] : 0.f;
            ull ampP = pack2(am0, am1), attP = pack2(at0, at1);
            ull y0 = fma2(attP, accT[i][0], fma2(ampP, accA[i][0], accI[i][0]));
            ull y1 = fma2(attP, accT[i][1], fma2(ampP, accA[i][1], accI[i][1]));
            float2 u0 = unpack2(y0), u1 = unpack2(y1);
            if (n0 < N)
                *(float2*)&outp[(size_t)n0 * 64 + tx * 2] =
                    make_float2(u0.x + bias.x, u1.x + bias.y);
            if (n0 + 1 < N)
                *(float2*)&outp[(size_t)(n0 + 1) * 64 + tx * 2] =
                    make_float2(u0.y + bias.x, u1.y + bias.y);
        }
    }
}

// ---------------- batchnorm stats ----------------
__global__ void k_bnstats(const float* __restrict__ out) {
    __shared__ float ss[4][64];
    __shared__ float sqv[4][64];
    int f = threadIdx.x & 63;
    int rg = threadIdx.x >> 6;
    int r0 = blockIdx.x * 128;
    int rend = r0 + 128;
    if (rend > N) rend = N;
    float s = 0.f, q = 0.f;
    for (int r = r0 + rg; r < rend; r += 4) {
        float x = out[(size_t)r * 64 + f];
        s += x; q += x * x;
    }
    ss[rg][f] = s; sqv[rg][f] = q;
    __syncthreads();
    if (threadIdx.x < 64) {
        float S = ss[0][f] + ss[1][f] + ss[2][f] + ss[3][f];
        float Q = sqv[0][f] + sqv[1][f] + sqv[2][f] + sqv[3][f];
        atomicAdd(&g_bnsum[f], S);
        atomicAdd(&g_bnsq[f], Q);
    }
}

// ---------------- batchnorm apply ----------------
__global__ void k_bnapply(float* __restrict__ out,
                          const float* __restrict__ gamma,
                          const float* __restrict__ beta) {
    int i = blockIdx.x * blockDim.x + threadIdx.x;
    if (i >= N * 64) return;
    int f = i & 63;
    const float invN = 1.f / (float)N;
    float mu = g_bnsum[f] * invN;
    float var = g_bnsq[f] * invN - mu * mu;
    float x = out[i];
    out[i] = (x - mu) * rsqrtf(var + EPS_BN) * gamma[f] + beta[f];
}

} // namespace

extern "C" void kernel_launch(void* const* d_in, const int* in_sizes, int n_in,
                              void* d_out, int out_size) {
    const float* h     = (const float*)d_in[0];
    const float* p     = (const float*)d_in[1];
    const float* e     = (const float*)d_in[2];
    const int*   src   = (const int*)d_in[3];
    const int*   dst   = (const int*)d_in[4];
    const float* snorm = (const float*)d_in[5];
    const float* Wph   = (const float*)d_in[6];
    const float* bph   = (const float*)d_in[7];
    const float* Wpp   = (const float*)d_in[8];
    const float* bpp   = (const float*)d_in[9];
    const float* Woh   = (const float*)d_in[10];
    const float* boh   = (const float*)d_in[11];
    const float* Wop   = (const float*)d_in[12];
    const float* bop   = (const float*)d_in[13];
    const float* gamma = (const float*)d_in[14];
    const float* beta  = (const float*)d_in[15];
    float* out = (float*)d_out;

    static cudaStream_t s_pre = nullptr, s_edge = nullptr;
    static cudaEvent_t ev_fork = nullptr, ev_pre = nullptr, ev_edge = nullptr;
    if (s_pre == nullptr) {
        cudaStreamCreateWithFlags(&s_pre, cudaStreamNonBlocking);
        cudaStreamCreateWithFlags(&s_edge, cudaStreamNonBlocking);
        cudaEventCreateWithFlags(&ev_fork, cudaEventDisableTiming);
        cudaEventCreateWithFlags(&ev_pre, cudaEventDisableTiming);
        cudaEventCreateWithFlags(&ev_edge, cudaEventDisableTiming);
    }

    cudaEventRecord(ev_fork, 0);
    cudaStreamWaitEvent(s_pre, ev_fork, 0);
    cudaStreamWaitEvent(s_edge, ev_fork, 0);

    // side stream 1: node pre-GEMMs (independent)
    k_nodepre<<<(N + 127) / 128, 256, 0, s_pre>>>(h, p, Wph, Wpp);
    cudaEventRecord(ev_pre, s_pre);

    // side stream 2: edge-feature GEMM in ORIGINAL edge order (independent)
    k_edgeE<<<E / 128, 256, 0, s_edge>>>(e, Wph, bph, Wpp, bpp);
    cudaEventRecord(ev_edge, s_edge);

    // main stream: CSR construction
    k_init<<<(N + 255) / 256, 256>>>();
    k_hist<<<(E + 255) / 256, 256>>>(dst);
    k_scan1<<<SCAN_BLOCKS, 1024>>>();
    k_scan2<<<1, 32>>>();
    k_scan3<<<SCAN_BLOCKS, 1024>>>();
    k_scatter<<<(E + 255) / 256, 256>>>(dst, src);

    // join: agg needs g_A/g_B (pre), g_ce (edge), g_perm/g_srcs/g_offs (main)
    cudaStreamWaitEvent(0, ev_pre, 0);
    cudaStreamWaitEvent(0, ev_edge, 0);
    k_agg<<<(N * 32 + 255) / 256, 256>>>();
    k_nodegemm<<<(N + 63) / 64, 256>>>(h, p, snorm, Woh, boh, Wop, bop, out);
    k_bnstats<<<(N + 127) / 128, 256>>>(out);
    k_bnapply<<<(N * 64 + 255) / 256, 256>>>(out, gamma, beta);
}

// round 9
// speedup vs baseline: 1.3659x; 1.0188x over previous
#include <cuda_runtime.h>
#include <cuda_fp16.h>
#include <math.h>

namespace {

constexpr int N = 50000;
constexpr int E = 800000;
constexpr float AVG_D_LOG = 2.8332f;
constexpr float EPS_STD = 1e-5f;
constexpr float EPS_BN = 1e-5f;
constexpr float FLT_BIG = 3.402823466e+38f;
constexpr int PITCH = 130;
constexpr int SCAN_BLOCKS = (N + 1023) / 1024;   // 49

typedef unsigned long long ull;

__device__ __forceinline__ ull fma2(ull a, ull b, ull c) {
    ull d;
    asm("fma.rn.f32x2 %0,%1,%2,%3;" : "=l"(d) : "l"(a), "l"(b), "l"(c));
    return d;
}
__device__ __forceinline__ ull pack2(float x, float y) {
    ull d;
    asm("mov.b64 %0,{%1,%2};" : "=l"(d) : "f"(x), "f"(y));
    return d;
}
__device__ __forceinline__ float2 unpack2(ull v) {
    float2 r;
    asm("mov.b64 {%0,%1},%2;" : "=f"(r.x), "=f"(r.y) : "l"(v));
    return r;
}

// ---- scratch (device globals: allocation-free contract) ----
__device__ int g_deg[N];
__device__ int g_offs[N + 1];
__device__ int g_cursor[N];
__device__ int g_perm[E];
__device__ int g_srcs[E];
__device__ int g_btot[SCAN_BLOCKS];
__device__ int g_boff[SCAN_BLOCKS];
__device__ __align__(16) __half g_A[(size_t)N * 128];    // [h@W1 | p@P1] fp16
__device__ __align__(16) __half g_B[(size_t)N * 128];    // [h@W2 | p@P2] fp16
__device__ __align__(16) __half g_ce[(size_t)E * 128];   // [e@W3+bh | e@P3+bp] fp16, ORIGINAL order
__device__ __align__(16) float g_aggh[(size_t)N * 256];  // [mean|max|min|std]
__device__ __align__(16) float g_aggp[(size_t)N * 256];
__device__ float g_amp[N];
__device__ float g_att[N];
__device__ float g_bnsum[64];
__device__ float g_bnsq[64];

// ---------------- init ----------------
__global__ void k_init() {
    int i = blockIdx.x * blockDim.x + threadIdx.x;
    if (i < N) g_deg[i] = 0;
    if (i < 64) { g_bnsum[i] = 0.f; g_bnsq[i] = 0.f; }
}

// ---------------- degree histogram ----------------
__global__ void k_hist(const int* __restrict__ dst) {
    int e = blockIdx.x * blockDim.x + threadIdx.x;
    if (e < E) atomicAdd(&g_deg[dst[e]], 1);
}

// ---------------- multi-block exclusive scan ----------------
__global__ void k_scan1() {
    __shared__ int ws[32];
    int t = threadIdx.x;
    int lane = t & 31, w = t >> 5;
    int base = blockIdx.x * 1024;
    int v = (base + t < N) ? g_deg[base + t] : 0;
    int x = v;
#pragma unroll
    for (int off = 1; off < 32; off <<= 1) {
        int y = __shfl_up_sync(0xffffffffu, x, off);
        if (lane >= off) x += y;
    }
    if (lane == 31) ws[w] = x;
    __syncthreads();
    if (w == 0) {
        int s = ws[lane];
#pragma unroll
        for (int off = 1; off < 32; off <<= 1) {
            int y = __shfl_up_sync(0xffffffffu, s, off);
            if (lane >= off) s += y;
        }
        ws[lane] = s;
    }
    __syncthreads();
    int incl = x + (w > 0 ? ws[w - 1] : 0);
    if (base + t < N) g_offs[base + t] = incl - v;
    if (t == 1023) g_btot[blockIdx.x] = incl;
}

__global__ void k_scan2() {
    if (threadIdx.x == 0) {
        int acc = 0;
        for (int i = 0; i < SCAN_BLOCKS; i++) {
            g_boff[i] = acc;
            acc += g_btot[i];
        }
    }
}

__global__ void k_scan3() {
    int t = threadIdx.x;
    int base = blockIdx.x * 1024;
    int off = g_boff[blockIdx.x];
    if (base + t < N) {
        int v = g_offs[base + t] + off;
        g_offs[base + t] = v;
        g_cursor[base + t] = v;
    }
    if (blockIdx.x == 0 && t == 0) g_offs[N] = E;
}

// ---------------- scatter: counting sort by dst ----------------
__global__ void k_scatter(const int* __restrict__ dst, const int* __restrict__ src) {
    int e = blockIdx.x * blockDim.x + threadIdx.x;
    if (e < E) {
        int pos = atomicAdd(&g_cursor[dst[e]], 1);
        g_perm[pos] = e;
        g_srcs[pos] = src[e];
    }
}

// ---------------- node pre-GEMMs -> fp16 g_A, g_B --------------
__global__ void __launch_bounds__(256) k_nodepre(
    const float* __restrict__ h, const float* __restrict__ p,
    const float* __restrict__ Wh, const float* __restrict__ Wp)
{
    __shared__ __align__(16) float Xs[32 * PITCH];
    __shared__ __align__(16) float Ws[32 * 128];

    int tid = threadIdx.x;
    int base = blockIdx.x * 128;

    int tx = tid & 15;
    int te = tid >> 4;
    int le = tid & 127;
    int lh = (tid >> 7) * 16;
    int wkk = tid >> 3;
    int woc = (tid & 7) * 16;

    int nl = base + le;
    bool okl = nl < N;

    ull acca[4][4], accb[4][4];

    // ===== h phase =====
#pragma unroll
    for (int i = 0; i < 4; i++)
#pragma unroll
        for (int j = 0; j < 4; j++) { acca[i][j] = 0ull; accb[i][j] = 0ull; }

    for (int t = 0; t < 4; t++) {
        int k0 = t * 32;
        const float* rowp = h + (size_t)nl * 128 + k0;
#pragma unroll
        for (int q = 0; q < 4; q++) {
            float4 a = okl ? *(const float4*)(rowp + lh + q * 4)
                           : make_float4(0.f, 0.f, 0.f, 0.f);
            Xs[(lh + q * 4 + 0) * PITCH + le] = a.x;
            Xs[(lh + q * 4 + 1) * PITCH + le] = a.y;
            Xs[(lh + q * 4 + 2) * PITCH + le] = a.z;
            Xs[(lh + q * 4 + 3) * PITCH + le] = a.w;
        }
        {
            const float* wr = (woc < 64) ? (Wh + (size_t)(k0 + wkk) * 64 + woc)
                                         : (Wh + (size_t)(128 + k0 + wkk) * 64 + (woc - 64));
#pragma unroll
            for (int q = 0; q < 4; q++)
                *(float4*)&Ws[wkk * 128 + woc + q * 4] = *(const float4*)(wr + q * 4);
        }
        __syncthreads();
#pragma unroll 16
        for (int kk = 0; kk < 32; kk++) {
            float4 wa = *(const float4*)&Ws[kk * 128 + tx * 4];
            float4 wb = *(const float4*)&Ws[kk * 128 + 64 + tx * 4];
            ull a0 = pack2(wa.x, wa.x), a1 = pack2(wa.y, wa.y);
            ull a2 = pack2(wa.z, wa.z), a3 = pack2(wa.w, wa.w);
            ull b0 = pack2(wb.x, wb.x), b1 = pack2(wb.y, wb.y);
            ull b2 = pack2(wb.z, wb.z), b3 = pack2(wb.w, wb.w);
            const ull* xp = (const ull*)&Xs[kk * PITCH + te * 8];
#pragma unroll
            for (int i = 0; i < 4; i++) {
                ull x = xp[i];
                acca[i][0] = fma2(x, a0, acca[i][0]);
                acca[i][1] = fma2(x, a1, acca[i][1]);
                acca[i][2] = fma2(x, a2, acca[i][2]);
                acca[i][3] = fma2(x, a3, acca[i][3]);
                accb[i][0] = fma2(x, b0, accb[i][0]);
                accb[i][1] = fma2(x, b1, accb[i][1]);
                accb[i][2] = fma2(x, b2, accb[i][2]);
                accb[i][3] = fma2(x, b3, accb[i][3]);
            }
        }
        __syncthreads();
    }
#pragma unroll
    for (int i = 0; i < 4; i++) {
        float2 a0 = unpack2(acca[i][0]), a1 = unpack2(acca[i][1]);
        float2 a2 = unpack2(acca[i][2]), a3 = unpack2(acca[i][3]);
        float2 b0 = unpack2(accb[i][0]), b1 = unpack2(accb[i][1]);
        float2 b2 = unpack2(accb[i][2]), b3 = unpack2(accb[i][3]);
        int n0 = base + te * 8 + 2 * i;
        if (n0 < N) {
            __half* Ar = g_A + (size_t)n0 * 128 + tx * 4;
            __half* Br = g_B + (size_t)n0 * 128 + tx * 4;
            *(__half2*)Ar = __floats2half2_rn(a0.x, a1.x);
            *(__half2*)(Ar + 2) = __floats2half2_rn(a2.x, a3.x);
            *(__half2*)Br = __floats2half2_rn(b0.x, b1.x);
            *(__half2*)(Br + 2) = __floats2half2_rn(b2.x, b3.x);
        }
        if (n0 + 1 < N) {
            __half* Ar = g_A + (size_t)(n0 + 1) * 128 + tx * 4;
            __half* Br = g_B + (size_t)(n0 + 1) * 128 + tx * 4;
            *(__half2*)Ar = __floats2half2_rn(a0.y, a1.y);
            *(__half2*)(Ar + 2) = __floats2half2_rn(a2.y, a3.y);
            *(__half2*)Br = __floats2half2_rn(b0.y, b1.y);
            *(__half2*)(Br + 2) = __floats2half2_rn(b2.y, b3.y);
        }
    }

    // ===== p phase =====
#pragma unroll
    for (int i = 0; i < 4; i++)
#pragma unroll
        for (int j = 0; j < 4; j++) { acca[i][j] = 0ull; accb[i][j] = 0ull; }

    for (int t = 0; t < 2; t++) {
        int k0 = t * 32;
        const float* rowp = p + (size_t)nl * 64 + k0;
#pragma unroll
        for (int q = 0; q < 4; q++) {
            float4 a = okl ? *(const float4*)(rowp + lh + q * 4)
                           : make_float4(0.f, 0.f, 0.f, 0.f);
            Xs[(lh + q * 4 + 0) * PITCH + le] = a.x;
            Xs[(lh + q * 4 + 1) * PITCH + le] = a.y;
            Xs[(lh + q * 4 + 2) * PITCH + le] = a.z;
            Xs[(lh + q * 4 + 3) * PITCH + le] = a.w;
        }
        {
            const float* wr = (woc < 64) ? (Wp + (size_t)(k0 + wkk) * 64 + woc)
                                         : (Wp + (size_t)(64 + k0 + wkk) * 64 + (woc - 64));
#pragma unroll
            for (int q = 0; q < 4; q++)
                *(float4*)&Ws[wkk * 128 + woc + q * 4] = *(const float4*)(wr + q * 4);
        }
        __syncthreads();
#pragma unroll 16
        for (int kk = 0; kk < 32; kk++) {
            float4 wa = *(const float4*)&Ws[kk * 128 + tx * 4];
            float4 wb = *(const float4*)&Ws[kk * 128 + 64 + tx * 4];
            ull a0 = pack2(wa.x, wa.x), a1 = pack2(wa.y, wa.y);
            ull a2 = pack2(wa.z, wa.z), a3 = pack2(wa.w, wa.w);
            ull b0 = pack2(wb.x, wb.x), b1 = pack2(wb.y, wb.y);
            ull b2 = pack2(wb.z, wb.z), b3 = pack2(wb.w, wb.w);
            const ull* xp = (const ull*)&Xs[kk * PITCH + te * 8];
#pragma unroll
            for (int i = 0; i < 4; i++) {
                ull x = xp[i];
                acca[i][0] = fma2(x, a0, acca[i][0]);
                acca[i][1] = fma2(x, a1, acca[i][1]);
                acca[i][2] = fma2(x, a2, acca[i][2]);
                acca[i][3] = fma2(x, a3, acca[i][3]);
                accb[i][0] = fma2(x, b0, accb[i][0]);
                accb[i][1] = fma2(x, b1, accb[i][1]);
                accb[i][2] = fma2(x, b2, accb[i][2]);
                accb[i][3] = fma2(x, b3, accb[i][3]);
            }
        }
        __syncthreads();
    }
#pragma unroll
    for (int i = 0; i < 4; i++) {
        float2 a0 = unpack2(acca[i][0]), a1 = unpack2(acca[i][1]);
        float2 a2 = unpack2(acca[i][2]), a3 = unpack2(acca[i][3]);
        float2 b0 = unpack2(accb[i][0]), b1 = unpack2(accb[i][1]);
        float2 b2 = unpack2(accb[i][2]), b3 = unpack2(accb[i][3]);
        int n0 = base + te * 8 + 2 * i;
        if (n0 < N) {
            __half* Ar = g_A + (size_t)n0 * 128 + 64 + tx * 4;
            __half* Br = g_B + (size_t)n0 * 128 + 64 + tx * 4;
            *(__half2*)Ar = __floats2half2_rn(a0.x, a1.x);
            *(__half2*)(Ar + 2) = __floats2half2_rn(a2.x, a3.x);
            *(__half2*)Br = __floats2half2_rn(b0.x, b1.x);
            *(__half2*)(Br + 2) = __floats2half2_rn(b2.x, b3.x);
        }
        if (n0 + 1 < N) {
            __half* Ar = g_A + (size_t)(n0 + 1) * 128 + 64 + tx * 4;
            __half* Br = g_B + (size_t)(n0 + 1) * 128 + 64 + tx * 4;
            *(__half2*)Ar = __floats2half2_rn(a0.y, a1.y);
            *(__half2*)(Ar + 2) = __floats2half2_rn(a2.y, a3.y);
            *(__half2*)Br = __floats2half2_rn(b0.y, b1.y);
            *(__half2*)(Br + 2) = __floats2half2_rn(b2.y, b3.y);
        }
    }
}

// ---------------- edge-feature GEMM -> fp16 messages, ORIGINAL edge order ------------
__global__ void __launch_bounds__(256) k_edgeE(
    const float* __restrict__ ef,
    const float* __restrict__ Wh, const float* __restrict__ bh,
    const float* __restrict__ Wp, const float* __restrict__ bp)
{
    __shared__ __align__(16) float Xs[32 * PITCH];
    __shared__ __align__(16) float Ws[32 * 128];

    int tid = threadIdx.x;
    int base = blockIdx.x * 128;

    int tx = tid & 15;
    int te = tid >> 4;
    int le = tid & 127;
    int lh = (tid >> 7) * 16;
    int wkk = tid >> 3;
    int woc = (tid & 7) * 16;

    {
        const float* wr = (woc < 64) ? (Wh + (size_t)(256 + wkk) * 64 + woc)
                                     : (Wp + (size_t)(128 + wkk) * 64 + (woc - 64));
#pragma unroll
        for (int q = 0; q < 4; q++)
            *(float4*)&Ws[wkk * 128 + woc + q * 4] = *(const float4*)(wr + q * 4);
    }
    __syncthreads();
    {
        const float* rowp = ef + (size_t)(base + le) * 32;
#pragma unroll
        for (int q = 0; q < 4; q++) {
            float4 a = *(const float4*)(rowp + lh + q * 4);
            Xs[(lh + q * 4 + 0) * PITCH + le] = a.x;
            Xs[(lh + q * 4 + 1) * PITCH + le] = a.y;
            Xs[(lh + q * 4 + 2) * PITCH + le] = a.z;
            Xs[(lh + q * 4 + 3) * PITCH + le] = a.w;
        }
    }
    __syncthreads();

    ull acca[4][4], accb[4][4];
#pragma unroll
    for (int i = 0; i < 4; i++)
#pragma unroll
        for (int j = 0; j < 4; j++) { acca[i][j] = 0ull; accb[i][j] = 0ull; }

#pragma unroll 16
    for (int kk = 0; kk < 32; kk++) {
        float4 wa = *(const float4*)&Ws[kk * 128 + tx * 4];
        float4 wb = *(const float4*)&Ws[kk * 128 + 64 + tx * 4];
        ull a0 = pack2(wa.x, wa.x), a1 = pack2(wa.y, wa.y);
        ull a2 = pack2(wa.z, wa.z), a3 = pack2(wa.w, wa.w);
        ull b0 = pack2(wb.x, wb.x), b1 = pack2(wb.y, wb.y);
        ull b2 = pack2(wb.z, wb.z), b3 = pack2(wb.w, wb.w);
        const ull* xp = (const ull*)&Xs[kk * PITCH + te * 8];
#pragma unroll
        for (int i = 0; i < 4; i++) {
            ull x = xp[i];
            acca[i][0] = fma2(x, a0, acca[i][0]);
            acca[i][1] = fma2(x, a1, acca[i][1]);
            acca[i][2] = fma2(x, a2, acca[i][2]);
            acca[i][3] = fma2(x, a3, acca[i][3]);
            accb[i][0] = fma2(x, b0, accb[i][0]);
            accb[i][1] = fma2(x, b1, accb[i][1]);
            accb[i][2] = fma2(x, b2, accb[i][2]);
            accb[i][3] = fma2(x, b3, accb[i][3]);
        }
    }

    float4 biash = *(const float4*)&bh[tx * 4];
    float4 biasp = *(const float4*)&bp[tx * 4];
#pragma unroll
    for (int i = 0; i < 4; i++) {
        float2 a0 = unpack2(acca[i][0]), a1 = unpack2(acca[i][1]);
        float2 a2 = unpack2(acca[i][2]), a3 = unpack2(acca[i][3]);
        float2 b0 = unpack2(accb[i][0]), b1 = unpack2(accb[i][1]);
        float2 b2 = unpack2(accb[i][2]), b3 = unpack2(accb[i][3]);
        int pos = base + te * 8 + 2 * i;
        __half* r0 = g_ce + (size_t)pos * 128;
        __half* r1 = g_ce + (size_t)(pos + 1) * 128;
        {
            __half2 lo = __floats2half2_rn(a0.x + biash.x, a1.x + biash.y);
            __half2 hi = __floats2half2_rn(a2.x + biash.z, a3.x + biash.w);
            *(__half2*)(r0 + tx * 4) = lo; *(__half2*)(r0 + tx * 4 + 2) = hi;
            lo = __floats2half2_rn(a0.y + biash.x, a1.y + biash.y);
            hi = __floats2half2_rn(a2.y + biash.z, a3.y + biash.w);
            *(__half2*)(r1 + tx * 4) = lo; *(__half2*)(r1 + tx * 4 + 2) = hi;
        }
        {
            __half2 lo = __floats2half2_rn(b0.x + biasp.x, b1.x + biasp.y);
            __half2 hi = __floats2half2_rn(b2.x + biasp.z, b3.x + biasp.w);
            *(__half2*)(r0 + 64 + tx * 4) = lo; *(__half2*)(r0 + 64 + tx * 4 + 2) = hi;
            lo = __floats2half2_rn(b0.y + biasp.x, b1.y + biasp.y);
            hi = __floats2half2_rn(b2.y + biasp.z, b3.y + biasp.w);
            *(__half2*)(r1 + 64 + tx * 4) = lo; *(__half2*)(r1 + 64 + tx * 4 + 2) = hi;
        }
    }
}

// ---------------- fused message + PNA aggregation (2x-unrolled, prefetch) ------------
__global__ void k_agg() {
    int warp = (blockIdx.x * blockDim.x + threadIdx.x) >> 5;
    int l = threadIdx.x & 31;
    if (warp >= N) return;
    int n = warp;
    int s0 = g_offs[n];
    int s1 = g_offs[n + 1];
    int d = s1 - s0;

    const __half* brow = g_B + (size_t)n * 128;
    float2 bh = __half22float2(*(const __half2*)(brow + 2 * l));
    float2 bp = __half22float2(*(const __half2*)(brow + 64 + 2 * l));

    float2 smh = make_float2(0.f, 0.f), smp = make_float2(0.f, 0.f);
    float2 sqh = make_float2(0.f, 0.f), sqp = make_float2(0.f, 0.f);
    float2 mxh = make_float2(-FLT_BIG, -FLT_BIG), mxp = make_float2(-FLT_BIG, -FLT_BIG);
    float2 mnh = make_float2(FLT_BIG, FLT_BIG), mnp = make_float2(FLT_BIG, FLT_BIG);

#define AGG_ACC(CH, CP, AH, AP)                                                    \
    do {                                                                           \
        float v0 = (CH).x + (AH).x + bh.x;                                         \
        float v1 = (CH).y + (AH).y + bh.y;                                         \
        float v2 = (CP).x + (AP).x + bp.x;                                         \
        float v3 = (CP).y + (AP).y + bp.y;                                         \
        smh.x += v0; sqh.x += v0 * v0; mxh.x = fmaxf(mxh.x, v0); mnh.x = fminf(mnh.x, v0); \
        smh.y += v1; sqh.y += v1 * v1; mxh.y = fmaxf(mxh.y, v1); mnh.y = fminf(mnh.y, v1); \
        smp.x += v2; sqp.x += v2 * v2; mxp.x = fmaxf(mxp.x, v2); mnp.x = fminf(mnp.x, v2); \
        smp.y += v3; sqp.y += v3 * v3; mxp.y = fmaxf(mxp.y, v3); mnp.y = fminf(mnp.y, v3); \
    } while (0)

    int i = s0;
    if ((s1 - s0) & 1) {
        int s = g_srcs[i];
        int eid = g_perm[i];
        const __half* a = g_A + (size_t)s * 128;
        const __half* c = g_ce + (size_t)eid * 128;
        float2 ch = __half22float2(*(const __half2*)(c + 2 * l));
        float2 cp = __half22float2(*(const __half2*)(c + 64 + 2 * l));
        float2 ah = __half22float2(*(const __half2*)(a + 2 * l));
        float2 ap = __half22float2(*(const __half2*)(a + 64 + 2 * l));
        AGG_ACC(ch, cp, ah, ap);
        i++;
    }
    for (; i < s1; i += 2) {
        int sA = g_srcs[i],     sB = g_srcs[i + 1];
        int eA = g_perm[i],     eB = g_perm[i + 1];
        const __half* aA = g_A + (size_t)sA * 128;
        const __half* cA = g_ce + (size_t)eA * 128;
        const __half* aB = g_A + (size_t)sB * 128;
        const __half* cB = g_ce + (size_t)eB * 128;
        // issue all 8 loads before consuming — doubles MLP against L2 latency
        __half2 chA = *(const __half2*)(cA + 2 * l);
        __half2 cpA = *(const __half2*)(cA + 64 + 2 * l);
        __half2 ahA = *(const __half2*)(aA + 2 * l);
        __half2 apA = *(const __half2*)(aA + 64 + 2 * l);
        __half2 chB = *(const __half2*)(cB + 2 * l);
        __half2 cpB = *(const __half2*)(cB + 64 + 2 * l);
        __half2 ahB = *(const __half2*)(aB + 2 * l);
        __half2 apB = *(const __half2*)(aB + 64 + 2 * l);
        float2 f0 = __half22float2(chA), f1 = __half22float2(cpA);
        float2 f2 = __half22float2(ahA), f3 = __half22float2(apA);
        AGG_ACC(f0, f1, f2, f3);
        f0 = __half22float2(chB); f1 = __half22float2(cpB);
        f2 = __half22float2(ahB); f3 = __half22float2(apB);
        AGG_ACC(f0, f1, f2, f3);
    }
#undef AGG_ACC

    float degc = fmaxf((float)d, 1.f);
    float inv = 1.f / degc;
    bool has = d > 0;
    float logd = has ? logf((float)d + 1.f) : 1.f;
    float amp = logd / AVG_D_LOG;
    float att = AVG_D_LOG / logd;
    if (l == 0) { g_amp[n] = amp; g_att[n] = att; }

    float* outh = g_aggh + (size_t)n * 256;
    float* outp = g_aggp + (size_t)n * 256;

    {
        float2 mean = make_float2(smh.x * inv, smh.y * inv);
        float2 var = make_float2(fmaxf(sqh.x * inv - mean.x * mean.x, 0.f),
                                 fmaxf(sqh.y * inv - mean.y * mean.y, 0.f));
        float2 sd = make_float2(sqrtf(var.x + EPS_STD), sqrtf(var.y + EPS_STD));
        float2 MX = has ? mxh : make_float2(0.f, 0.f);
        float2 MN = has ? mnh : make_float2(0.f, 0.f);
        *(float2*)(outh + 2 * l) = mean;
        *(float2*)(outh + 64 + 2 * l) = MX;
        *(float2*)(outh + 128 + 2 * l) = MN;
        *(float2*)(outh + 192 + 2 * l) = sd;
    }
    {
        float2 mean = make_float2(smp.x * inv, smp.y * inv);
        float2 var = make_float2(fmaxf(sqp.x * inv - mean.x * mean.x, 0.f),
                                 fmaxf(sqp.y * inv - mean.y * mean.y, 0.f));
        float2 sd = make_float2(sqrtf(var.x + EPS_STD), sqrtf(var.y + EPS_STD));
        float2 MX = has ? mxp : make_float2(0.f, 0.f);
        float2 MN = has ? mnp : make_float2(0.f, 0.f);
        *(float2*)(outp + 2 * l) = mean;
        *(float2*)(outp + 64 + 2 * l) = MX;
        *(float2*)(outp + 128 + 2 * l) = MN;
        *(float2*)(outp + 192 + 2 * l) = sd;
    }
}

// ---------------- node GEMMs: 3 rails + FUSED BN stats (reuses Xs smem) ----------
__global__ void __launch_bounds__(256) k_nodegemm(
    const float* __restrict__ h, const float* __restrict__ p,
    const float* __restrict__ snorm,
    const float* __restrict__ Woh, const float* __restrict__ boh,
    const float* __restrict__ Wop, const float* __restrict__ bop,
    float* __restrict__ out)
{
    __shared__ __align__(16) float Xs[32 * 64];
    __shared__ __align__(16) float Ws[3 * 32 * 64];

    int tid = threadIdx.x;
    int base = blockIdx.x * 64;

    int tx = tid & 31;
    int te = tid >> 5;
    int le = tid & 63;
    int lh = (tid >> 6) * 8;
    int wkk = tid >> 3;
    int woc = (tid & 7) * 8;

    int nl = base + le;
    bool okl = nl < N;

    ull accI[4][2], accA[4][2], accT[4][2];

    // =================== phase H =========
#pragma unroll
    for (int i = 0; i < 4; i++)
#pragma unroll
        for (int j = 0; j < 2; j++) { accI[i][j] = 0ull; accA[i][j] = 0ull; accT[i][j] = 0ull; }

    for (int t = 0; t < 12; t++) {
        int k0 = t * 32;
        bool isAgg = (t >= 4);
        const float* rowp = isAgg ? (g_aggh + (size_t)nl * 256 + (k0 - 128))
                                  : (h + (size_t)nl * 128 + k0);
#pragma unroll
        for (int q = 0; q < 2; q++) {
            float4 a = okl ? *(const float4*)(rowp + lh + q * 4)
                           : make_float4(0.f, 0.f, 0.f, 0.f);
            Xs[(lh + q * 4 + 0) * 64 + le] = a.x;
            Xs[(lh + q * 4 + 1) * 64 + le] = a.y;
            Xs[(lh + q * 4 + 2) * 64 + le] = a.z;
            Xs[(lh + q * 4 + 3) * 64 + le] = a.w;
        }
        if (isAgg) {
            int aggk = k0 - 128;
            const float* wI = Woh + (size_t)(128 + aggk + wkk) * 64 + woc;
            const float* wA = Woh + (size_t)(384 + aggk + wkk) * 64 + woc;
            const float* wT = Woh + (size_t)(640 + aggk + wkk) * 64 + woc;
            *(float4*)&Ws[wkk * 64 + woc]              = *(const float4*)(wI);
            *(float4*)&Ws[wkk * 64 + woc + 4]          = *(const float4*)(wI + 4);
            *(float4*)&Ws[2048 + wkk * 64 + woc]       = *(const float4*)(wA);
            *(float4*)&Ws[2048 + wkk * 64 + woc + 4]   = *(const float4*)(wA + 4);
            *(float4*)&Ws[4096 + wkk * 64 + woc]       = *(const float4*)(wT);
            *(float4*)&Ws[4096 + wkk * 64 + woc + 4]   = *(const float4*)(wT + 4);
        } else {
            const float* wI = Woh + (size_t)(k0 + wkk) * 64 + woc;
            *(float4*)&Ws[wkk * 64 + woc]     = *(const float4*)(wI);
            *(float4*)&Ws[wkk * 64 + woc + 4] = *(const float4*)(wI + 4);
        }
        __syncthreads();
        if (isAgg) {
#pragma unroll 8
            for (int kk = 0; kk < 32; kk++) {
                float2 wi = *(const float2*)&Ws[kk * 64 + tx * 2];
                float2 wa = *(const float2*)&Ws[2048 + kk * 64 + tx * 2];
                float2 wt = *(const float2*)&Ws[4096 + kk * 64 + tx * 2];
                ull i0 = pack2(wi.x, wi.x), i1 = pack2(wi.y, wi.y);
                ull a0 = pack2(wa.x, wa.x), a1 = pack2(wa.y, wa.y);
                ull t0 = pack2(wt.x, wt.x), t1 = pack2(wt.y, wt.y);
                const ull* xp = (const ull*)&Xs[kk * 64 + te * 8];
#pragma unroll
                for (int i = 0; i < 4; i++) {
                    ull x = xp[i];
                    accI[i][0] = fma2(x, i0, accI[i][0]);
                    accI[i][1] = fma2(x, i1, accI[i][1]);
                    accA[i][0] = fma2(x, a0, accA[i][0]);
                    accA[i][1] = fma2(x, a1, accA[i][1]);
                    accT[i][0] = fma2(x, t0, accT[i][0]);
                    accT[i][1] = fma2(x, t1, accT[i][1]);
                }
            }
        } else {
#pragma unroll 8
            for (int kk = 0; kk < 32; kk++) {
                float2 wi = *(const float2*)&Ws[kk * 64 + tx * 2];
                ull i0 = pack2(wi.x, wi.x), i1 = pack2(wi.y, wi.y);
                const ull* xp = (const ull*)&Xs[kk * 64 + te * 8];
#pragma unroll
                for (int i = 0; i < 4; i++) {
                    ull x = xp[i];
                    accI[i][0] = fma2(x, i0, accI[i][0]);
                    accI[i][1] = fma2(x, i1, accI[i][1]);
                }
            }
        }
        __syncthreads();
    }
    {
        float2 bias = *(const float2*)&boh[tx * 2];
        float s0 = 0.f, q0 = 0.f, s1 = 0.f, q1 = 0.f;
#pragma unroll
        for (int i = 0; i < 4; i++) {
            int n0 = base + te * 8 + 2 * i;
            float am0 = (n0 < N) ? g_amp[n0] : 0.f;
            float am1 = (n0 + 1 < N) ? g_amp[n0 + 1] : 0.f;
            float at0 = (n0 < N) ? g_att[n0] : 0.f;
            float at1 = (n0 + 1 < N) ? g_att[n0 + 1] : 0.f;
            ull ampP = pack2(am0, am1), attP = pack2(at0, at1);
            ull y0 = fma2(attP, accT[i][0], fma2(ampP, accA[i][0], accI[i][0]));
            ull y1 = fma2(attP, accT[i][1], fma2(ampP, accA[i][1], accI[i][1]));
            float2 u0 = unpack2(y0), u1 = unpack2(y1);
            if (n0 < N) {
                float sn = snorm[n0];
                float o0 = (u0.x + bias.x) * sn, o1 = (u1.x + bias.y) * sn;
                *(float2*)&out[(size_t)n0 * 64 + tx * 2] = make_float2(o0, o1);
                s0 += o0; q0 += o0 * o0; s1 += o1; q1 += o1 * o1;
            }
            if (n0 + 1 < N) {
                float sn = snorm[n0 + 1];
                float o0 = (u0.y + bias.x) * sn, o1 = (u1.y + bias.y) * sn;
                *(float2*)&out[(size_t)(n0 + 1) * 64 + tx * 2] = make_float2(o0, o1);
                s0 += o0; q0 += o0 * o0; s1 += o1; q1 += o1 * o1;
            }
        }
        // fused BN-stats reduction: reuse Xs (2048 floats) as [sum:0..511 | sq:512..1023]
        __syncthreads();
        Xs[te * 64 + 2 * tx]       = s0;
        Xs[te * 64 + 2 * tx + 1]   = s1;
        Xs[512 + te * 64 + 2 * tx]     = q0;
        Xs[512 + te * 64 + 2 * tx + 1] = q1;
        __syncthreads();
        if (tid < 64) {
            float S = 0.f, Q = 0.f;
#pragma unroll
            for (int r = 0; r < 8; r++) { S += Xs[r * 64 + tid]; Q += Xs[512 + r * 64 + tid]; }
            atomicAdd(&g_bnsum[tid], S);
            atomicAdd(&g_bnsq[tid], Q);
        }
        __syncthreads();
    }

    // =================== phase P ==========
#pragma unroll
    for (int i = 0; i < 4; i++)
#pragma unroll
        for (int j = 0; j < 2; j++) { accI[i][j] = 0ull; accA[i][j] = 0ull; accT[i][j] = 0ull; }

    for (int t = 0; t < 10; t++) {
        int k0 = t * 32;
        bool isAgg = (t >= 2);
        const float* rowp = isAgg ? (g_aggp + (size_t)nl * 256 + (k0 - 64))
                                  : (p + (size_t)nl * 64 + k0);
#pragma unroll
        for (int q = 0; q < 2; q++) {
            float4 a = okl ? *(const float4*)(rowp + lh + q * 4)
                           : make_float4(0.f, 0.f, 0.f, 0.f);
            Xs[(lh + q * 4 + 0) * 64 + le] = a.x;
            Xs[(lh + q * 4 + 1) * 64 + le] = a.y;
            Xs[(lh + q * 4 + 2) * 64 + le] = a.z;
            Xs[(lh + q * 4 + 3) * 64 + le] = a.w;
        }
        if (isAgg) {
            int aggk = k0 - 64;
            const float* wI = Wop + (size_t)(64 + aggk + wkk) * 64 + woc;
            const float* wA = Wop + (size_t)(320 + aggk + wkk) * 64 + woc;
            const float* wT = Wop + (size_t)(576 + aggk + wkk) * 64 + woc;
            *(float4*)&Ws[wkk * 64 + woc]              = *(const float4*)(wI);
            *(float4*)&Ws[wkk * 64 + woc + 4]          = *(const float4*)(wI + 4);
            *(float4*)&Ws[2048 + wkk * 64 + woc]       = *(const float4*)(wA);
            *(float4*)&Ws[2048 + wkk * 64 + woc + 4]   = *(const float4*)(wA + 4);
            *(float4*)&Ws[4096 + wkk * 64 + woc]       = *(const float4*)(wT);
            *(float4*)&Ws[4096 + wkk * 64 + woc + 4]   = *(const float4*)(wT + 4);
        } else {
            const float* wI = Wop + (size_t)(k0 + wkk) * 64 + woc;
            *(float4*)&Ws[wkk * 64 + woc]     = *(const float4*)(wI);
            *(float4*)&Ws[wkk * 64 + woc + 4] = *(const float4*)(wI + 4);
        }
        __syncthreads();
        if (isAgg) {
#pragma unroll 8
            for (int kk = 0; kk < 32; kk++) {
                float2 wi = *(const float2*)&Ws[kk * 64 + tx * 2];
                float2 wa = *(const float2*)&Ws[2048 + kk * 64 + tx * 2];
                float2 wt = *(const float2*)&Ws[4096 + kk * 64 + tx * 2];
                ull i0 = pack2(wi.x, wi.x), i1 = pack2(wi.y, wi.y);
                ull a0 = pack2(wa.x, wa.x), a1 = pack2(wa.y, wa.y);
                ull t0 = pack2(wt.x, wt.x), t1 = pack2(wt.y, wt.y);
                const ull* xp = (const ull*)&Xs[kk * 64 + te * 8];
#pragma unroll
                for (int i = 0; i < 4; i++) {
                    ull x = xp[i];
                    accI[i][0] = fma2(x, i0, accI[i][0]);
                    accI[i][1] = fma2(x, i1, accI[i][1]);
                    accA[i][0] = fma2(x, a0, accA[i][0]);
                    accA[i][1] = fma2(x, a1, accA[i][1]);
                    accT[i][0] = fma2(x, t0, accT[i][0]);
                    accT[i][1] = fma2(x, t1, accT[i][1]);
                }
            }
        } else {
#pragma unroll 8
            for (int kk = 0; kk < 32; kk++) {
                float2 wi = *(const float2*)&Ws[kk * 64 + tx * 2];
                ull i0 = pack2(wi.x, wi.x), i1 = pack2(wi.y, wi.y);
                const ull* xp = (const ull*)&Xs[kk * 64 + te * 8];
#pragma unroll
                for (int i = 0; i < 4; i++) {
                    ull x = xp[i];
                    accI[i][0] = fma2(x, i0, accI[i][0]);
                    accI[i][1] = fma2(x, i1, accI[i][1]);
                }
            }
        }
        __syncthreads();
    }
    {
        float2 bias = *(const float2*)&bop[tx * 2];
        float* outp = out + (size_t)N * 64;
#pragma unroll
        for (int i = 0; i < 4; i++) {
            int n0 = base + te * 8 + 2 * i;
            float am0 = (n0 < N) ? g_amp[n0] : 0.f;
            float am1 = (n0 + 1 < N) ? g_amp[n0 + 1] : 0.f;
            float at0 = (n0 < N) ? g_att[n0] : 0.f;
            float at1 = (n0 + 1 < N) ? g_att[n0 + 1] : 0.f;
            ull ampP = pack2(am0, am1), attP = pack2(at0, at1);
            ull y0 = fma2(attP, accT[i][0], fma2(ampP, accA[i][0], accI[i][0]));
            ull y1 = fma2(attP, accT[i][1], fma2(ampP, accA[i][1], accI[i][1]));
            float2 u0 = unpack2(y0), u1 = unpack2(y1);
            if (n0 < N)
                *(float2*)&outp[(size_t)n0 * 64 + tx * 2] =
                    make_float2(u0.x + bias.x, u1.x + bias.y);
            if (n0 + 1 < N)
                *(float2*)&outp[(size_t)(n0 + 1) * 64 + tx * 2] =
                    make_float2(u0.y + bias.x, u1.y + bias.y);
        }
    }
}

// ---------------- batchnorm apply ----------------
__global__ void k_bnapply(float* __restrict__ out,
                          const float* __restrict__ gamma,
                          const float* __restrict__ beta) {
    int i = blockIdx.x * blockDim.x + threadIdx.x;
    if (i >= N * 64) return;
    int f = i & 63;
    const float invN = 1.f / (float)N;
    float mu = g_bnsum[f] * invN;
    float var = g_bnsq[f] * invN - mu * mu;
    float x = out[i];
    out[i] = (x - mu) * rsqrtf(var + EPS_BN) * gamma[f] + beta[f];
}

} // namespace

extern "C" void kernel_launch(void* const* d_in, const int* in_sizes, int n_in,
                              void* d_out, int out_size) {
    const float* h     = (const float*)d_in[0];
    const float* p     = (const float*)d_in[1];
    const float* e     = (const float*)d_in[2];
    const int*   src   = (const int*)d_in[3];
    const int*   dst   = (const int*)d_in[4];
    const float* snorm = (const float*)d_in[5];
    const float* Wph   = (const float*)d_in[6];
    const float* bph   = (const float*)d_in[7];
    const float* Wpp   = (const float*)d_in[8];
    const float* bpp   = (const float*)d_in[9];
    const float* Woh   = (const float*)d_in[10];
    const float* boh   = (const float*)d_in[11];
    const float* Wop   = (const float*)d_in[12];
    const float* bop   = (const float*)d_in[13];
    const float* gamma = (const float*)d_in[14];
    const float* beta  = (const float*)d_in[15];
    float* out = (float*)d_out;

    static cudaStream_t s_pre = nullptr, s_edge = nullptr;
    static cudaEvent_t ev_fork = nullptr, ev_pre = nullptr, ev_edge = nullptr;
    if (s_pre == nullptr) {
        cudaStreamCreateWithFlags(&s_pre, cudaStreamNonBlocking);
        cudaStreamCreateWithFlags(&s_edge, cudaStreamNonBlocking);
        cudaEventCreateWithFlags(&ev_fork, cudaEventDisableTiming);
        cudaEventCreateWithFlags(&ev_pre, cudaEventDisableTiming);
        cudaEventCreateWithFlags(&ev_edge, cudaEventDisableTiming);
    }

    cudaEventRecord(ev_fork, 0);
    cudaStreamWaitEvent(s_pre, ev_fork, 0);
    cudaStreamWaitEvent(s_edge, ev_fork, 0);

    // side stream 1: node pre-GEMMs (independent)
    k_nodepre<<<(N + 127) / 128, 256, 0, s_pre>>>(h, p, Wph, Wpp);
    cudaEventRecord(ev_pre, s_pre);

    // side stream 2: edge-feature GEMM in ORIGINAL edge order (independent)
    k_edgeE<<<E / 128, 256, 0, s_edge>>>(e, Wph, bph, Wpp, bpp);
    cudaEventRecord(ev_edge, s_edge);

    // main stream: CSR construction
    k_init<<<(N + 255) / 256, 256>>>();
    k_hist<<<(E + 255) / 256, 256>>>(dst);
    k_scan1<<<SCAN_BLOCKS, 1024>>>();
    k_scan2<<<1, 32>>>();
    k_scan3<<<SCAN_BLOCKS, 1024>>>();
    k_scatter<<<(E + 255) / 256, 256>>>(dst, src);

    // join: agg needs g_A/g_B (pre), g_ce (edge), g_perm/g_srcs/g_offs (main)
    cudaStreamWaitEvent(0, ev_pre, 0);
    cudaStreamWaitEvent(0, ev_edge, 0);
    k_agg<<<(N * 32 + 255) / 256, 256>>>();
    k_nodegemm<<<(N + 63) / 64, 256>>>(h, p, snorm, Woh, boh, Wop, bop, out);
    k_bnapply<<<(N * 64 + 255) / 256, 256>>>(out, gamma, beta);
}

// round 10
// speedup vs baseline: 1.4077x; 1.0306x over previous
#include <cuda_runtime.h>
#include <cuda_fp16.h>
#include <math.h>

namespace {

constexpr int N = 50000;
constexpr int E = 800000;
constexpr float AVG_D_LOG = 2.8332f;
constexpr float EPS_STD = 1e-5f;
constexpr float EPS_BN = 1e-5f;
constexpr float FLT_BIG = 3.402823466e+38f;
constexpr int PITCH = 130;
constexpr int SCAN_BLOCKS = (N + 1023) / 1024;   // 49

typedef unsigned long long ull;

__device__ __forceinline__ ull fma2(ull a, ull b, ull c) {
    ull d;
    asm("fma.rn.f32x2 %0,%1,%2,%3;" : "=l"(d) : "l"(a), "l"(b), "l"(c));
    return d;
}
__device__ __forceinline__ ull pack2(float x, float y) {
    ull d;
    asm("mov.b64 %0,{%1,%2};" : "=l"(d) : "f"(x), "f"(y));
    return d;
}
__device__ __forceinline__ float2 unpack2(ull v) {
    float2 r;
    asm("mov.b64 {%0,%1},%2;" : "=f"(r.x), "=f"(r.y) : "l"(v));
    return r;
}
// 8-byte load of 4 halfs -> float4
__device__ __forceinline__ float4 ldh4(const __half* ptr) {
    uint2 u = *(const uint2*)ptr;
    __half2 lo = *reinterpret_cast<__half2*>(&u.x);
    __half2 hi = *reinterpret_cast<__half2*>(&u.y);
    float2 f01 = __half22float2(lo), f23 = __half22float2(hi);
    return make_float4(f01.x, f01.y, f23.x, f23.y);
}

// ---- scratch (device globals: allocation-free contract) ----
__device__ int g_deg[N];
__device__ int g_offs[N + 1];
__device__ int g_cursor[N];
__device__ int g_perm[E];
__device__ int g_srcs[E];
__device__ int g_btot[SCAN_BLOCKS];
__device__ int g_boff[SCAN_BLOCKS];
__device__ __align__(16) __half g_A[(size_t)N * 128];    // [h@W1 | p@P1] fp16
__device__ __align__(16) __half g_B[(size_t)N * 128];    // [h@W2 | p@P2] fp16
__device__ __align__(16) __half g_ce[(size_t)E * 128];   // [e@W3+bh | e@P3+bp] fp16, ORIGINAL order
__device__ __align__(16) float g_aggh[(size_t)N * 256];  // [mean|max|min|std]
__device__ __align__(16) float g_aggp[(size_t)N * 256];
__device__ float g_amp[N];
__device__ float g_att[N];
__device__ float g_bnsum[64];
__device__ float g_bnsq[64];

// ---------------- init ----------------
__global__ void k_init() {
    int i = blockIdx.x * blockDim.x + threadIdx.x;
    if (i < N) g_deg[i] = 0;
    if (i < 64) { g_bnsum[i] = 0.f; g_bnsq[i] = 0.f; }
}

// ---------------- degree histogram ----------------
__global__ void k_hist(const int* __restrict__ dst) {
    int e = blockIdx.x * blockDim.x + threadIdx.x;
    if (e < E) atomicAdd(&g_deg[dst[e]], 1);
}

// ---------------- multi-block exclusive scan ----------------
__global__ void k_scan1() {
    __shared__ int ws[32];
    int t = threadIdx.x;
    int lane = t & 31, w = t >> 5;
    int base = blockIdx.x * 1024;
    int v = (base + t < N) ? g_deg[base + t] : 0;
    int x = v;
#pragma unroll
    for (int off = 1; off < 32; off <<= 1) {
        int y = __shfl_up_sync(0xffffffffu, x, off);
        if (lane >= off) x += y;
    }
    if (lane == 31) ws[w] = x;
    __syncthreads();
    if (w == 0) {
        int s = ws[lane];
#pragma unroll
        for (int off = 1; off < 32; off <<= 1) {
            int y = __shfl_up_sync(0xffffffffu, s, off);
            if (lane >= off) s += y;
        }
        ws[lane] = s;
    }
    __syncthreads();
    int incl = x + (w > 0 ? ws[w - 1] : 0);
    if (base + t < N) g_offs[base + t] = incl - v;
    if (t == 1023) g_btot[blockIdx.x] = incl;
}

__global__ void k_scan2() {
    if (threadIdx.x == 0) {
        int acc = 0;
        for (int i = 0; i < SCAN_BLOCKS; i++) {
            g_boff[i] = acc;
            acc += g_btot[i];
        }
    }
}

__global__ void k_scan3() {
    int t = threadIdx.x;
    int base = blockIdx.x * 1024;
    int off = g_boff[blockIdx.x];
    if (base + t < N) {
        int v = g_offs[base + t] + off;
        g_offs[base + t] = v;
        g_cursor[base + t] = v;
    }
    if (blockIdx.x == 0 && t == 0) g_offs[N] = E;
}

// ---------------- scatter: counting sort by dst ----------------
__global__ void k_scatter(const int* __restrict__ dst, const int* __restrict__ src) {
    int e = blockIdx.x * blockDim.x + threadIdx.x;
    if (e < E) {
        int pos = atomicAdd(&g_cursor[dst[e]], 1);
        g_perm[pos] = e;
        g_srcs[pos] = src[e];
    }
}

// ---------------- node pre-GEMMs -> fp16 g_A, g_B --------------
__global__ void __launch_bounds__(256) k_nodepre(
    const float* __restrict__ h, const float* __restrict__ p,
    const float* __restrict__ Wh, const float* __restrict__ Wp)
{
    __shared__ __align__(16) float Xs[32 * PITCH];
    __shared__ __align__(16) float Ws[32 * 128];

    int tid = threadIdx.x;
    int base = blockIdx.x * 128;

    int tx = tid & 15;
    int te = tid >> 4;
    int le = tid & 127;
    int lh = (tid >> 7) * 16;
    int wkk = tid >> 3;
    int woc = (tid & 7) * 16;

    int nl = base + le;
    bool okl = nl < N;

    ull acca[4][4], accb[4][4];

    // ===== h phase =====
#pragma unroll
    for (int i = 0; i < 4; i++)
#pragma unroll
        for (int j = 0; j < 4; j++) { acca[i][j] = 0ull; accb[i][j] = 0ull; }

    for (int t = 0; t < 4; t++) {
        int k0 = t * 32;
        const float* rowp = h + (size_t)nl * 128 + k0;
#pragma unroll
        for (int q = 0; q < 4; q++) {
            float4 a = okl ? *(const float4*)(rowp + lh + q * 4)
                           : make_float4(0.f, 0.f, 0.f, 0.f);
            Xs[(lh + q * 4 + 0) * PITCH + le] = a.x;
            Xs[(lh + q * 4 + 1) * PITCH + le] = a.y;
            Xs[(lh + q * 4 + 2) * PITCH + le] = a.z;
            Xs[(lh + q * 4 + 3) * PITCH + le] = a.w;
        }
        {
            const float* wr = (woc < 64) ? (Wh + (size_t)(k0 + wkk) * 64 + woc)
                                         : (Wh + (size_t)(128 + k0 + wkk) * 64 + (woc - 64));
#pragma unroll
            for (int q = 0; q < 4; q++)
                *(float4*)&Ws[wkk * 128 + woc + q * 4] = *(const float4*)(wr + q * 4);
        }
        __syncthreads();
#pragma unroll 16
        for (int kk = 0; kk < 32; kk++) {
            float4 wa = *(const float4*)&Ws[kk * 128 + tx * 4];
            float4 wb = *(const float4*)&Ws[kk * 128 + 64 + tx * 4];
            ull a0 = pack2(wa.x, wa.x), a1 = pack2(wa.y, wa.y);
            ull a2 = pack2(wa.z, wa.z), a3 = pack2(wa.w, wa.w);
            ull b0 = pack2(wb.x, wb.x), b1 = pack2(wb.y, wb.y);
            ull b2 = pack2(wb.z, wb.z), b3 = pack2(wb.w, wb.w);
            const ull* xp = (const ull*)&Xs[kk * PITCH + te * 8];
#pragma unroll
            for (int i = 0; i < 4; i++) {
                ull x = xp[i];
                acca[i][0] = fma2(x, a0, acca[i][0]);
                acca[i][1] = fma2(x, a1, acca[i][1]);
                acca[i][2] = fma2(x, a2, acca[i][2]);
                acca[i][3] = fma2(x, a3, acca[i][3]);
                accb[i][0] = fma2(x, b0, accb[i][0]);
                accb[i][1] = fma2(x, b1, accb[i][1]);
                accb[i][2] = fma2(x, b2, accb[i][2]);
                accb[i][3] = fma2(x, b3, accb[i][3]);
            }
        }
        __syncthreads();
    }
#pragma unroll
    for (int i = 0; i < 4; i++) {
        float2 a0 = unpack2(acca[i][0]), a1 = unpack2(acca[i][1]);
        float2 a2 = unpack2(acca[i][2]), a3 = unpack2(acca[i][3]);
        float2 b0 = unpack2(accb[i][0]), b1 = unpack2(accb[i][1]);
        float2 b2 = unpack2(accb[i][2]), b3 = unpack2(accb[i][3]);
        int n0 = base + te * 8 + 2 * i;
        if (n0 < N) {
            __half* Ar = g_A + (size_t)n0 * 128 + tx * 4;
            __half* Br = g_B + (size_t)n0 * 128 + tx * 4;
            *(__half2*)Ar = __floats2half2_rn(a0.x, a1.x);
            *(__half2*)(Ar + 2) = __floats2half2_rn(a2.x, a3.x);
            *(__half2*)Br = __floats2half2_rn(b0.x, b1.x);
            *(__half2*)(Br + 2) = __floats2half2_rn(b2.x, b3.x);
        }
        if (n0 + 1 < N) {
            __half* Ar = g_A + (size_t)(n0 + 1) * 128 + tx * 4;
            __half* Br = g_B + (size_t)(n0 + 1) * 128 + tx * 4;
            *(__half2*)Ar = __floats2half2_rn(a0.y, a1.y);
            *(__half2*)(Ar + 2) = __floats2half2_rn(a2.y, a3.y);
            *(__half2*)Br = __floats2half2_rn(b0.y, b1.y);
            *(__half2*)(Br + 2) = __floats2half2_rn(b2.y, b3.y);
        }
    }

    // ===== p phase =====
#pragma unroll
    for (int i = 0; i < 4; i++)
#pragma unroll
        for (int j = 0; j < 4; j++) { acca[i][j] = 0ull; accb[i][j] = 0ull; }

    for (int t = 0; t < 2; t++) {
        int k0 = t * 32;
        const float* rowp = p + (size_t)nl * 64 + k0;
#pragma unroll
        for (int q = 0; q < 4; q++) {
            float4 a = okl ? *(const float4*)(rowp + lh + q * 4)
                           : make_float4(0.f, 0.f, 0.f, 0.f);
            Xs[(lh + q * 4 + 0) * PITCH + le] = a.x;
            Xs[(lh + q * 4 + 1) * PITCH + le] = a.y;
            Xs[(lh + q * 4 + 2) * PITCH + le] = a.z;
            Xs[(lh + q * 4 + 3) * PITCH + le] = a.w;
        }
        {
            const float* wr = (woc < 64) ? (Wp + (size_t)(k0 + wkk) * 64 + woc)
                                         : (Wp + (size_t)(64 + k0 + wkk) * 64 + (woc - 64));
#pragma unroll
            for (int q = 0; q < 4; q++)
                *(float4*)&Ws[wkk * 128 + woc + q * 4] = *(const float4*)(wr + q * 4);
        }
        __syncthreads();
#pragma unroll 16
        for (int kk = 0; kk < 32; kk++) {
            float4 wa = *(const float4*)&Ws[kk * 128 + tx * 4];
            float4 wb = *(const float4*)&Ws[kk * 128 + 64 + tx * 4];
            ull a0 = pack2(wa.x, wa.x), a1 = pack2(wa.y, wa.y);
            ull a2 = pack2(wa.z, wa.z), a3 = pack2(wa.w, wa.w);
            ull b0 = pack2(wb.x, wb.x), b1 = pack2(wb.y, wb.y);
            ull b2 = pack2(wb.z, wb.z), b3 = pack2(wb.w, wb.w);
            const ull* xp = (const ull*)&Xs[kk * PITCH + te * 8];
#pragma unroll
            for (int i = 0; i < 4; i++) {
                ull x = xp[i];
                acca[i][0] = fma2(x, a0, acca[i][0]);
                acca[i][1] = fma2(x, a1, acca[i][1]);
                acca[i][2] = fma2(x, a2, acca[i][2]);
                acca[i][3] = fma2(x, a3, acca[i][3]);
                accb[i][0] = fma2(x, b0, accb[i][0]);
                accb[i][1] = fma2(x, b1, accb[i][1]);
                accb[i][2] = fma2(x, b2, accb[i][2]);
                accb[i][3] = fma2(x, b3, accb[i][3]);
            }
        }
        __syncthreads();
    }
#pragma unroll
    for (int i = 0; i < 4; i++) {
        float2 a0 = unpack2(acca[i][0]), a1 = unpack2(acca[i][1]);
        float2 a2 = unpack2(acca[i][2]), a3 = unpack2(acca[i][3]);
        float2 b0 = unpack2(accb[i][0]), b1 = unpack2(accb[i][1]);
        float2 b2 = unpack2(accb[i][2]), b3 = unpack2(accb[i][3]);
        int n0 = base + te * 8 + 2 * i;
        if (n0 < N) {
            __half* Ar = g_A + (size_t)n0 * 128 + 64 + tx * 4;
            __half* Br = g_B + (size_t)n0 * 128 + 64 + tx * 4;
            *(__half2*)Ar = __floats2half2_rn(a0.x, a1.x);
            *(__half2*)(Ar + 2) = __floats2half2_rn(a2.x, a3.x);
            *(__half2*)Br = __floats2half2_rn(b0.x, b1.x);
            *(__half2*)(Br + 2) = __floats2half2_rn(b2.x, b3.x);
        }
        if (n0 + 1 < N) {
            __half* Ar = g_A + (size_t)(n0 + 1) * 128 + 64 + tx * 4;
            __half* Br = g_B + (size_t)(n0 + 1) * 128 + 64 + tx * 4;
            *(__half2*)Ar = __floats2half2_rn(a0.y, a1.y);
            *(__half2*)(Ar + 2) = __floats2half2_rn(a2.y, a3.y);
            *(__half2*)Br = __floats2half2_rn(b0.y, b1.y);
            *(__half2*)(Br + 2) = __floats2half2_rn(b2.y, b3.y);
        }
    }
}

// ---------------- edge-feature GEMM -> fp16 messages, ORIGINAL edge order ------------
__global__ void __launch_bounds__(256) k_edgeE(
    const float* __restrict__ ef,
    const float* __restrict__ Wh, const float* __restrict__ bh,
    const float* __restrict__ Wp, const float* __restrict__ bp)
{
    __shared__ __align__(16) float Xs[32 * PITCH];
    __shared__ __align__(16) float Ws[32 * 128];

    int tid = threadIdx.x;
    int base = blockIdx.x * 128;

    int tx = tid & 15;
    int te = tid >> 4;
    int le = tid & 127;
    int lh = (tid >> 7) * 16;
    int wkk = tid >> 3;
    int woc = (tid & 7) * 16;

    {
        const float* wr = (woc < 64) ? (Wh + (size_t)(256 + wkk) * 64 + woc)
                                     : (Wp + (size_t)(128 + wkk) * 64 + (woc - 64));
#pragma unroll
        for (int q = 0; q < 4; q++)
            *(float4*)&Ws[wkk * 128 + woc + q * 4] = *(const float4*)(wr + q * 4);
    }
    __syncthreads();
    {
        const float* rowp = ef + (size_t)(base + le) * 32;
#pragma unroll
        for (int q = 0; q < 4; q++) {
            float4 a = *(const float4*)(rowp + lh + q * 4);
            Xs[(lh + q * 4 + 0) * PITCH + le] = a.x;
            Xs[(lh + q * 4 + 1) * PITCH + le] = a.y;
            Xs[(lh + q * 4 + 2) * PITCH + le] = a.z;
            Xs[(lh + q * 4 + 3) * PITCH + le] = a.w;
        }
    }
    __syncthreads();

    ull acca[4][4], accb[4][4];
#pragma unroll
    for (int i = 0; i < 4; i++)
#pragma unroll
        for (int j = 0; j < 4; j++) { acca[i][j] = 0ull; accb[i][j] = 0ull; }

#pragma unroll 16
    for (int kk = 0; kk < 32; kk++) {
        float4 wa = *(const float4*)&Ws[kk * 128 + tx * 4];
        float4 wb = *(const float4*)&Ws[kk * 128 + 64 + tx * 4];
        ull a0 = pack2(wa.x, wa.x), a1 = pack2(wa.y, wa.y);
        ull a2 = pack2(wa.z, wa.z), a3 = pack2(wa.w, wa.w);
        ull b0 = pack2(wb.x, wb.x), b1 = pack2(wb.y, wb.y);
        ull b2 = pack2(wb.z, wb.z), b3 = pack2(wb.w, wb.w);
        const ull* xp = (const ull*)&Xs[kk * PITCH + te * 8];
#pragma unroll
        for (int i = 0; i < 4; i++) {
            ull x = xp[i];
            acca[i][0] = fma2(x, a0, acca[i][0]);
            acca[i][1] = fma2(x, a1, acca[i][1]);
            acca[i][2] = fma2(x, a2, acca[i][2]);
            acca[i][3] = fma2(x, a3, acca[i][3]);
            accb[i][0] = fma2(x, b0, accb[i][0]);
            accb[i][1] = fma2(x, b1, accb[i][1]);
            accb[i][2] = fma2(x, b2, accb[i][2]);
            accb[i][3] = fma2(x, b3, accb[i][3]);
        }
    }

    float4 biash = *(const float4*)&bh[tx * 4];
    float4 biasp = *(const float4*)&bp[tx * 4];
#pragma unroll
    for (int i = 0; i < 4; i++) {
        float2 a0 = unpack2(acca[i][0]), a1 = unpack2(acca[i][1]);
        float2 a2 = unpack2(acca[i][2]), a3 = unpack2(acca[i][3]);
        float2 b0 = unpack2(accb[i][0]), b1 = unpack2(accb[i][1]);
        float2 b2 = unpack2(accb[i][2]), b3 = unpack2(accb[i][3]);
        int pos = base + te * 8 + 2 * i;
        __half* r0 = g_ce + (size_t)pos * 128;
        __half* r1 = g_ce + (size_t)(pos + 1) * 128;
        {
            __half2 lo = __floats2half2_rn(a0.x + biash.x, a1.x + biash.y);
            __half2 hi = __floats2half2_rn(a2.x + biash.z, a3.x + biash.w);
            *(__half2*)(r0 + tx * 4) = lo; *(__half2*)(r0 + tx * 4 + 2) = hi;
            lo = __floats2half2_rn(a0.y + biash.x, a1.y + biash.y);
            hi = __floats2half2_rn(a2.y + biash.z, a3.y + biash.w);
            *(__half2*)(r1 + tx * 4) = lo; *(__half2*)(r1 + tx * 4 + 2) = hi;
        }
        {
            __half2 lo = __floats2half2_rn(b0.x + biasp.x, b1.x + biasp.y);
            __half2 hi = __floats2half2_rn(b2.x + biasp.z, b3.x + biasp.w);
            *(__half2*)(r0 + 64 + tx * 4) = lo; *(__half2*)(r0 + 64 + tx * 4 + 2) = hi;
            lo = __floats2half2_rn(b0.y + biasp.x, b1.y + biasp.y);
            hi = __floats2half2_rn(b2.y + biasp.z, b3.y + biasp.w);
            *(__half2*)(r1 + 64 + tx * 4) = lo; *(__half2*)(r1 + 64 + tx * 4 + 2) = hi;
        }
    }
}

// ---------------- fused message + PNA aggregation ----------------
// Lane l owns 4 CONSECUTIVE features: halfs [4l, 4l+4) of the 128-half row.
// Lanes 0-15 cover the h side, lanes 16-31 the p side.
// Per edge: 2 x 8B loads per lane (ce row + A row) — half the LDG count of the
// previous paired-feature layout.
__global__ void k_agg() {
    int warp = (blockIdx.x * blockDim.x + threadIdx.x) >> 5;
    int l = threadIdx.x & 31;
    if (warp >= N) return;
    int n = warp;
    int s0 = g_offs[n];
    int s1 = g_offs[n + 1];
    int d = s1 - s0;

    int off4 = 4 * l;   // half offset of this lane's 4 features
    float4 bv = ldh4(g_B + (size_t)n * 128 + off4);

    float4 sm = make_float4(0.f, 0.f, 0.f, 0.f);
    float4 sq = make_float4(0.f, 0.f, 0.f, 0.f);
    float4 mx = make_float4(-FLT_BIG, -FLT_BIG, -FLT_BIG, -FLT_BIG);
    float4 mn = make_float4(FLT_BIG, FLT_BIG, FLT_BIG, FLT_BIG);

#define AGG_ACC(CV, AV)                                                          \
    do {                                                                         \
        float v0 = (CV).x + (AV).x + bv.x;                                       \
        float v1 = (CV).y + (AV).y + bv.y;                                       \
        float v2 = (CV).z + (AV).z + bv.z;                                       \
        float v3 = (CV).w + (AV).w + bv.w;                                       \
        sm.x += v0; sq.x += v0 * v0; mx.x = fmaxf(mx.x, v0); mn.x = fminf(mn.x, v0); \
        sm.y += v1; sq.y += v1 * v1; mx.y = fmaxf(mx.y, v1); mn.y = fminf(mn.y, v1); \
        sm.z += v2; sq.z += v2 * v2; mx.z = fmaxf(mx.z, v2); mn.z = fminf(mn.z, v2); \
        sm.w += v3; sq.w += v3 * v3; mx.w = fmaxf(mx.w, v3); mn.w = fminf(mn.w, v3); \
    } while (0)

    int i = s0;
    if ((s1 - s0) & 1) {
        int s = g_srcs[i];
        int eid = g_perm[i];
        float4 cv = ldh4(g_ce + (size_t)eid * 128 + off4);
        float4 av = ldh4(g_A + (size_t)s * 128 + off4);
        AGG_ACC(cv, av);
        i++;
    }
    for (; i < s1; i += 2) {
        int sA = g_srcs[i],   sB = g_srcs[i + 1];
        int eA = g_perm[i],   eB = g_perm[i + 1];
        // issue all 4 loads before consuming
        uint2 uCA = *(const uint2*)(g_ce + (size_t)eA * 128 + off4);
        uint2 uAA = *(const uint2*)(g_A + (size_t)sA * 128 + off4);
        uint2 uCB = *(const uint2*)(g_ce + (size_t)eB * 128 + off4);
        uint2 uAB = *(const uint2*)(g_A + (size_t)sB * 128 + off4);
        {
            __half2 lo = *reinterpret_cast<__half2*>(&uCA.x);
            __half2 hi = *reinterpret_cast<__half2*>(&uCA.y);
            float2 c01 = __half22float2(lo), c23 = __half22float2(hi);
            lo = *reinterpret_cast<__half2*>(&uAA.x);
            hi = *reinterpret_cast<__half2*>(&uAA.y);
            float2 a01 = __half22float2(lo), a23 = __half22float2(hi);
            float4 cv = make_float4(c01.x, c01.y, c23.x, c23.y);
            float4 av = make_float4(a01.x, a01.y, a23.x, a23.y);
            AGG_ACC(cv, av);
        }
        {
            __half2 lo = *reinterpret_cast<__half2*>(&uCB.x);
            __half2 hi = *reinterpret_cast<__half2*>(&uCB.y);
            float2 c01 = __half22float2(lo), c23 = __half22float2(hi);
            lo = *reinterpret_cast<__half2*>(&uAB.x);
            hi = *reinterpret_cast<__half2*>(&uAB.y);
            float2 a01 = __half22float2(lo), a23 = __half22float2(hi);
            float4 cv = make_float4(c01.x, c01.y, c23.x, c23.y);
            float4 av = make_float4(a01.x, a01.y, a23.x, a23.y);
            AGG_ACC(cv, av);
        }
    }
#undef AGG_ACC

    float degc = fmaxf((float)d, 1.f);
    float inv = 1.f / degc;
    bool has = d > 0;
    float logd = has ? logf((float)d + 1.f) : 1.f;
    float amp = logd / AVG_D_LOG;
    float att = AVG_D_LOG / logd;
    if (l == 0) { g_amp[n] = amp; g_att[n] = att; }

    // output: lane's 4 features live on one side
    float* o = (off4 < 64) ? (g_aggh + (size_t)n * 256) : (g_aggp + (size_t)n * 256);
    int f = off4 & 63;

    float4 mean = make_float4(sm.x * inv, sm.y * inv, sm.z * inv, sm.w * inv);
    float4 var = make_float4(fmaxf(sq.x * inv - mean.x * mean.x, 0.f),
                             fmaxf(sq.y * inv - mean.y * mean.y, 0.f),
                             fmaxf(sq.z * inv - mean.z * mean.z, 0.f),
                             fmaxf(sq.w * inv - mean.w * mean.w, 0.f));
    float4 sd = make_float4(sqrtf(var.x + EPS_STD), sqrtf(var.y + EPS_STD),
                            sqrtf(var.z + EPS_STD), sqrtf(var.w + EPS_STD));
    float4 MX = has ? mx : make_float4(0.f, 0.f, 0.f, 0.f);
    float4 MN = has ? mn : make_float4(0.f, 0.f, 0.f, 0.f);
    *(float4*)(o + f) = mean;
    *(float4*)(o + 64 + f) = MX;
    *(float4*)(o + 128 + f) = MN;
    *(float4*)(o + 192 + f) = sd;
}

// ---------------- node GEMMs: 3 rails + FUSED BN stats (reuses Xs smem) ----------
__global__ void __launch_bounds__(256) k_nodegemm(
    const float* __restrict__ h, const float* __restrict__ p,
    const float* __restrict__ snorm,
    const float* __restrict__ Woh, const float* __restrict__ boh,
    const float* __restrict__ Wop, const float* __restrict__ bop,
    float* __restrict__ out)
{
    __shared__ __align__(16) float Xs[32 * 64];
    __shared__ __align__(16) float Ws[3 * 32 * 64];

    int tid = threadIdx.x;
    int base = blockIdx.x * 64;

    int tx = tid & 31;
    int te = tid >> 5;
    int le = tid & 63;
    int lh = (tid >> 6) * 8;
    int wkk = tid >> 3;
    int woc = (tid & 7) * 8;

    int nl = base + le;
    bool okl = nl < N;

    ull accI[4][2], accA[4][2], accT[4][2];

    // =================== phase H =========
#pragma unroll
    for (int i = 0; i < 4; i++)
#pragma unroll
        for (int j = 0; j < 2; j++) { accI[i][j] = 0ull; accA[i][j] = 0ull; accT[i][j] = 0ull; }

    for (int t = 0; t < 12; t++) {
        int k0 = t * 32;
        bool isAgg = (t >= 4);
        const float* rowp = isAgg ? (g_aggh + (size_t)nl * 256 + (k0 - 128))
                                  : (h + (size_t)nl * 128 + k0);
#pragma unroll
        for (int q = 0; q < 2; q++) {
            float4 a = okl ? *(const float4*)(rowp + lh + q * 4)
                           : make_float4(0.f, 0.f, 0.f, 0.f);
            Xs[(lh + q * 4 + 0) * 64 + le] = a.x;
            Xs[(lh + q * 4 + 1) * 64 + le] = a.y;
            Xs[(lh + q * 4 + 2) * 64 + le] = a.z;
            Xs[(lh + q * 4 + 3) * 64 + le] = a.w;
        }
        if (isAgg) {
            int aggk = k0 - 128;
            const float* wI = Woh + (size_t)(128 + aggk + wkk) * 64 + woc;
            const float* wA = Woh + (size_t)(384 + aggk + wkk) * 64 + woc;
            const float* wT = Woh + (size_t)(640 + aggk + wkk) * 64 + woc;
            *(float4*)&Ws[wkk * 64 + woc]              = *(const float4*)(wI);
            *(float4*)&Ws[wkk * 64 + woc + 4]          = *(const float4*)(wI + 4);
            *(float4*)&Ws[2048 + wkk * 64 + woc]       = *(const float4*)(wA);
            *(float4*)&Ws[2048 + wkk * 64 + woc + 4]   = *(const float4*)(wA + 4);
            *(float4*)&Ws[4096 + wkk * 64 + woc]       = *(const float4*)(wT);
            *(float4*)&Ws[4096 + wkk * 64 + woc + 4]   = *(const float4*)(wT + 4);
        } else {
            const float* wI = Woh + (size_t)(k0 + wkk) * 64 + woc;
            *(float4*)&Ws[wkk * 64 + woc]     = *(const float4*)(wI);
            *(float4*)&Ws[wkk * 64 + woc + 4] = *(const float4*)(wI + 4);
        }
        __syncthreads();
        if (isAgg) {
#pragma unroll 8
            for (int kk = 0; kk < 32; kk++) {
                float2 wi = *(const float2*)&Ws[kk * 64 + tx * 2];
                float2 wa = *(const float2*)&Ws[2048 + kk * 64 + tx * 2];
                float2 wt = *(const float2*)&Ws[4096 + kk * 64 + tx * 2];
                ull i0 = pack2(wi.x, wi.x), i1 = pack2(wi.y, wi.y);
                ull a0 = pack2(wa.x, wa.x), a1 = pack2(wa.y, wa.y);
                ull t0 = pack2(wt.x, wt.x), t1 = pack2(wt.y, wt.y);
                const ull* xp = (const ull*)&Xs[kk * 64 + te * 8];
#pragma unroll
                for (int i = 0; i < 4; i++) {
                    ull x = xp[i];
                    accI[i][0] = fma2(x, i0, accI[i][0]);
                    accI[i][1] = fma2(x, i1, accI[i][1]);
                    accA[i][0] = fma2(x, a0, accA[i][0]);
                    accA[i][1] = fma2(x, a1, accA[i][1]);
                    accT[i][0] = fma2(x, t0, accT[i][0]);
                    accT[i][1] = fma2(x, t1, accT[i][1]);
                }
            }
        } else {
#pragma unroll 8
            for (int kk = 0; kk < 32; kk++) {
                float2 wi = *(const float2*)&Ws[kk * 64 + tx * 2];
                ull i0 = pack2(wi.x, wi.x), i1 = pack2(wi.y, wi.y);
                const ull* xp = (const ull*)&Xs[kk * 64 + te * 8];
#pragma unroll
                for (int i = 0; i < 4; i++) {
                    ull x = xp[i];
                    accI[i][0] = fma2(x, i0, accI[i][0]);
                    accI[i][1] = fma2(x, i1, accI[i][1]);
                }
            }
        }
        __syncthreads();
    }
    {
        float2 bias = *(const float2*)&boh[tx * 2];
        float s0 = 0.f, q0 = 0.f, s1 = 0.f, q1 = 0.f;
#pragma unroll
        for (int i = 0; i < 4; i++) {
            int n0 = base + te * 8 + 2 * i;
            float am0 = (n0 < N) ? g_amp[n0] : 0.f;
            float am1 = (n0 + 1 < N) ? g_amp[n0 + 1] : 0.f;
            float at0 = (n0 < N) ? g_att[n0] : 0.f;
            float at1 = (n0 + 1 < N) ? g_att[n0 + 1] : 0.f;
            ull ampP = pack2(am0, am1), attP = pack2(at0, at1);
            ull y0 = fma2(attP, accT[i][0], fma2(ampP, accA[i][0], accI[i][0]));
            ull y1 = fma2(attP, accT[i][1], fma2(ampP, accA[i][1], accI[i][1]));
            float2 u0 = unpack2(y0), u1 = unpack2(y1);
            if (n0 < N) {
                float sn = snorm[n0];
                float o0 = (u0.x + bias.x) * sn, o1 = (u1.x + bias.y) * sn;
                *(float2*)&out[(size_t)n0 * 64 + tx * 2] = make_float2(o0, o1);
                s0 += o0; q0 += o0 * o0; s1 += o1; q1 += o1 * o1;
            }
            if (n0 + 1 < N) {
                float sn = snorm[n0 + 1];
                float o0 = (u0.y + bias.x) * sn, o1 = (u1.y + bias.y) * sn;
                *(float2*)&out[(size_t)(n0 + 1) * 64 + tx * 2] = make_float2(o0, o1);
                s0 += o0; q0 += o0 * o0; s1 += o1; q1 += o1 * o1;
            }
        }
        __syncthreads();
        Xs[te * 64 + 2 * tx]       = s0;
        Xs[te * 64 + 2 * tx + 1]   = s1;
        Xs[512 + te * 64 + 2 * tx]     = q0;
        Xs[512 + te * 64 + 2 * tx + 1] = q1;
        __syncthreads();
        if (tid < 64) {
            float S = 0.f, Q = 0.f;
#pragma unroll
            for (int r = 0; r < 8; r++) { S += Xs[r * 64 + tid]; Q += Xs[512 + r * 64 + tid]; }
            atomicAdd(&g_bnsum[tid], S);
            atomicAdd(&g_bnsq[tid], Q);
        }
        __syncthreads();
    }

    // =================== phase P ==========
#pragma unroll
    for (int i = 0; i < 4; i++)
#pragma unroll
        for (int j = 0; j < 2; j++) { accI[i][j] = 0ull; accA[i][j] = 0ull; accT[i][j] = 0ull; }

    for (int t = 0; t < 10; t++) {
        int k0 = t * 32;
        bool isAgg = (t >= 2);
        const float* rowp = isAgg ? (g_aggp + (size_t)nl * 256 + (k0 - 64))
                                  : (p + (size_t)nl * 64 + k0);
#pragma unroll
        for (int q = 0; q < 2; q++) {
            float4 a = okl ? *(const float4*)(rowp + lh + q * 4)
                           : make_float4(0.f, 0.f, 0.f, 0.f);
            Xs[(lh + q * 4 + 0) * 64 + le] = a.x;
            Xs[(lh + q * 4 + 1) * 64 + le] = a.y;
            Xs[(lh + q * 4 + 2) * 64 + le] = a.z;
            Xs[(lh + q * 4 + 3) * 64 + le] = a.w;
        }
        if (isAgg) {
            int aggk = k0 - 64;
            const float* wI = Wop + (size_t)(64 + aggk + wkk) * 64 + woc;
            const float* wA = Wop + (size_t)(320 + aggk + wkk) * 64 + woc;
            const float* wT = Wop + (size_t)(576 + aggk + wkk) * 64 + woc;
            *(float4*)&Ws[wkk * 64 + woc]              = *(const float4*)(wI);
            *(float4*)&Ws[wkk * 64 + woc + 4]          = *(const float4*)(wI + 4);
            *(float4*)&Ws[2048 + wkk * 64 + woc]       = *(const float4*)(wA);
            *(float4*)&Ws[2048 + wkk * 64 + woc + 4]   = *(const float4*)(wA + 4);
            *(float4*)&Ws[4096 + wkk * 64 + woc]       = *(const float4*)(wT);
            *(float4*)&Ws[4096 + wkk * 64 + woc + 4]   = *(const float4*)(wT + 4);
        } else {
            const float* wI = Wop + (size_t)(k0 + wkk) * 64 + woc;
            *(float4*)&Ws[wkk * 64 + woc]     = *(const float4*)(wI);
            *(float4*)&Ws[wkk * 64 + woc + 4] = *(const float4*)(wI + 4);
        }
        __syncthreads();
        if (isAgg) {
#pragma unroll 8
            for (int kk = 0; kk < 32; kk++) {
                float2 wi = *(const float2*)&Ws[kk * 64 + tx * 2];
                float2 wa = *(const float2*)&Ws[2048 + kk * 64 + tx * 2];
                float2 wt = *(const float2*)&Ws[4096 + kk * 64 + tx * 2];
                ull i0 = pack2(wi.x, wi.x), i1 = pack2(wi.y, wi.y);
                ull a0 = pack2(wa.x, wa.x), a1 = pack2(wa.y, wa.y);
                ull t0 = pack2(wt.x, wt.x), t1 = pack2(wt.y, wt.y);
                const ull* xp = (const ull*)&Xs[kk * 64 + te * 8];
#pragma unroll
                for (int i = 0; i < 4; i++) {
                    ull x = xp[i];
                    accI[i][0] = fma2(x, i0, accI[i][0]);
                    accI[i][1] = fma2(x, i1, accI[i][1]);
                    accA[i][0] = fma2(x, a0, accA[i][0]);
                    accA[i][1] = fma2(x, a1, accA[i][1]);
                    accT[i][0] = fma2(x, t0, accT[i][0]);
                    accT[i][1] = fma2(x, t1, accT[i][1]);
                }
            }
        } else {
#pragma unroll 8
            for (int kk = 0; kk < 32; kk++) {
                float2 wi = *(const float2*)&Ws[kk * 64 + tx * 2];
                ull i0 = pack2(wi.x, wi.x), i1 = pack2(wi.y, wi.y);
                const ull* xp = (const ull*)&Xs[kk * 64 + te * 8];
#pragma unroll
                for (int i = 0; i < 4; i++) {
                    ull x = xp[i];
                    accI[i][0] = fma2(x, i0, accI[i][0]);
                    accI[i][1] = fma2(x, i1, accI[i][1]);
                }
            }
        }
        __syncthreads();
    }
    {
        float2 bias = *(const float2*)&bop[tx * 2];
        float* outp = out + (size_t)N * 64;
#pragma unroll
        for (int i = 0; i < 4; i++) {
            int n0 = base + te * 8 + 2 * i;
            float am0 = (n0 < N) ? g_amp[n0] : 0.f;
            float am1 = (n0 + 1 < N) ? g_amp[n0 + 1] : 0.f;
            float at0 = (n0 < N) ? g_att[n0] : 0.f;
            float at1 = (n0 + 1 < N) ? g_att[n0 + 1] : 0.f;
            ull ampP = pack2(am0, am1), attP = pack2(at0, at1);
            ull y0 = fma2(attP, accT[i][0], fma2(ampP, accA[i][0], accI[i][0]));
            ull y1 = fma2(attP, accT[i][1], fma2(ampP, accA[i][1], accI[i][1]));
            float2 u0 = unpack2(y0), u1 = unpack2(y1);
            if (n0 < N)
                *(float2*)&outp[(size_t)n0 * 64 + tx * 2] =
                    make_float2(u0.x + bias.x, u1.x + bias.y);
            if (n0 + 1 < N)
                *(float2*)&outp[(size_t)(n0 + 1) * 64 + tx * 2] =
                    make_float2(u0.y + bias.x, u1.y + bias.y);
        }
    }
}

// ---------------- batchnorm apply (float4 vectorized) ----------------
__global__ void k_bnapply(float* __restrict__ out,
                          const float* __restrict__ gamma,
                          const float* __restrict__ beta) {
    int i = blockIdx.x * blockDim.x + threadIdx.x;   // one float4 per thread
    if (i >= N * 16) return;
    int f = (i & 15) * 4;
    const float invN = 1.f / (float)N;
    float4 su = *(const float4*)&g_bnsum[f];
    float4 qu = *(const float4*)&g_bnsq[f];
    float4 ga = *(const float4*)&gamma[f];
    float4 be = *(const float4*)&beta[f];
    float4 mu = make_float4(su.x * invN, su.y * invN, su.z * invN, su.w * invN);
    float4 rs = make_float4(
        rsqrtf(qu.x * invN - mu.x * mu.x + EPS_BN),
        rsqrtf(qu.y * invN - mu.y * mu.y + EPS_BN),
        rsqrtf(qu.z * invN - mu.z * mu.z + EPS_BN),
        rsqrtf(qu.w * invN - mu.w * mu.w + EPS_BN));
    float4 x = *(float4*)&out[(size_t)i * 4];
    x.x = (x.x - mu.x) * rs.x * ga.x + be.x;
    x.y = (x.y - mu.y) * rs.y * ga.y + be.y;
    x.z = (x.z - mu.z) * rs.z * ga.z + be.z;
    x.w = (x.w - mu.w) * rs.w * ga.w + be.w;
    *(float4*)&out[(size_t)i * 4] = x;
}

} // namespace

extern "C" void kernel_launch(void* const* d_in, const int* in_sizes, int n_in,
                              void* d_out, int out_size) {
    const float* h     = (const float*)d_in[0];
    const float* p     = (const float*)d_in[1];
    const float* e     = (const float*)d_in[2];
    const int*   src   = (const int*)d_in[3];
    const int*   dst   = (const int*)d_in[4];
    const float* snorm = (const float*)d_in[5];
    const float* Wph   = (const float*)d_in[6];
    const float* bph   = (const float*)d_in[7];
    const float* Wpp   = (const float*)d_in[8];
    const float* bpp   = (const float*)d_in[9];
    const float* Woh   = (const float*)d_in[10];
    const float* boh   = (const float*)d_in[11];
    const float* Wop   = (const float*)d_in[12];
    const float* bop   = (const float*)d_in[13];
    const float* gamma = (const float*)d_in[14];
    const float* beta  = (const float*)d_in[15];
    float* out = (float*)d_out;

    static cudaStream_t s_pre = nullptr, s_edge = nullptr;
    static cudaEvent_t ev_fork = nullptr, ev_pre = nullptr, ev_edge = nullptr;
    if (s_pre == nullptr) {
        cudaStreamCreateWithFlags(&s_pre, cudaStreamNonBlocking);
        cudaStreamCreateWithFlags(&s_edge, cudaStreamNonBlocking);
        cudaEventCreateWithFlags(&ev_fork, cudaEventDisableTiming);
        cudaEventCreateWithFlags(&ev_pre, cudaEventDisableTiming);
        cudaEventCreateWithFlags(&ev_edge, cudaEventDisableTiming);
    }

    cudaEventRecord(ev_fork, 0);
    cudaStreamWaitEvent(s_pre, ev_fork, 0);
    cudaStreamWaitEvent(s_edge, ev_fork, 0);

    // side stream 1: node pre-GEMMs (independent)
    k_nodepre<<<(N + 127) / 128, 256, 0, s_pre>>>(h, p, Wph, Wpp);
    cudaEventRecord(ev_pre, s_pre);

    // side stream 2: edge-feature GEMM in ORIGINAL edge order (independent)
    k_edgeE<<<E / 128, 256, 0, s_edge>>>(e, Wph, bph, Wpp, bpp);
    cudaEventRecord(ev_edge, s_edge);

    // main stream: CSR construction
    k_init<<<(N + 255) / 256, 256>>>();
    k_hist<<<(E + 255) / 256, 256>>>(dst);
    k_scan1<<<SCAN_BLOCKS, 1024>>>();
    k_scan2<<<1, 32>>>();
    k_scan3<<<SCAN_BLOCKS, 1024>>>();
    k_scatter<<<(E + 255) / 256, 256>>>(dst, src);

    // join: agg needs g_A/g_B (pre), g_ce (edge), g_perm/g_srcs/g_offs (main)
    cudaStreamWaitEvent(0, ev_pre, 0);
    cudaStreamWaitEvent(0, ev_edge, 0);
    k_agg<<<(N * 32 + 255) / 256, 256>>>();
    k_nodegemm<<<(N + 63) / 64, 256>>>(h, p, snorm, Woh, boh, Wop, bop, out);
    k_bnapply<<<(N * 16 + 255) / 256, 256>>>(out, gamma, beta);
}

// round 11
// speedup vs baseline: 1.5015x; 1.0666x over previous
#include <cuda_runtime.h>
#include <cuda_fp16.h>
#include <math.h>

namespace {

constexpr int N = 50000;
constexpr int E = 800000;
constexpr float AVG_D_LOG = 2.8332f;
constexpr float EPS_STD = 1e-5f;
constexpr float EPS_BN = 1e-5f;
constexpr float FLT_BIG = 3.402823466e+38f;
constexpr int PITCH = 130;
constexpr int SCAN_BLOCKS = (N + 1023) / 1024;   // 49

typedef unsigned long long ull;

__device__ __forceinline__ ull fma2(ull a, ull b, ull c) {
    ull d;
    asm("fma.rn.f32x2 %0,%1,%2,%3;" : "=l"(d) : "l"(a), "l"(b), "l"(c));
    return d;
}
__device__ __forceinline__ ull pack2(float x, float y) {
    ull d;
    asm("mov.b64 %0,{%1,%2};" : "=l"(d) : "f"(x), "f"(y));
    return d;
}
__device__ __forceinline__ float2 unpack2(ull v) {
    float2 r;
    asm("mov.b64 {%0,%1},%2;" : "=f"(r.x), "=f"(r.y) : "l"(v));
    return r;
}
__device__ __forceinline__ float4 ldh4(const __half* ptr) {
    uint2 u = *(const uint2*)ptr;
    __half2 lo = *reinterpret_cast<__half2*>(&u.x);
    __half2 hi = *reinterpret_cast<__half2*>(&u.y);
    float2 f01 = __half22float2(lo), f23 = __half22float2(hi);
    return make_float4(f01.x, f01.y, f23.x, f23.y);
}
__device__ __forceinline__ uint4 ldsm_x4(unsigned addr) {
    uint4 r;
    asm volatile("ldmatrix.sync.aligned.m8n8.x4.shared.b16 {%0,%1,%2,%3}, [%4];"
                 : "=r"(r.x), "=r"(r.y), "=r"(r.z), "=r"(r.w) : "r"(addr));
    return r;
}
__device__ __forceinline__ uint4 ldsm_x4_t(unsigned addr) {
    uint4 r;
    asm volatile("ldmatrix.sync.aligned.m8n8.x4.trans.shared.b16 {%0,%1,%2,%3}, [%4];"
                 : "=r"(r.x), "=r"(r.y), "=r"(r.z), "=r"(r.w) : "r"(addr));
    return r;
}
__device__ __forceinline__ void mma16816(float* d, uint4 a, unsigned b0, unsigned b1) {
    asm volatile(
        "mma.sync.aligned.m16n8k16.row.col.f32.f16.f16.f32 "
        "{%0,%1,%2,%3},{%4,%5,%6,%7},{%8,%9},{%0,%1,%2,%3};"
        : "+f"(d[0]), "+f"(d[1]), "+f"(d[2]), "+f"(d[3])
        : "r"(a.x), "r"(a.y), "r"(a.z), "r"(a.w), "r"(b0), "r"(b1));
}

// ---- scratch (device globals: allocation-free contract) ----
__device__ int g_deg[N];
__device__ int g_offs[N + 1];
__device__ int g_cursor[N];
__device__ int g_perm[E];
__device__ int g_srcs[E];
__device__ int g_btot[SCAN_BLOCKS];
__device__ int g_boff[SCAN_BLOCKS];
__device__ __align__(16) __half g_A[(size_t)N * 128];
__device__ __align__(16) __half g_B[(size_t)N * 128];
__device__ __align__(16) __half g_ce[(size_t)E * 128];   // ORIGINAL edge order
__device__ __align__(16) float g_aggh[(size_t)N * 256];
__device__ __align__(16) float g_aggp[(size_t)N * 256];
__device__ float g_amp[N];
__device__ float g_att[N];
__device__ float g_bnsum[64];
__device__ float g_bnsq[64];

// ---------------- init ----------------
__global__ void k_init() {
    int i = blockIdx.x * blockDim.x + threadIdx.x;
    if (i < N) g_deg[i] = 0;
    if (i < 64) { g_bnsum[i] = 0.f; g_bnsq[i] = 0.f; }
}

// ---------------- degree histogram ----------------
__global__ void k_hist(const int* __restrict__ dst) {
    int e = blockIdx.x * blockDim.x + threadIdx.x;
    if (e < E) atomicAdd(&g_deg[dst[e]], 1);
}

// ---------------- multi-block exclusive scan ----------------
__global__ void k_scan1() {
    __shared__ int ws[32];
    int t = threadIdx.x;
    int lane = t & 31, w = t >> 5;
    int base = blockIdx.x * 1024;
    int v = (base + t < N) ? g_deg[base + t] : 0;
    int x = v;
#pragma unroll
    for (int off = 1; off < 32; off <<= 1) {
        int y = __shfl_up_sync(0xffffffffu, x, off);
        if (lane >= off) x += y;
    }
    if (lane == 31) ws[w] = x;
    __syncthreads();
    if (w == 0) {
        int s = ws[lane];
#pragma unroll
        for (int off = 1; off < 32; off <<= 1) {
            int y = __shfl_up_sync(0xffffffffu, s, off);
            if (lane >= off) s += y;
        }
        ws[lane] = s;
    }
    __syncthreads();
    int incl = x + (w > 0 ? ws[w - 1] : 0);
    if (base + t < N) g_offs[base + t] = incl - v;
    if (t == 1023) g_btot[blockIdx.x] = incl;
}

__global__ void k_scan2() {
    if (threadIdx.x == 0) {
        int acc = 0;
        for (int i = 0; i < SCAN_BLOCKS; i++) {
            g_boff[i] = acc;
            acc += g_btot[i];
        }
    }
}

__global__ void k_scan3() {
    int t = threadIdx.x;
    int base = blockIdx.x * 1024;
    int off = g_boff[blockIdx.x];
    if (base + t < N) {
        int v = g_offs[base + t] + off;
        g_offs[base + t] = v;
        g_cursor[base + t] = v;
    }
    if (blockIdx.x == 0 && t == 0) g_offs[N] = E;
}

// ---------------- scatter: counting sort by dst ----------------
__global__ void k_scatter(const int* __restrict__ dst, const int* __restrict__ src) {
    int e = blockIdx.x * blockDim.x + threadIdx.x;
    if (e < E) {
        int pos = atomicAdd(&g_cursor[dst[e]], 1);
        g_perm[pos] = e;
        g_srcs[pos] = src[e];
    }
}

// ---------------- node pre-GEMMs -> fp16 g_A, g_B --------------
__global__ void __launch_bounds__(256) k_nodepre(
    const float* __restrict__ h, const float* __restrict__ p,
    const float* __restrict__ Wh, const float* __restrict__ Wp)
{
    __shared__ __align__(16) float Xs[32 * PITCH];
    __shared__ __align__(16) float Ws[32 * 128];

    int tid = threadIdx.x;
    int base = blockIdx.x * 128;

    int tx = tid & 15;
    int te = tid >> 4;
    int le = tid & 127;
    int lh = (tid >> 7) * 16;
    int wkk = tid >> 3;
    int woc = (tid & 7) * 16;

    int nl = base + le;
    bool okl = nl < N;

    ull acca[4][4], accb[4][4];

    // ===== h phase =====
#pragma unroll
    for (int i = 0; i < 4; i++)
#pragma unroll
        for (int j = 0; j < 4; j++) { acca[i][j] = 0ull; accb[i][j] = 0ull; }

    for (int t = 0; t < 4; t++) {
        int k0 = t * 32;
        const float* rowp = h + (size_t)nl * 128 + k0;
#pragma unroll
        for (int q = 0; q < 4; q++) {
            float4 a = okl ? *(const float4*)(rowp + lh + q * 4)
                           : make_float4(0.f, 0.f, 0.f, 0.f);
            Xs[(lh + q * 4 + 0) * PITCH + le] = a.x;
            Xs[(lh + q * 4 + 1) * PITCH + le] = a.y;
            Xs[(lh + q * 4 + 2) * PITCH + le] = a.z;
            Xs[(lh + q * 4 + 3) * PITCH + le] = a.w;
        }
        {
            const float* wr = (woc < 64) ? (Wh + (size_t)(k0 + wkk) * 64 + woc)
                                         : (Wh + (size_t)(128 + k0 + wkk) * 64 + (woc - 64));
#pragma unroll
            for (int q = 0; q < 4; q++)
                *(float4*)&Ws[wkk * 128 + woc + q * 4] = *(const float4*)(wr + q * 4);
        }
        __syncthreads();
#pragma unroll 16
        for (int kk = 0; kk < 32; kk++) {
            float4 wa = *(const float4*)&Ws[kk * 128 + tx * 4];
            float4 wb = *(const float4*)&Ws[kk * 128 + 64 + tx * 4];
            ull a0 = pack2(wa.x, wa.x), a1 = pack2(wa.y, wa.y);
            ull a2 = pack2(wa.z, wa.z), a3 = pack2(wa.w, wa.w);
            ull b0 = pack2(wb.x, wb.x), b1 = pack2(wb.y, wb.y);
            ull b2 = pack2(wb.z, wb.z), b3 = pack2(wb.w, wb.w);
            const ull* xp = (const ull*)&Xs[kk * PITCH + te * 8];
#pragma unroll
            for (int i = 0; i < 4; i++) {
                ull x = xp[i];
                acca[i][0] = fma2(x, a0, acca[i][0]);
                acca[i][1] = fma2(x, a1, acca[i][1]);
                acca[i][2] = fma2(x, a2, acca[i][2]);
                acca[i][3] = fma2(x, a3, acca[i][3]);
                accb[i][0] = fma2(x, b0, accb[i][0]);
                accb[i][1] = fma2(x, b1, accb[i][1]);
                accb[i][2] = fma2(x, b2, accb[i][2]);
                accb[i][3] = fma2(x, b3, accb[i][3]);
            }
        }
        __syncthreads();
    }
#pragma unroll
    for (int i = 0; i < 4; i++) {
        float2 a0 = unpack2(acca[i][0]), a1 = unpack2(acca[i][1]);
        float2 a2 = unpack2(acca[i][2]), a3 = unpack2(acca[i][3]);
        float2 b0 = unpack2(accb[i][0]), b1 = unpack2(accb[i][1]);
        float2 b2 = unpack2(accb[i][2]), b3 = unpack2(accb[i][3]);
        int n0 = base + te * 8 + 2 * i;
        if (n0 < N) {
            __half* Ar = g_A + (size_t)n0 * 128 + tx * 4;
            __half* Br = g_B + (size_t)n0 * 128 + tx * 4;
            *(__half2*)Ar = __floats2half2_rn(a0.x, a1.x);
            *(__half2*)(Ar + 2) = __floats2half2_rn(a2.x, a3.x);
            *(__half2*)Br = __floats2half2_rn(b0.x, b1.x);
            *(__half2*)(Br + 2) = __floats2half2_rn(b2.x, b3.x);
        }
        if (n0 + 1 < N) {
            __half* Ar = g_A + (size_t)(n0 + 1) * 128 + tx * 4;
            __half* Br = g_B + (size_t)(n0 + 1) * 128 + tx * 4;
            *(__half2*)Ar = __floats2half2_rn(a0.y, a1.y);
            *(__half2*)(Ar + 2) = __floats2half2_rn(a2.y, a3.y);
            *(__half2*)Br = __floats2half2_rn(b0.y, b1.y);
            *(__half2*)(Br + 2) = __floats2half2_rn(b2.y, b3.y);
        }
    }

    // ===== p phase =====
#pragma unroll
    for (int i = 0; i < 4; i++)
#pragma unroll
        for (int j = 0; j < 4; j++) { acca[i][j] = 0ull; accb[i][j] = 0ull; }

    for (int t = 0; t < 2; t++) {
        int k0 = t * 32;
        const float* rowp = p + (size_t)nl * 64 + k0;
#pragma unroll
        for (int q = 0; q < 4; q++) {
            float4 a = okl ? *(const float4*)(rowp + lh + q * 4)
                           : make_float4(0.f, 0.f, 0.f, 0.f);
            Xs[(lh + q * 4 + 0) * PITCH + le] = a.x;
            Xs[(lh + q * 4 + 1) * PITCH + le] = a.y;
            Xs[(lh + q * 4 + 2) * PITCH + le] = a.z;
            Xs[(lh + q * 4 + 3) * PITCH + le] = a.w;
        }
        {
            const float* wr = (woc < 64) ? (Wp + (size_t)(k0 + wkk) * 64 + woc)
                                         : (Wp + (size_t)(64 + k0 + wkk) * 64 + (woc - 64));
#pragma unroll
            for (int q = 0; q < 4; q++)
                *(float4*)&Ws[wkk * 128 + woc + q * 4] = *(const float4*)(wr + q * 4);
        }
        __syncthreads();
#pragma unroll 16
        for (int kk = 0; kk < 32; kk++) {
            float4 wa = *(const float4*)&Ws[kk * 128 + tx * 4];
            float4 wb = *(const float4*)&Ws[kk * 128 + 64 + tx * 4];
            ull a0 = pack2(wa.x, wa.x), a1 = pack2(wa.y, wa.y);
            ull a2 = pack2(wa.z, wa.z), a3 = pack2(wa.w, wa.w);
            ull b0 = pack2(wb.x, wb.x), b1 = pack2(wb.y, wb.y);
            ull b2 = pack2(wb.z, wb.z), b3 = pack2(wb.w, wb.w);
            const ull* xp = (const ull*)&Xs[kk * PITCH + te * 8];
#pragma unroll
            for (int i = 0; i < 4; i++) {
                ull x = xp[i];
                acca[i][0] = fma2(x, a0, acca[i][0]);
                acca[i][1] = fma2(x, a1, acca[i][1]);
                acca[i][2] = fma2(x, a2, acca[i][2]);
                acca[i][3] = fma2(x, a3, acca[i][3]);
                accb[i][0] = fma2(x, b0, accb[i][0]);
                accb[i][1] = fma2(x, b1, accb[i][1]);
                accb[i][2] = fma2(x, b2, accb[i][2]);
                accb[i][3] = fma2(x, b3, accb[i][3]);
            }
        }
        __syncthreads();
    }
#pragma unroll
    for (int i = 0; i < 4; i++) {
        float2 a0 = unpack2(acca[i][0]), a1 = unpack2(acca[i][1]);
        float2 a2 = unpack2(acca[i][2]), a3 = unpack2(acca[i][3]);
        float2 b0 = unpack2(accb[i][0]), b1 = unpack2(accb[i][1]);
        float2 b2 = unpack2(accb[i][2]), b3 = unpack2(accb[i][3]);
        int n0 = base + te * 8 + 2 * i;
        if (n0 < N) {
            __half* Ar = g_A + (size_t)n0 * 128 + 64 + tx * 4;
            __half* Br = g_B + (size_t)n0 * 128 + 64 + tx * 4;
            *(__half2*)Ar = __floats2half2_rn(a0.x, a1.x);
            *(__half2*)(Ar + 2) = __floats2half2_rn(a2.x, a3.x);
            *(__half2*)Br = __floats2half2_rn(b0.x, b1.x);
            *(__half2*)(Br + 2) = __floats2half2_rn(b2.x, b3.x);
        }
        if (n0 + 1 < N) {
            __half* Ar = g_A + (size_t)(n0 + 1) * 128 + 64 + tx * 4;
            __half* Br = g_B + (size_t)(n0 + 1) * 128 + 64 + tx * 4;
            *(__half2*)Ar = __floats2half2_rn(a0.y, a1.y);
            *(__half2*)(Ar + 2) = __floats2half2_rn(a2.y, a3.y);
            *(__half2*)Br = __floats2half2_rn(b0.y, b1.y);
            *(__half2*)(Br + 2) = __floats2half2_rn(b2.y, b3.y);
        }
    }
}

// ---------------- edge-feature GEMM via mma.sync (tensor cores) ------------------
// Per block: C[128 edges, 128 outs] = X[128,32] @ W[32,128] + bias, fp16 out.
// W cols 0..63 = Wh rows 256..287; cols 64..127 = Wp rows 128..159.
constexpr int XP = 40;    // X smem pitch in halfs (20 banks -> ldmatrix conflict-free)
constexpr int WP = 136;   // W smem pitch in halfs (4-bank row stride -> conflict-free)

__global__ void __launch_bounds__(256) k_edgeE(
    const float* __restrict__ ef,
    const float* __restrict__ Wh, const float* __restrict__ bh,
    const float* __restrict__ Wp, const float* __restrict__ bp)
{
    __shared__ __align__(16) __half Xs[128 * XP];
    __shared__ __align__(16) __half Ws[32 * WP];
    __shared__ float bias[128];

    int tid = threadIdx.x;
    int base = blockIdx.x * 128;
    int w = tid >> 5;
    int l = tid & 31;

    // stage X: 128 edges x 32 k, fp32 -> fp16
    {
        int row = tid >> 1;
        int c0 = (tid & 1) * 16;
        const float* rowp = ef + (size_t)(base + row) * 32 + c0;
        __half* xd = Xs + row * XP + c0;
#pragma unroll
        for (int q = 0; q < 4; q++) {
            float4 a = *(const float4*)(rowp + q * 4);
            *(__half2*)(xd + q * 4)     = __floats2half2_rn(a.x, a.y);
            *(__half2*)(xd + q * 4 + 2) = __floats2half2_rn(a.z, a.w);
        }
    }
    // stage W: 32 k x 128 outs, fp32 -> fp16
    {
        int k = tid >> 3;
        int c0 = (tid & 7) * 16;
        const float* wr = (c0 < 64) ? (Wh + (size_t)(256 + k) * 64 + c0)
                                    : (Wp + (size_t)(128 + k) * 64 + (c0 - 64));
        __half* wd = Ws + k * WP + c0;
#pragma unroll
        for (int q = 0; q < 4; q++) {
            float4 a = *(const float4*)(wr + q * 4);
            *(__half2*)(wd + q * 4)     = __floats2half2_rn(a.x, a.y);
            *(__half2*)(wd + q * 4 + 2) = __floats2half2_rn(a.z, a.w);
        }
    }
    if (tid < 128) bias[tid] = (tid < 64) ? bh[tid] : bp[tid - 64];
    __syncthreads();

    float acc[16][4];
#pragma unroll
    for (int j = 0; j < 16; j++)
#pragma unroll
        for (int q = 0; q < 4; q++) acc[j][q] = 0.f;

    int slab = w * 16;
    int r8 = l & 7;
    int mat = l >> 3;

    unsigned xsbase = (unsigned)__cvta_generic_to_shared(Xs);
    unsigned wsbase = (unsigned)__cvta_generic_to_shared(Ws);

#pragma unroll
    for (int kc = 0; kc < 2; kc++) {
        // A fragment: rows slab..slab+15, k = 16*kc..+16
        int arow = slab + r8 + ((mat & 1) ? 8 : 0);
        int acol = kc * 16 + ((mat & 2) ? 8 : 0);
        uint4 a = ldsm_x4(xsbase + (unsigned)(arow * XP + acol) * 2u);
#pragma unroll
        for (int j = 0; j < 8; j++) {
            // B fragments for cols 16j..16j+15
            int bk = kc * 16 + r8 + ((mat & 1) ? 8 : 0);
            int bn = j * 16 + ((mat & 2) ? 8 : 0);
            uint4 b = ldsm_x4_t(wsbase + (unsigned)(bk * WP + bn) * 2u);
            mma16816(acc[2 * j],     a, b.x, b.y);
            mma16816(acc[2 * j + 1], a, b.z, b.w);
        }
    }

    // epilogue: D lane map: d0=(r,c) d1=(r,c+1) d2=(r+8,c) d3=(r+8,c+1)
    int r0 = slab + (l >> 2);
    int c0 = (l & 3) * 2;
    __half* out0 = g_ce + (size_t)(base + r0) * 128;
    __half* out1 = g_ce + (size_t)(base + r0 + 8) * 128;
#pragma unroll
    for (int j = 0; j < 16; j++) {
        int col = 8 * j + c0;
        float bz0 = bias[col], bz1 = bias[col + 1];
        *(__half2*)(out0 + col) = __floats2half2_rn(acc[j][0] + bz0, acc[j][1] + bz1);
        *(__half2*)(out1 + col) = __floats2half2_rn(acc[j][2] + bz0, acc[j][3] + bz1);
    }
}

// ---------------- fused message + PNA aggregation ----------------
__global__ void k_agg() {
    int warp = (blockIdx.x * blockDim.x + threadIdx.x) >> 5;
    int l = threadIdx.x & 31;
    if (warp >= N) return;
    int n = warp;
    int s0 = g_offs[n];
    int s1 = g_offs[n + 1];
    int d = s1 - s0;

    int off4 = 4 * l;
    float4 bv = ldh4(g_B + (size_t)n * 128 + off4);

    float4 sm = make_float4(0.f, 0.f, 0.f, 0.f);
    float4 sq = make_float4(0.f, 0.f, 0.f, 0.f);
    float4 mx = make_float4(-FLT_BIG, -FLT_BIG, -FLT_BIG, -FLT_BIG);
    float4 mn = make_float4(FLT_BIG, FLT_BIG, FLT_BIG, FLT_BIG);

#define AGG_ACC(CV, AV)                                                          \
    do {                                                                         \
        float v0 = (CV).x + (AV).x + bv.x;                                       \
        float v1 = (CV).y + (AV).y + bv.y;                                       \
        float v2 = (CV).z + (AV).z + bv.z;                                       \
        float v3 = (CV).w + (AV).w + bv.w;                                       \
        sm.x += v0; sq.x += v0 * v0; mx.x = fmaxf(mx.x, v0); mn.x = fminf(mn.x, v0); \
        sm.y += v1; sq.y += v1 * v1; mx.y = fmaxf(mx.y, v1); mn.y = fminf(mn.y, v1); \
        sm.z += v2; sq.z += v2 * v2; mx.z = fmaxf(mx.z, v2); mn.z = fminf(mn.z, v2); \
        sm.w += v3; sq.w += v3 * v3; mx.w = fmaxf(mx.w, v3); mn.w = fminf(mn.w, v3); \
    } while (0)

    int i = s0;
    if ((s1 - s0) & 1) {
        int s = g_srcs[i];
        int eid = g_perm[i];
        float4 cv = ldh4(g_ce + (size_t)eid * 128 + off4);
        float4 av = ldh4(g_A + (size_t)s * 128 + off4);
        AGG_ACC(cv, av);
        i++;
    }
    for (; i < s1; i += 2) {
        int sA = g_srcs[i],   sB = g_srcs[i + 1];
        int eA = g_perm[i],   eB = g_perm[i + 1];
        uint2 uCA = *(const uint2*)(g_ce + (size_t)eA * 128 + off4);
        uint2 uAA = *(const uint2*)(g_A + (size_t)sA * 128 + off4);
        uint2 uCB = *(const uint2*)(g_ce + (size_t)eB * 128 + off4);
        uint2 uAB = *(const uint2*)(g_A + (size_t)sB * 128 + off4);
        {
            __half2 lo = *reinterpret_cast<__half2*>(&uCA.x);
            __half2 hi = *reinterpret_cast<__half2*>(&uCA.y);
            float2 c01 = __half22float2(lo), c23 = __half22float2(hi);
            lo = *reinterpret_cast<__half2*>(&uAA.x);
            hi = *reinterpret_cast<__half2*>(&uAA.y);
            float2 a01 = __half22float2(lo), a23 = __half22float2(hi);
            float4 cv = make_float4(c01.x, c01.y, c23.x, c23.y);
            float4 av = make_float4(a01.x, a01.y, a23.x, a23.y);
            AGG_ACC(cv, av);
        }
        {
            __half2 lo = *reinterpret_cast<__half2*>(&uCB.x);
            __half2 hi = *reinterpret_cast<__half2*>(&uCB.y);
            float2 c01 = __half22float2(lo), c23 = __half22float2(hi);
            lo = *reinterpret_cast<__half2*>(&uAB.x);
            hi = *reinterpret_cast<__half2*>(&uAB.y);
            float2 a01 = __half22float2(lo), a23 = __half22float2(hi);
            float4 cv = make_float4(c01.x, c01.y, c23.x, c23.y);
            float4 av = make_float4(a01.x, a01.y, a23.x, a23.y);
            AGG_ACC(cv, av);
        }
    }
#undef AGG_ACC

    float degc = fmaxf((float)d, 1.f);
    float inv = 1.f / degc;
    bool has = d > 0;
    float logd = has ? logf((float)d + 1.f) : 1.f;
    float amp = logd / AVG_D_LOG;
    float att = AVG_D_LOG / logd;
    if (l == 0) { g_amp[n] = amp; g_att[n] = att; }

    float* o = (off4 < 64) ? (g_aggh + (size_t)n * 256) : (g_aggp + (size_t)n * 256);
    int f = off4 & 63;

    float4 mean = make_float4(sm.x * inv, sm.y * inv, sm.z * inv, sm.w * inv);
    float4 var = make_float4(fmaxf(sq.x * inv - mean.x * mean.x, 0.f),
                             fmaxf(sq.y * inv - mean.y * mean.y, 0.f),
                             fmaxf(sq.z * inv - mean.z * mean.z, 0.f),
                             fmaxf(sq.w * inv - mean.w * mean.w, 0.f));
    float4 sd = make_float4(sqrtf(var.x + EPS_STD), sqrtf(var.y + EPS_STD),
                            sqrtf(var.z + EPS_STD), sqrtf(var.w + EPS_STD));
    float4 MX = has ? mx : make_float4(0.f, 0.f, 0.f, 0.f);
    float4 MN = has ? mn : make_float4(0.f, 0.f, 0.f, 0.f);
    *(float4*)(o + f) = mean;
    *(float4*)(o + 64 + f) = MX;
    *(float4*)(o + 128 + f) = MN;
    *(float4*)(o + 192 + f) = sd;
}

// ---------------- node GEMMs: 3 rails + FUSED BN stats (reuses Xs smem) ----------
__global__ void __launch_bounds__(256) k_nodegemm(
    const float* __restrict__ h, const float* __restrict__ p,
    const float* __restrict__ snorm,
    const float* __restrict__ Woh, const float* __restrict__ boh,
    const float* __restrict__ Wop, const float* __restrict__ bop,
    float* __restrict__ out)
{
    __shared__ __align__(16) float Xs[32 * 64];
    __shared__ __align__(16) float Ws[3 * 32 * 64];

    int tid = threadIdx.x;
    int base = blockIdx.x * 64;

    int tx = tid & 31;
    int te = tid >> 5;
    int le = tid & 63;
    int lh = (tid >> 6) * 8;
    int wkk = tid >> 3;
    int woc = (tid & 7) * 8;

    int nl = base + le;
    bool okl = nl < N;

    ull accI[4][2], accA[4][2], accT[4][2];

    // =================== phase H =========
#pragma unroll
    for (int i = 0; i < 4; i++)
#pragma unroll
        for (int j = 0; j < 2; j++) { accI[i][j] = 0ull; accA[i][j] = 0ull; accT[i][j] = 0ull; }

    for (int t = 0; t < 12; t++) {
        int k0 = t * 32;
        bool isAgg = (t >= 4);
        const float* rowp = isAgg ? (g_aggh + (size_t)nl * 256 + (k0 - 128))
                                  : (h + (size_t)nl * 128 + k0);
#pragma unroll
        for (int q = 0; q < 2; q++) {
            float4 a = okl ? *(const float4*)(rowp + lh + q * 4)
                           : make_float4(0.f, 0.f, 0.f, 0.f);
            Xs[(lh + q * 4 + 0) * 64 + le] = a.x;
            Xs[(lh + q * 4 + 1) * 64 + le] = a.y;
            Xs[(lh + q * 4 + 2) * 64 + le] = a.z;
            Xs[(lh + q * 4 + 3) * 64 + le] = a.w;
        }
        if (isAgg) {
            int aggk = k0 - 128;
            const float* wI = Woh + (size_t)(128 + aggk + wkk) * 64 + woc;
            const float* wA = Woh + (size_t)(384 + aggk + wkk) * 64 + woc;
            const float* wT = Woh + (size_t)(640 + aggk + wkk) * 64 + woc;
            *(float4*)&Ws[wkk * 64 + woc]              = *(const float4*)(wI);
            *(float4*)&Ws[wkk * 64 + woc + 4]          = *(const float4*)(wI + 4);
            *(float4*)&Ws[2048 + wkk * 64 + woc]       = *(const float4*)(wA);
            *(float4*)&Ws[2048 + wkk * 64 + woc + 4]   = *(const float4*)(wA + 4);
            *(float4*)&Ws[4096 + wkk * 64 + woc]       = *(const float4*)(wT);
            *(float4*)&Ws[4096 + wkk * 64 + woc + 4]   = *(const float4*)(wT + 4);
        } else {
            const float* wI = Woh + (size_t)(k0 + wkk) * 64 + woc;
            *(float4*)&Ws[wkk * 64 + woc]     = *(const float4*)(wI);
            *(float4*)&Ws[wkk * 64 + woc + 4] = *(const float4*)(wI + 4);
        }
        __syncthreads();
        if (isAgg) {
#pragma unroll 8
            for (int kk = 0; kk < 32; kk++) {
                float2 wi = *(const float2*)&Ws[kk * 64 + tx * 2];
                float2 wa = *(const float2*)&Ws[2048 + kk * 64 + tx * 2];
                float2 wt = *(const float2*)&Ws[4096 + kk * 64 + tx * 2];
                ull i0 = pack2(wi.x, wi.x), i1 = pack2(wi.y, wi.y);
                ull a0 = pack2(wa.x, wa.x), a1 = pack2(wa.y, wa.y);
                ull t0 = pack2(wt.x, wt.x), t1 = pack2(wt.y, wt.y);
                const ull* xp = (const ull*)&Xs[kk * 64 + te * 8];
#pragma unroll
                for (int i = 0; i < 4; i++) {
                    ull x = xp[i];
                    accI[i][0] = fma2(x, i0, accI[i][0]);
                    accI[i][1] = fma2(x, i1, accI[i][1]);
                    accA[i][0] = fma2(x, a0, accA[i][0]);
                    accA[i][1] = fma2(x, a1, accA[i][1]);
                    accT[i][0] = fma2(x, t0, accT[i][0]);
                    accT[i][1] = fma2(x, t1, accT[i][1]);
                }
            }
        } else {
#pragma unroll 8
            for (int kk = 0; kk < 32; kk++) {
                float2 wi = *(const float2*)&Ws[kk * 64 + tx * 2];
                ull i0 = pack2(wi.x, wi.x), i1 = pack2(wi.y, wi.y);
                const ull* xp = (const ull*)&Xs[kk * 64 + te * 8];
#pragma unroll
                for (int i = 0; i < 4; i++) {
                    ull x = xp[i];
                    accI[i][0] = fma2(x, i0, accI[i][0]);
                    accI[i][1] = fma2(x, i1, accI[i][1]);
                }
            }
        }
        __syncthreads();
    }
    {
        float2 bias = *(const float2*)&boh[tx * 2];
        float s0 = 0.f, q0 = 0.f, s1 = 0.f, q1 = 0.f;
#pragma unroll
        for (int i = 0; i < 4; i++) {
            int n0 = base + te * 8 + 2 * i;
            float am0 = (n0 < N) ? g_amp[n0] : 0.f;
            float am1 = (n0 + 1 < N) ? g_amp[n0 + 1] : 0.f;
            float at0 = (n0 < N) ? g_att[n0] : 0.f;
            float at1 = (n0 + 1 < N) ? g_att[n0 + 1] : 0.f;
            ull ampP = pack2(am0, am1), attP = pack2(at0, at1);
            ull y0 = fma2(attP, accT[i][0], fma2(ampP, accA[i][0], accI[i][0]));
            ull y1 = fma2(attP, accT[i][1], fma2(ampP, accA[i][1], accI[i][1]));
            float2 u0 = unpack2(y0), u1 = unpack2(y1);
            if (n0 < N) {
                float sn = snorm[n0];
                float o0 = (u0.x + bias.x) * sn, o1 = (u1.x + bias.y) * sn;
                *(float2*)&out[(size_t)n0 * 64 + tx * 2] = make_float2(o0, o1);
                s0 += o0; q0 += o0 * o0; s1 += o1; q1 += o1 * o1;
            }
            if (n0 + 1 < N) {
                float sn = snorm[n0 + 1];
                float o0 = (u0.y + bias.x) * sn, o1 = (u1.y + bias.y) * sn;
                *(float2*)&out[(size_t)(n0 + 1) * 64 + tx * 2] = make_float2(o0, o1);
                s0 += o0; q0 += o0 * o0; s1 += o1; q1 += o1 * o1;
            }
        }
        __syncthreads();
        Xs[te * 64 + 2 * tx]       = s0;
        Xs[te * 64 + 2 * tx + 1]   = s1;
        Xs[512 + te * 64 + 2 * tx]     = q0;
        Xs[512 + te * 64 + 2 * tx + 1] = q1;
        __syncthreads();
        if (tid < 64) {
            float S = 0.f, Q = 0.f;
#pragma unroll
            for (int r = 0; r < 8; r++) { S += Xs[r * 64 + tid]; Q += Xs[512 + r * 64 + tid]; }
            atomicAdd(&g_bnsum[tid], S);
            atomicAdd(&g_bnsq[tid], Q);
        }
        __syncthreads();
    }

    // =================== phase P ==========
#pragma unroll
    for (int i = 0; i < 4; i++)
#pragma unroll
        for (int j = 0; j < 2; j++) { accI[i][j] = 0ull; accA[i][j] = 0ull; accT[i][j] = 0ull; }

    for (int t = 0; t < 10; t++) {
        int k0 = t * 32;
        bool isAgg = (t >= 2);
        const float* rowp = isAgg ? (g_aggp + (size_t)nl * 256 + (k0 - 64))
                                  : (p + (size_t)nl * 64 + k0);
#pragma unroll
        for (int q = 0; q < 2; q++) {
            float4 a = okl ? *(const float4*)(rowp + lh + q * 4)
                           : make_float4(0.f, 0.f, 0.f, 0.f);
            Xs[(lh + q * 4 + 0) * 64 + le] = a.x;
            Xs[(lh + q * 4 + 1) * 64 + le] = a.y;
            Xs[(lh + q * 4 + 2) * 64 + le] = a.z;
            Xs[(lh + q * 4 + 3) * 64 + le] = a.w;
        }
        if (isAgg) {
            int aggk = k0 - 64;
            const float* wI = Wop + (size_t)(64 + aggk + wkk) * 64 + woc;
            const float* wA = Wop + (size_t)(320 + aggk + wkk) * 64 + woc;
            const float* wT = Wop + (size_t)(576 + aggk + wkk) * 64 + woc;
            *(float4*)&Ws[wkk * 64 + woc]              = *(const float4*)(wI);
            *(float4*)&Ws[wkk * 64 + woc + 4]          = *(const float4*)(wI + 4);
            *(float4*)&Ws[2048 + wkk * 64 + woc]       = *(const float4*)(wA);
            *(float4*)&Ws[2048 + wkk * 64 + woc + 4]   = *(const float4*)(wA + 4);
            *(float4*)&Ws[4096 + wkk * 64 + woc]       = *(const float4*)(wT);
            *(float4*)&Ws[4096 + wkk * 64 + woc + 4]   = *(const float4*)(wT + 4);
        } else {
            const float* wI = Wop + (size_t)(k0 + wkk) * 64 + woc;
            *(float4*)&Ws[wkk * 64 + woc]     = *(const float4*)(wI);
            *(float4*)&Ws[wkk * 64 + woc + 4] = *(const float4*)(wI + 4);
        }
        __syncthreads();
        if (isAgg) {
#pragma unroll 8
            for (int kk = 0; kk < 32; kk++) {
                float2 wi = *(const float2*)&Ws[kk * 64 + tx * 2];
                float2 wa = *(const float2*)&Ws[2048 + kk * 64 + tx * 2];
                float2 wt = *(const float2*)&Ws[4096 + kk * 64 + tx * 2];
                ull i0 = pack2(wi.x, wi.x), i1 = pack2(wi.y, wi.y);
                ull a0 = pack2(wa.x, wa.x), a1 = pack2(wa.y, wa.y);
                ull t0 = pack2(wt.x, wt.x), t1 = pack2(wt.y, wt.y);
                const ull* xp = (const ull*)&Xs[kk * 64 + te * 8];
#pragma unroll
                for (int i = 0; i < 4; i++) {
                    ull x = xp[i];
                    accI[i][0] = fma2(x, i0, accI[i][0]);
                    accI[i][1] = fma2(x, i1, accI[i][1]);
                    accA[i][0] = fma2(x, a0, accA[i][0]);
                    accA[i][1] = fma2(x, a1, accA[i][1]);
                    accT[i][0] = fma2(x, t0, accT[i][0]);
                    accT[i][1] = fma2(x, t1, accT[i][1]);
                }
            }
        } else {
#pragma unroll 8
            for (int kk = 0; kk < 32; kk++) {
                float2 wi = *(const float2*)&Ws[kk * 64 + tx * 2];
                ull i0 = pack2(wi.x, wi.x), i1 = pack2(wi.y, wi.y);
                const ull* xp = (const ull*)&Xs[kk * 64 + te * 8];
#pragma unroll
                for (int i = 0; i < 4; i++) {
                    ull x = xp[i];
                    accI[i][0] = fma2(x, i0, accI[i][0]);
                    accI[i][1] = fma2(x, i1, accI[i][1]);
                }
            }
        }
        __syncthreads();
    }
    {
        float2 bias = *(const float2*)&bop[tx * 2];
        float* outp = out + (size_t)N * 64;
#pragma unroll
        for (int i = 0; i < 4; i++) {
            int n0 = base + te * 8 + 2 * i;
            float am0 = (n0 < N) ? g_amp[n0] : 0.f;
            float am1 = (n0 + 1 < N) ? g_amp[n0 + 1] : 0.f;
            float at0 = (n0 < N) ? g_att[n0] : 0.f;
            float at1 = (n0 + 1 < N) ? g_att[n0 + 1] : 0.f;
            ull ampP = pack2(am0, am1), attP = pack2(at0, at1);
            ull y0 = fma2(attP, accT[i][0], fma2(ampP, accA[i][0], accI[i][0]));
            ull y1 = fma2(attP, accT[i][1], fma2(ampP, accA[i][1], accI[i][1]));
            float2 u0 = unpack2(y0), u1 = unpack2(y1);
            if (n0 < N)
                *(float2*)&outp[(size_t)n0 * 64 + tx * 2] =
                    make_float2(u0.x + bias.x, u1.x + bias.y);
            if (n0 + 1 < N)
                *(float2*)&outp[(size_t)(n0 + 1) * 64 + tx * 2] =
                    make_float2(u0.y + bias.x, u1.y + bias.y);
        }
    }
}

// ---------------- batchnorm apply (float4 vectorized) ----------------
__global__ void k_bnapply(float* __restrict__ out,
                          const float* __restrict__ gamma,
                          const float* __restrict__ beta) {
    int i = blockIdx.x * blockDim.x + threadIdx.x;
    if (i >= N * 16) return;
    int f = (i & 15) * 4;
    const float invN = 1.f / (float)N;
    float4 su = *(const float4*)&g_bnsum[f];
    float4 qu = *(const float4*)&g_bnsq[f];
    float4 ga = *(const float4*)&gamma[f];
    float4 be = *(const float4*)&beta[f];
    float4 mu = make_float4(su.x * invN, su.y * invN, su.z * invN, su.w * invN);
    float4 rs = make_float4(
        rsqrtf(qu.x * invN - mu.x * mu.x + EPS_BN),
        rsqrtf(qu.y * invN - mu.y * mu.y + EPS_BN),
        rsqrtf(qu.z * invN - mu.z * mu.z + EPS_BN),
        rsqrtf(qu.w * invN - mu.w * mu.w + EPS_BN));
    float4 x = *(float4*)&out[(size_t)i * 4];
    x.x = (x.x - mu.x) * rs.x * ga.x + be.x;
    x.y = (x.y - mu.y) * rs.y * ga.y + be.y;
    x.z = (x.z - mu.z) * rs.z * ga.z + be.z;
    x.w = (x.w - mu.w) * rs.w * ga.w + be.w;
    *(float4*)&out[(size_t)i * 4] = x;
}

} // namespace

extern "C" void kernel_launch(void* const* d_in, const int* in_sizes, int n_in,
                              void* d_out, int out_size) {
    const float* h     = (const float*)d_in[0];
    const float* p     = (const float*)d_in[1];
    const float* e     = (const float*)d_in[2];
    const int*   src   = (const int*)d_in[3];
    const int*   dst   = (const int*)d_in[4];
    const float* snorm = (const float*)d_in[5];
    const float* Wph   = (const float*)d_in[6];
    const float* bph   = (const float*)d_in[7];
    const float* Wpp   = (const float*)d_in[8];
    const float* bpp   = (const float*)d_in[9];
    const float* Woh   = (const float*)d_in[10];
    const float* boh   = (const float*)d_in[11];
    const float* Wop   = (const float*)d_in[12];
    const float* bop   = (const float*)d_in[13];
    const float* gamma = (const float*)d_in[14];
    const float* beta  = (const float*)d_in[15];
    float* out = (float*)d_out;

    static cudaStream_t s_pre = nullptr, s_edge = nullptr;
    static cudaEvent_t ev_fork = nullptr, ev_pre = nullptr, ev_edge = nullptr;
    if (s_pre == nullptr) {
        cudaStreamCreateWithFlags(&s_pre, cudaStreamNonBlocking);
        cudaStreamCreateWithFlags(&s_edge, cudaStreamNonBlocking);
        cudaEventCreateWithFlags(&ev_fork, cudaEventDisableTiming);
        cudaEventCreateWithFlags(&ev_pre, cudaEventDisableTiming);
        cudaEventCreateWithFlags(&ev_edge, cudaEventDisableTiming);
    }

    cudaEventRecord(ev_fork, 0);
    cudaStreamWaitEvent(s_pre, ev_fork, 0);
    cudaStreamWaitEvent(s_edge, ev_fork, 0);

    k_nodepre<<<(N + 127) / 128, 256, 0, s_pre>>>(h, p, Wph, Wpp);
    cudaEventRecord(ev_pre, s_pre);

    k_edgeE<<<E / 128, 256, 0, s_edge>>>(e, Wph, bph, Wpp, bpp);
    cudaEventRecord(ev_edge, s_edge);

    k_init<<<(N + 255) / 256, 256>>>();
    k_hist<<<(E + 255) / 256, 256>>>(dst);
    k_scan1<<<SCAN_BLOCKS, 1024>>>();
    k_scan2<<<1, 32>>>();
    k_scan3<<<SCAN_BLOCKS, 1024>>>();
    k_scatter<<<(E + 255) / 256, 256>>>(dst, src);

    cudaStreamWaitEvent(0, ev_pre, 0);
    cudaStreamWaitEvent(0, ev_edge, 0);
    k_agg<<<(N * 32 + 255) / 256, 256>>>();
    k_nodegemm<<<(N + 63) / 64, 256>>>(h, p, snorm, Woh, boh, Wop, bop, out);
    k_bnapply<<<(N * 16 + 255) / 256, 256>>>(out, gamma, beta);
}

// round 12
// speedup vs baseline: 1.9462x; 1.2962x over previous
#include <cuda_runtime.h>
#include <cuda_fp16.h>
#include <math.h>

namespace {

constexpr int N = 50000;
constexpr int E = 800000;
constexpr float AVG_D_LOG = 2.8332f;
constexpr float EPS_STD = 1e-5f;
constexpr float EPS_BN = 1e-5f;
constexpr float FLT_BIG = 3.402823466e+38f;
constexpr int PITCH = 130;
constexpr int SCAN_BLOCKS = (N + 1023) / 1024;   // 49

typedef unsigned long long ull;

__device__ __forceinline__ ull fma2(ull a, ull b, ull c) {
    ull d;
    asm("fma.rn.f32x2 %0,%1,%2,%3;" : "=l"(d) : "l"(a), "l"(b), "l"(c));
    return d;
}
__device__ __forceinline__ ull pack2(float x, float y) {
    ull d;
    asm("mov.b64 %0,{%1,%2};" : "=l"(d) : "f"(x), "f"(y));
    return d;
}
__device__ __forceinline__ float2 unpack2(ull v) {
    float2 r;
    asm("mov.b64 {%0,%1},%2;" : "=f"(r.x), "=f"(r.y) : "l"(v));
    return r;
}
__device__ __forceinline__ float4 ldh4(const __half* ptr) {
    uint2 u = *(const uint2*)ptr;
    __half2 lo = *reinterpret_cast<__half2*>(&u.x);
    __half2 hi = *reinterpret_cast<__half2*>(&u.y);
    float2 f01 = __half22float2(lo), f23 = __half22float2(hi);
    return make_float4(f01.x, f01.y, f23.x, f23.y);
}
__device__ __forceinline__ uint4 ldsm_x4(unsigned addr) {
    uint4 r;
    asm volatile("ldmatrix.sync.aligned.m8n8.x4.shared.b16 {%0,%1,%2,%3}, [%4];"
                 : "=r"(r.x), "=r"(r.y), "=r"(r.z), "=r"(r.w) : "r"(addr));
    return r;
}
__device__ __forceinline__ uint4 ldsm_x4_t(unsigned addr) {
    uint4 r;
    asm volatile("ldmatrix.sync.aligned.m8n8.x4.trans.shared.b16 {%0,%1,%2,%3}, [%4];"
                 : "=r"(r.x), "=r"(r.y), "=r"(r.z), "=r"(r.w) : "r"(addr));
    return r;
}
__device__ __forceinline__ void mma16816(float* d, uint4 a, unsigned b0, unsigned b1) {
    asm volatile(
        "mma.sync.aligned.m16n8k16.row.col.f32.f16.f16.f32 "
        "{%0,%1,%2,%3},{%4,%5,%6,%7},{%8,%9},{%0,%1,%2,%3};"
        : "+f"(d[0]), "+f"(d[1]), "+f"(d[2]), "+f"(d[3])
        : "r"(a.x), "r"(a.y), "r"(a.z), "r"(a.w), "r"(b0), "r"(b1));
}

// ---- scratch (device globals: allocation-free contract) ----
__device__ int g_deg[N];
__device__ int g_offs[N + 1];
__device__ int g_cursor[N];
__device__ int g_perm[E];
__device__ int g_srcs[E];
__device__ int g_btot[SCAN_BLOCKS];
__device__ int g_boff[SCAN_BLOCKS];
__device__ __align__(16) __half g_A[(size_t)N * 128];
__device__ __align__(16) __half g_B[(size_t)N * 128];
__device__ __align__(16) __half g_ce[(size_t)E * 128];   // ORIGINAL edge order
__device__ __align__(16) __half g_aggh[(size_t)N * 256]; // fp16 [mean|max|min|std]
__device__ __align__(16) __half g_aggp[(size_t)N * 256];
__device__ float g_amp[N];
__device__ float g_att[N];
__device__ float g_bnsum[64];
__device__ float g_bnsq[64];

// ---------------- init ----------------
__global__ void k_init() {
    int i = blockIdx.x * blockDim.x + threadIdx.x;
    if (i < N) g_deg[i] = 0;
    if (i < 64) { g_bnsum[i] = 0.f; g_bnsq[i] = 0.f; }
}

// ---------------- degree histogram ----------------
__global__ void k_hist(const int* __restrict__ dst) {
    int e = blockIdx.x * blockDim.x + threadIdx.x;
    if (e < E) atomicAdd(&g_deg[dst[e]], 1);
}

// ---------------- multi-block exclusive scan ----------------
__global__ void k_scan1() {
    __shared__ int ws[32];
    int t = threadIdx.x;
    int lane = t & 31, w = t >> 5;
    int base = blockIdx.x * 1024;
    int v = (base + t < N) ? g_deg[base + t] : 0;
    int x = v;
#pragma unroll
    for (int off = 1; off < 32; off <<= 1) {
        int y = __shfl_up_sync(0xffffffffu, x, off);
        if (lane >= off) x += y;
    }
    if (lane == 31) ws[w] = x;
    __syncthreads();
    if (w == 0) {
        int s = ws[lane];
#pragma unroll
        for (int off = 1; off < 32; off <<= 1) {
            int y = __shfl_up_sync(0xffffffffu, s, off);
            if (lane >= off) s += y;
        }
        ws[lane] = s;
    }
    __syncthreads();
    int incl = x + (w > 0 ? ws[w - 1] : 0);
    if (base + t < N) g_offs[base + t] = incl - v;
    if (t == 1023) g_btot[blockIdx.x] = incl;
}

__global__ void k_scan2() {
    if (threadIdx.x == 0) {
        int acc = 0;
        for (int i = 0; i < SCAN_BLOCKS; i++) {
            g_boff[i] = acc;
            acc += g_btot[i];
        }
    }
}

__global__ void k_scan3() {
    int t = threadIdx.x;
    int base = blockIdx.x * 1024;
    int off = g_boff[blockIdx.x];
    if (base + t < N) {
        int v = g_offs[base + t] + off;
        g_offs[base + t] = v;
        g_cursor[base + t] = v;
    }
    if (blockIdx.x == 0 && t == 0) g_offs[N] = E;
}

// ---------------- scatter: counting sort by dst ----------------
__global__ void k_scatter(const int* __restrict__ dst, const int* __restrict__ src) {
    int e = blockIdx.x * blockDim.x + threadIdx.x;
    if (e < E) {
        int pos = atomicAdd(&g_cursor[dst[e]], 1);
        g_perm[pos] = e;
        g_srcs[pos] = src[e];
    }
}

// ---------------- node pre-GEMMs -> fp16 g_A, g_B (fma2 path, unchanged) ---------
__global__ void __launch_bounds__(256) k_nodepre(
    const float* __restrict__ h, const float* __restrict__ p,
    const float* __restrict__ Wh, const float* __restrict__ Wp)
{
    __shared__ __align__(16) float Xs[32 * PITCH];
    __shared__ __align__(16) float Ws[32 * 128];

    int tid = threadIdx.x;
    int base = blockIdx.x * 128;

    int tx = tid & 15;
    int te = tid >> 4;
    int le = tid & 127;
    int lh = (tid >> 7) * 16;
    int wkk = tid >> 3;
    int woc = (tid & 7) * 16;

    int nl = base + le;
    bool okl = nl < N;

    ull acca[4][4], accb[4][4];

#pragma unroll
    for (int i = 0; i < 4; i++)
#pragma unroll
        for (int j = 0; j < 4; j++) { acca[i][j] = 0ull; accb[i][j] = 0ull; }

    for (int t = 0; t < 4; t++) {
        int k0 = t * 32;
        const float* rowp = h + (size_t)nl * 128 + k0;
#pragma unroll
        for (int q = 0; q < 4; q++) {
            float4 a = okl ? *(const float4*)(rowp + lh + q * 4)
                           : make_float4(0.f, 0.f, 0.f, 0.f);
            Xs[(lh + q * 4 + 0) * PITCH + le] = a.x;
            Xs[(lh + q * 4 + 1) * PITCH + le] = a.y;
            Xs[(lh + q * 4 + 2) * PITCH + le] = a.z;
            Xs[(lh + q * 4 + 3) * PITCH + le] = a.w;
        }
        {
            const float* wr = (woc < 64) ? (Wh + (size_t)(k0 + wkk) * 64 + woc)
                                         : (Wh + (size_t)(128 + k0 + wkk) * 64 + (woc - 64));
#pragma unroll
            for (int q = 0; q < 4; q++)
                *(float4*)&Ws[wkk * 128 + woc + q * 4] = *(const float4*)(wr + q * 4);
        }
        __syncthreads();
#pragma unroll 16
        for (int kk = 0; kk < 32; kk++) {
            float4 wa = *(const float4*)&Ws[kk * 128 + tx * 4];
            float4 wb = *(const float4*)&Ws[kk * 128 + 64 + tx * 4];
            ull a0 = pack2(wa.x, wa.x), a1 = pack2(wa.y, wa.y);
            ull a2 = pack2(wa.z, wa.z), a3 = pack2(wa.w, wa.w);
            ull b0 = pack2(wb.x, wb.x), b1 = pack2(wb.y, wb.y);
            ull b2 = pack2(wb.z, wb.z), b3 = pack2(wb.w, wb.w);
            const ull* xp = (const ull*)&Xs[kk * PITCH + te * 8];
#pragma unroll
            for (int i = 0; i < 4; i++) {
                ull x = xp[i];
                acca[i][0] = fma2(x, a0, acca[i][0]);
                acca[i][1] = fma2(x, a1, acca[i][1]);
                acca[i][2] = fma2(x, a2, acca[i][2]);
                acca[i][3] = fma2(x, a3, acca[i][3]);
                accb[i][0] = fma2(x, b0, accb[i][0]);
                accb[i][1] = fma2(x, b1, accb[i][1]);
                accb[i][2] = fma2(x, b2, accb[i][2]);
                accb[i][3] = fma2(x, b3, accb[i][3]);
            }
        }
        __syncthreads();
    }
#pragma unroll
    for (int i = 0; i < 4; i++) {
        float2 a0 = unpack2(acca[i][0]), a1 = unpack2(acca[i][1]);
        float2 a2 = unpack2(acca[i][2]), a3 = unpack2(acca[i][3]);
        float2 b0 = unpack2(accb[i][0]), b1 = unpack2(accb[i][1]);
        float2 b2 = unpack2(accb[i][2]), b3 = unpack2(accb[i][3]);
        int n0 = base + te * 8 + 2 * i;
        if (n0 < N) {
            __half* Ar = g_A + (size_t)n0 * 128 + tx * 4;
            __half* Br = g_B + (size_t)n0 * 128 + tx * 4;
            *(__half2*)Ar = __floats2half2_rn(a0.x, a1.x);
            *(__half2*)(Ar + 2) = __floats2half2_rn(a2.x, a3.x);
            *(__half2*)Br = __floats2half2_rn(b0.x, b1.x);
            *(__half2*)(Br + 2) = __floats2half2_rn(b2.x, b3.x);
        }
        if (n0 + 1 < N) {
            __half* Ar = g_A + (size_t)(n0 + 1) * 128 + tx * 4;
            __half* Br = g_B + (size_t)(n0 + 1) * 128 + tx * 4;
            *(__half2*)Ar = __floats2half2_rn(a0.y, a1.y);
            *(__half2*)(Ar + 2) = __floats2half2_rn(a2.y, a3.y);
            *(__half2*)Br = __floats2half2_rn(b0.y, b1.y);
            *(__half2*)(Br + 2) = __floats2half2_rn(b2.y, b3.y);
        }
    }

#pragma unroll
    for (int i = 0; i < 4; i++)
#pragma unroll
        for (int j = 0; j < 4; j++) { acca[i][j] = 0ull; accb[i][j] = 0ull; }

    for (int t = 0; t < 2; t++) {
        int k0 = t * 32;
        const float* rowp = p + (size_t)nl * 64 + k0;
#pragma unroll
        for (int q = 0; q < 4; q++) {
            float4 a = okl ? *(const float4*)(rowp + lh + q * 4)
                           : make_float4(0.f, 0.f, 0.f, 0.f);
            Xs[(lh + q * 4 + 0) * PITCH + le] = a.x;
            Xs[(lh + q * 4 + 1) * PITCH + le] = a.y;
            Xs[(lh + q * 4 + 2) * PITCH + le] = a.z;
            Xs[(lh + q * 4 + 3) * PITCH + le] = a.w;
        }
        {
            const float* wr = (woc < 64) ? (Wp + (size_t)(k0 + wkk) * 64 + woc)
                                         : (Wp + (size_t)(64 + k0 + wkk) * 64 + (woc - 64));
#pragma unroll
            for (int q = 0; q < 4; q++)
                *(float4*)&Ws[wkk * 128 + woc + q * 4] = *(const float4*)(wr + q * 4);
        }
        __syncthreads();
#pragma unroll 16
        for (int kk = 0; kk < 32; kk++) {
            float4 wa = *(const float4*)&Ws[kk * 128 + tx * 4];
            float4 wb = *(const float4*)&Ws[kk * 128 + 64 + tx * 4];
            ull a0 = pack2(wa.x, wa.x), a1 = pack2(wa.y, wa.y);
            ull a2 = pack2(wa.z, wa.z), a3 = pack2(wa.w, wa.w);
            ull b0 = pack2(wb.x, wb.x), b1 = pack2(wb.y, wb.y);
            ull b2 = pack2(wb.z, wb.z), b3 = pack2(wb.w, wb.w);
            const ull* xp = (const ull*)&Xs[kk * PITCH + te * 8];
#pragma unroll
            for (int i = 0; i < 4; i++) {
                ull x = xp[i];
                acca[i][0] = fma2(x, a0, acca[i][0]);
                acca[i][1] = fma2(x, a1, acca[i][1]);
                acca[i][2] = fma2(x, a2, acca[i][2]);
                acca[i][3] = fma2(x, a3, acca[i][3]);
                accb[i][0] = fma2(x, b0, accb[i][0]);
                accb[i][1] = fma2(x, b1, accb[i][1]);
                accb[i][2] = fma2(x, b2, accb[i][2]);
                accb[i][3] = fma2(x, b3, accb[i][3]);
            }
        }
        __syncthreads();
    }
#pragma unroll
    for (int i = 0; i < 4; i++) {
        float2 a0 = unpack2(acca[i][0]), a1 = unpack2(acca[i][1]);
        float2 a2 = unpack2(acca[i][2]), a3 = unpack2(acca[i][3]);
        float2 b0 = unpack2(accb[i][0]), b1 = unpack2(accb[i][1]);
        float2 b2 = unpack2(accb[i][2]), b3 = unpack2(accb[i][3]);
        int n0 = base + te * 8 + 2 * i;
        if (n0 < N) {
            __half* Ar = g_A + (size_t)n0 * 128 + 64 + tx * 4;
            __half* Br = g_B + (size_t)n0 * 128 + 64 + tx * 4;
            *(__half2*)Ar = __floats2half2_rn(a0.x, a1.x);
            *(__half2*)(Ar + 2) = __floats2half2_rn(a2.x, a3.x);
            *(__half2*)Br = __floats2half2_rn(b0.x, b1.x);
            *(__half2*)(Br + 2) = __floats2half2_rn(b2.x, b3.x);
        }
        if (n0 + 1 < N) {
            __half* Ar = g_A + (size_t)(n0 + 1) * 128 + 64 + tx * 4;
            __half* Br = g_B + (size_t)(n0 + 1) * 128 + 64 + tx * 4;
            *(__half2*)Ar = __floats2half2_rn(a0.y, a1.y);
            *(__half2*)(Ar + 2) = __floats2half2_rn(a2.y, a3.y);
            *(__half2*)Br = __floats2half2_rn(b0.y, b1.y);
            *(__half2*)(Br + 2) = __floats2half2_rn(b2.y, b3.y);
        }
    }
}

// ---------------- edge-feature GEMM via mma.sync (tensor cores) ------------------
constexpr int XP = 40;
constexpr int WP = 136;

__global__ void __launch_bounds__(256) k_edgeE(
    const float* __restrict__ ef,
    const float* __restrict__ Wh, const float* __restrict__ bh,
    const float* __restrict__ Wp, const float* __restrict__ bp)
{
    __shared__ __align__(16) __half Xs[128 * XP];
    __shared__ __align__(16) __half Ws[32 * WP];
    __shared__ float bias[128];

    int tid = threadIdx.x;
    int base = blockIdx.x * 128;
    int w = tid >> 5;
    int l = tid & 31;

    {
        int row = tid >> 1;
        int c0 = (tid & 1) * 16;
        const float* rowp = ef + (size_t)(base + row) * 32 + c0;
        __half* xd = Xs + row * XP + c0;
#pragma unroll
        for (int q = 0; q < 4; q++) {
            float4 a = *(const float4*)(rowp + q * 4);
            *(__half2*)(xd + q * 4)     = __floats2half2_rn(a.x, a.y);
            *(__half2*)(xd + q * 4 + 2) = __floats2half2_rn(a.z, a.w);
        }
    }
    {
        int k = tid >> 3;
        int c0 = (tid & 7) * 16;
        const float* wr = (c0 < 64) ? (Wh + (size_t)(256 + k) * 64 + c0)
                                    : (Wp + (size_t)(128 + k) * 64 + (c0 - 64));
        __half* wd = Ws + k * WP + c0;
#pragma unroll
        for (int q = 0; q < 4; q++) {
            float4 a = *(const float4*)(wr + q * 4);
            *(__half2*)(wd + q * 4)     = __floats2half2_rn(a.x, a.y);
            *(__half2*)(wd + q * 4 + 2) = __floats2half2_rn(a.z, a.w);
        }
    }
    if (tid < 128) bias[tid] = (tid < 64) ? bh[tid] : bp[tid - 64];
    __syncthreads();

    float acc[16][4];
#pragma unroll
    for (int j = 0; j < 16; j++)
#pragma unroll
        for (int q = 0; q < 4; q++) acc[j][q] = 0.f;

    int slab = w * 16;
    int r8 = l & 7;
    int mat = l >> 3;

    unsigned xsbase = (unsigned)__cvta_generic_to_shared(Xs);
    unsigned wsbase = (unsigned)__cvta_generic_to_shared(Ws);

#pragma unroll
    for (int kc = 0; kc < 2; kc++) {
        int arow = slab + r8 + ((mat & 1) ? 8 : 0);
        int acol = kc * 16 + ((mat & 2) ? 8 : 0);
        uint4 a = ldsm_x4(xsbase + (unsigned)(arow * XP + acol) * 2u);
#pragma unroll
        for (int j = 0; j < 8; j++) {
            int bk = kc * 16 + r8 + ((mat & 1) ? 8 : 0);
            int bn = j * 16 + ((mat & 2) ? 8 : 0);
            uint4 b = ldsm_x4_t(wsbase + (unsigned)(bk * WP + bn) * 2u);
            mma16816(acc[2 * j],     a, b.x, b.y);
            mma16816(acc[2 * j + 1], a, b.z, b.w);
        }
    }

    int r0 = slab + (l >> 2);
    int c0 = (l & 3) * 2;
    __half* out0 = g_ce + (size_t)(base + r0) * 128;
    __half* out1 = g_ce + (size_t)(base + r0 + 8) * 128;
#pragma unroll
    for (int j = 0; j < 16; j++) {
        int col = 8 * j + c0;
        float bz0 = bias[col], bz1 = bias[col + 1];
        *(__half2*)(out0 + col) = __floats2half2_rn(acc[j][0] + bz0, acc[j][1] + bz1);
        *(__half2*)(out1 + col) = __floats2half2_rn(acc[j][2] + bz0, acc[j][3] + bz1);
    }
}

// ---------------- fused message + PNA aggregation (fp16 agg out) ----------------
__global__ void k_agg() {
    int warp = (blockIdx.x * blockDim.x + threadIdx.x) >> 5;
    int l = threadIdx.x & 31;
    if (warp >= N) return;
    int n = warp;
    int s0 = g_offs[n];
    int s1 = g_offs[n + 1];
    int d = s1 - s0;

    int off4 = 4 * l;
    float4 bv = ldh4(g_B + (size_t)n * 128 + off4);

    float4 sm = make_float4(0.f, 0.f, 0.f, 0.f);
    float4 sq = make_float4(0.f, 0.f, 0.f, 0.f);
    float4 mx = make_float4(-FLT_BIG, -FLT_BIG, -FLT_BIG, -FLT_BIG);
    float4 mn = make_float4(FLT_BIG, FLT_BIG, FLT_BIG, FLT_BIG);

#define AGG_ACC(CV, AV)                                                          \
    do {                                                                         \
        float v0 = (CV).x + (AV).x + bv.x;                                       \
        float v1 = (CV).y + (AV).y + bv.y;                                       \
        float v2 = (CV).z + (AV).z + bv.z;                                       \
        float v3 = (CV).w + (AV).w + bv.w;                                       \
        sm.x += v0; sq.x += v0 * v0; mx.x = fmaxf(mx.x, v0); mn.x = fminf(mn.x, v0); \
        sm.y += v1; sq.y += v1 * v1; mx.y = fmaxf(mx.y, v1); mn.y = fminf(mn.y, v1); \
        sm.z += v2; sq.z += v2 * v2; mx.z = fmaxf(mx.z, v2); mn.z = fminf(mn.z, v2); \
        sm.w += v3; sq.w += v3 * v3; mx.w = fmaxf(mx.w, v3); mn.w = fminf(mn.w, v3); \
    } while (0)

    int i = s0;
    if ((s1 - s0) & 1) {
        int s = g_srcs[i];
        int eid = g_perm[i];
        float4 cv = ldh4(g_ce + (size_t)eid * 128 + off4);
        float4 av = ldh4(g_A + (size_t)s * 128 + off4);
        AGG_ACC(cv, av);
        i++;
    }
    for (; i < s1; i += 2) {
        int sA = g_srcs[i],   sB = g_srcs[i + 1];
        int eA = g_perm[i],   eB = g_perm[i + 1];
        uint2 uCA = *(const uint2*)(g_ce + (size_t)eA * 128 + off4);
        uint2 uAA = *(const uint2*)(g_A + (size_t)sA * 128 + off4);
        uint2 uCB = *(const uint2*)(g_ce + (size_t)eB * 128 + off4);
        uint2 uAB = *(const uint2*)(g_A + (size_t)sB * 128 + off4);
        {
            __half2 lo = *reinterpret_cast<__half2*>(&uCA.x);
            __half2 hi = *reinterpret_cast<__half2*>(&uCA.y);
            float2 c01 = __half22float2(lo), c23 = __half22float2(hi);
            lo = *reinterpret_cast<__half2*>(&uAA.x);
            hi = *reinterpret_cast<__half2*>(&uAA.y);
            float2 a01 = __half22float2(lo), a23 = __half22float2(hi);
            float4 cv = make_float4(c01.x, c01.y, c23.x, c23.y);
            float4 av = make_float4(a01.x, a01.y, a23.x, a23.y);
            AGG_ACC(cv, av);
        }
        {
            __half2 lo = *reinterpret_cast<__half2*>(&uCB.x);
            __half2 hi = *reinterpret_cast<__half2*>(&uCB.y);
            float2 c01 = __half22float2(lo), c23 = __half22float2(hi);
            lo = *reinterpret_cast<__half2*>(&uAB.x);
            hi = *reinterpret_cast<__half2*>(&uAB.y);
            float2 a01 = __half22float2(lo), a23 = __half22float2(hi);
            float4 cv = make_float4(c01.x, c01.y, c23.x, c23.y);
            float4 av = make_float4(a01.x, a01.y, a23.x, a23.y);
            AGG_ACC(cv, av);
        }
    }
#undef AGG_ACC

    float degc = fmaxf((float)d, 1.f);
    float inv = 1.f / degc;
    bool has = d > 0;
    float logd = has ? logf((float)d + 1.f) : 1.f;
    float amp = logd / AVG_D_LOG;
    float att = AVG_D_LOG / logd;
    if (l == 0) { g_amp[n] = amp; g_att[n] = att; }

    __half* o = (off4 < 64) ? (g_aggh + (size_t)n * 256) : (g_aggp + (size_t)n * 256);
    int f = off4 & 63;

    float4 mean = make_float4(sm.x * inv, sm.y * inv, sm.z * inv, sm.w * inv);
    float4 var = make_float4(fmaxf(sq.x * inv - mean.x * mean.x, 0.f),
                             fmaxf(sq.y * inv - mean.y * mean.y, 0.f),
                             fmaxf(sq.z * inv - mean.z * mean.z, 0.f),
                             fmaxf(sq.w * inv - mean.w * mean.w, 0.f));
    float4 sd = make_float4(sqrtf(var.x + EPS_STD), sqrtf(var.y + EPS_STD),
                            sqrtf(var.z + EPS_STD), sqrtf(var.w + EPS_STD));
    float4 MX = has ? mx : make_float4(0.f, 0.f, 0.f, 0.f);
    float4 MN = has ? mn : make_float4(0.f, 0.f, 0.f, 0.f);
    *(__half2*)(o + f)       = __floats2half2_rn(mean.x, mean.y);
    *(__half2*)(o + f + 2)   = __floats2half2_rn(mean.z, mean.w);
    *(__half2*)(o + 64 + f)     = __floats2half2_rn(MX.x, MX.y);
    *(__half2*)(o + 64 + f + 2) = __floats2half2_rn(MX.z, MX.w);
    *(__half2*)(o + 128 + f)     = __floats2half2_rn(MN.x, MN.y);
    *(__half2*)(o + 128 + f + 2) = __floats2half2_rn(MN.z, MN.w);
    *(__half2*)(o + 192 + f)     = __floats2half2_rn(sd.x, sd.y);
    *(__half2*)(o + 192 + f + 2) = __floats2half2_rn(sd.z, sd.w);
}

// ---------------- node GEMMs via mma.sync: 3 rails + fused BN stats -------------
// Block: 128 nodes x 64 outs, 8 warps x 16-row slabs.
constexpr int XP2 = 40;   // X pitch (halfs)
constexpr int WP2 = 72;   // W pitch (halfs); 144B row stride -> conflict-free ldsm.trans

__global__ void __launch_bounds__(256) k_nodegemm(
    const float* __restrict__ h, const float* __restrict__ p,
    const float* __restrict__ snorm,
    const float* __restrict__ Woh, const float* __restrict__ boh,
    const float* __restrict__ Wop, const float* __restrict__ bop,
    float* __restrict__ out)
{
    __shared__ __align__(16) __half Xs[128 * XP2];        // 10240 B
    __shared__ __align__(16) __half Ws[3][32 * WP2];      // 13824 B
    __shared__ float sbias[64];
    __shared__ float s_amp[128], s_att[128], s_sn[128];
    __shared__ float sbn[64], sbq[64];

    int tid = threadIdx.x;
    int base = blockIdx.x * 128;
    int w = tid >> 5;
    int l = tid & 31;
    int slab = w * 16;
    int r8 = l & 7;
    int mat = l >> 3;

    if (tid < 128) {
        int n0 = base + tid;
        bool ok = n0 < N;
        s_amp[tid] = ok ? g_amp[n0] : 0.f;
        s_att[tid] = ok ? g_att[n0] : 0.f;
        s_sn[tid]  = ok ? snorm[n0] : 0.f;
    }
    if (tid < 64) { sbn[tid] = 0.f; sbq[tid] = 0.f; sbias[tid] = boh[tid]; }

    unsigned xsb = (unsigned)__cvta_generic_to_shared(Xs);
    unsigned wsb0 = (unsigned)__cvta_generic_to_shared(&Ws[0][0]);
    unsigned wsb1 = (unsigned)__cvta_generic_to_shared(&Ws[1][0]);
    unsigned wsb2 = (unsigned)__cvta_generic_to_shared(&Ws[2][0]);

    float accI[8][4], accA[8][4], accT[8][4];

    int xrow = tid >> 1;
    int xc0 = (tid & 1) * 16;
    int wk = (tid * 8) >> 6;     // 0..31
    int wn = (tid * 8) & 63;     // 0,8,..,56

    // ================= phase H: 4 base tiles (h) + 8 agg tiles =================
#pragma unroll
    for (int j = 0; j < 8; j++)
#pragma unroll
        for (int q = 0; q < 4; q++) { accI[j][q] = 0.f; accA[j][q] = 0.f; accT[j][q] = 0.f; }

    for (int t = 0; t < 12; t++) {
        int k0 = t * 32;
        bool isAgg = (t >= 4);
        __syncthreads();
        // stage X
        {
            int n0 = base + xrow;
            __half* xd = Xs + xrow * XP2 + xc0;
            if (n0 < N) {
                if (!isAgg) {
                    const float* rp = h + (size_t)n0 * 128 + k0 + xc0;
#pragma unroll
                    for (int q = 0; q < 4; q++) {
                        float4 a = *(const float4*)(rp + q * 4);
                        *(__half2*)(xd + q * 4)     = __floats2half2_rn(a.x, a.y);
                        *(__half2*)(xd + q * 4 + 2) = __floats2half2_rn(a.z, a.w);
                    }
                } else {
                    const __half* rp = g_aggh + (size_t)n0 * 256 + (k0 - 128) + xc0;
                    *(uint4*)xd       = *(const uint4*)rp;
                    *(uint4*)(xd + 8) = *(const uint4*)(rp + 8);
                }
            } else {
                uint4 z = make_uint4(0, 0, 0, 0);
                *(uint4*)xd = z; *(uint4*)(xd + 8) = z;
            }
        }
        // stage W rails (fp32 -> fp16), 8 elems per thread per rail
        {
            if (isAgg) {
                int aggk = k0 - 128;
                const float* wI = Woh + (size_t)(128 + aggk + wk) * 64 + wn;
                const float* wA = Woh + (size_t)(384 + aggk + wk) * 64 + wn;
                const float* wT = Woh + (size_t)(640 + aggk + wk) * 64 + wn;
                __half* dI = &Ws[0][wk * WP2 + wn];
                __half* dA = &Ws[1][wk * WP2 + wn];
                __half* dT = &Ws[2][wk * WP2 + wn];
#pragma unroll
                for (int q = 0; q < 2; q++) {
                    float4 a = *(const float4*)(wI + q * 4);
                    *(__half2*)(dI + q * 4)     = __floats2half2_rn(a.x, a.y);
                    *(__half2*)(dI + q * 4 + 2) = __floats2half2_rn(a.z, a.w);
                    a = *(const float4*)(wA + q * 4);
                    *(__half2*)(dA + q * 4)     = __floats2half2_rn(a.x, a.y);
                    *(__half2*)(dA + q * 4 + 2) = __floats2half2_rn(a.z, a.w);
                    a = *(const float4*)(wT + q * 4);
                    *(__half2*)(dT + q * 4)     = __floats2half2_rn(a.x, a.y);
                    *(__half2*)(dT + q * 4 + 2) = __floats2half2_rn(a.z, a.w);
                }
            } else {
                const float* wI = Woh + (size_t)(k0 + wk) * 64 + wn;
                __half* dI = &Ws[0][wk * WP2 + wn];
#pragma unroll
                for (int q = 0; q < 2; q++) {
                    float4 a = *(const float4*)(wI + q * 4);
                    *(__half2*)(dI + q * 4)     = __floats2half2_rn(a.x, a.y);
                    *(__half2*)(dI + q * 4 + 2) = __floats2half2_rn(a.z, a.w);
                }
            }
        }
        __syncthreads();
#pragma unroll
        for (int kc = 0; kc < 2; kc++) {
            int arow = slab + r8 + ((mat & 1) ? 8 : 0);
            int acol = kc * 16 + ((mat & 2) ? 8 : 0);
            uint4 a = ldsm_x4(xsb + (unsigned)(arow * XP2 + acol) * 2u);
            int bk = kc * 16 + r8 + ((mat & 1) ? 8 : 0);
#pragma unroll
            for (int j = 0; j < 4; j++) {
                int bn = j * 16 + ((mat & 2) ? 8 : 0);
                unsigned boff = (unsigned)(bk * WP2 + bn) * 2u;
                uint4 bI = ldsm_x4_t(wsb0 + boff);
                mma16816(accI[2 * j],     a, bI.x, bI.y);
                mma16816(accI[2 * j + 1], a, bI.z, bI.w);
                if (isAgg) {
                    uint4 bA = ldsm_x4_t(wsb1 + boff);
                    mma16816(accA[2 * j],     a, bA.x, bA.y);
                    mma16816(accA[2 * j + 1], a, bA.z, bA.w);
                    uint4 bT = ldsm_x4_t(wsb2 + boff);
                    mma16816(accT[2 * j],     a, bT.x, bT.y);
                    mma16816(accT[2 * j + 1], a, bT.z, bT.w);
                }
            }
        }
    }
    // epilogue H + BN partials
    {
        int r0 = slab + (l >> 2);
        int c0l = (l & 3) * 2;
        int n0 = base + r0, n1 = base + r0 + 8;
        bool v0 = n0 < N, v1 = n1 < N;
        float amp0 = s_amp[r0], att0 = s_att[r0], sn0 = s_sn[r0];
        float amp1 = s_amp[r0 + 8], att1 = s_att[r0 + 8], sn1 = s_sn[r0 + 8];
#pragma unroll
        for (int j = 0; j < 8; j++) {
            int col = 8 * j + c0l;
            float b0 = sbias[col], b1 = sbias[col + 1];
            float y00 = (accI[j][0] + amp0 * accA[j][0] + att0 * accT[j][0] + b0) * sn0;
            float y01 = (accI[j][1] + amp0 * accA[j][1] + att0 * accT[j][1] + b1) * sn0;
            float y10 = (accI[j][2] + amp1 * accA[j][2] + att1 * accT[j][2] + b0) * sn1;
            float y11 = (accI[j][3] + amp1 * accA[j][3] + att1 * accT[j][3] + b1) * sn1;
            float ss0 = 0.f, ss1 = 0.f, qq0 = 0.f, qq1 = 0.f;
            if (v0) {
                *(float2*)&out[(size_t)n0 * 64 + col] = make_float2(y00, y01);
                ss0 += y00; ss1 += y01; qq0 += y00 * y00; qq1 += y01 * y01;
            }
            if (v1) {
                *(float2*)&out[(size_t)n1 * 64 + col] = make_float2(y10, y11);
                ss0 += y10; ss1 += y11; qq0 += y10 * y10; qq1 += y11 * y11;
            }
            atomicAdd(&sbn[col], ss0); atomicAdd(&sbn[col + 1], ss1);
            atomicAdd(&sbq[col], qq0); atomicAdd(&sbq[col + 1], qq1);
        }
    }
    __syncthreads();
    if (tid < 64) {
        atomicAdd(&g_bnsum[tid], sbn[tid]);
        atomicAdd(&g_bnsq[tid], sbq[tid]);
        sbias[tid] = bop[tid];
    }

    // ================= phase P: 2 base tiles (p) + 8 agg tiles =================
#pragma unroll
    for (int j = 0; j < 8; j++)
#pragma unroll
        for (int q = 0; q < 4; q++) { accI[j][q] = 0.f; accA[j][q] = 0.f; accT[j][q] = 0.f; }

    for (int t = 0; t < 10; t++) {
        int k0 = t * 32;
        bool isAgg = (t >= 2);
        __syncthreads();
        {
            int n0 = base + xrow;
            __half* xd = Xs + xrow * XP2 + xc0;
            if (n0 < N) {
                if (!isAgg) {
                    const float* rp = p + (size_t)n0 * 64 + k0 + xc0;
#pragma unroll
                    for (int q = 0; q < 4; q++) {
                        float4 a = *(const float4*)(rp + q * 4);
                        *(__half2*)(xd + q * 4)     = __floats2half2_rn(a.x, a.y);
                        *(__half2*)(xd + q * 4 + 2) = __floats2half2_rn(a.z, a.w);
                    }
                } else {
                    const __half* rp = g_aggp + (size_t)n0 * 256 + (k0 - 64) + xc0;
                    *(uint4*)xd       = *(const uint4*)rp;
                    *(uint4*)(xd + 8) = *(const uint4*)(rp + 8);
                }
            } else {
                uint4 z = make_uint4(0, 0, 0, 0);
                *(uint4*)xd = z; *(uint4*)(xd + 8) = z;
            }
        }
        {
            if (isAgg) {
                int aggk = k0 - 64;
                const float* wI = Wop + (size_t)(64 + aggk + wk) * 64 + wn;
                const float* wA = Wop + (size_t)(320 + aggk + wk) * 64 + wn;
                const float* wT = Wop + (size_t)(576 + aggk + wk) * 64 + wn;
                __half* dI = &Ws[0][wk * WP2 + wn];
                __half* dA = &Ws[1][wk * WP2 + wn];
                __half* dT = &Ws[2][wk * WP2 + wn];
#pragma unroll
                for (int q = 0; q < 2; q++) {
                    float4 a = *(const float4*)(wI + q * 4);
                    *(__half2*)(dI + q * 4)     = __floats2half2_rn(a.x, a.y);
                    *(__half2*)(dI + q * 4 + 2) = __floats2half2_rn(a.z, a.w);
                    a = *(const float4*)(wA + q * 4);
                    *(__half2*)(dA + q * 4)     = __floats2half2_rn(a.x, a.y);
                    *(__half2*)(dA + q * 4 + 2) = __floats2half2_rn(a.z, a.w);
                    a = *(const float4*)(wT + q * 4);
                    *(__half2*)(dT + q * 4)     = __floats2half2_rn(a.x, a.y);
                    *(__half2*)(dT + q * 4 + 2) = __floats2half2_rn(a.z, a.w);
                }
            } else {
                const float* wI = Wop + (size_t)(k0 + wk) * 64 + wn;
                __half* dI = &Ws[0][wk * WP2 + wn];
#pragma unroll
                for (int q = 0; q < 2; q++) {
                    float4 a = *(const float4*)(wI + q * 4);
                    *(__half2*)(dI + q * 4)     = __floats2half2_rn(a.x, a.y);
                    *(__half2*)(dI + q * 4 + 2) = __floats2half2_rn(a.z, a.w);
                }
            }
        }
        __syncthreads();
#pragma unroll
        for (int kc = 0; kc < 2; kc++) {
            int arow = slab + r8 + ((mat & 1) ? 8 : 0);
            int acol = kc * 16 + ((mat & 2) ? 8 : 0);
            uint4 a = ldsm_x4(xsb + (unsigned)(arow * XP2 + acol) * 2u);
            int bk = kc * 16 + r8 + ((mat & 1) ? 8 : 0);
#pragma unroll
            for (int j = 0; j < 4; j++) {
                int bn = j * 16 + ((mat & 2) ? 8 : 0);
                unsigned boff = (unsigned)(bk * WP2 + bn) * 2u;
                uint4 bI = ldsm_x4_t(wsb0 + boff);
                mma16816(accI[2 * j],     a, bI.x, bI.y);
                mma16816(accI[2 * j + 1], a, bI.z, bI.w);
                if (isAgg) {
                    uint4 bA = ldsm_x4_t(wsb1 + boff);
                    mma16816(accA[2 * j],     a, bA.x, bA.y);
                    mma16816(accA[2 * j + 1], a, bA.z, bA.w);
                    uint4 bT = ldsm_x4_t(wsb2 + boff);
                    mma16816(accT[2 * j],     a, bT.x, bT.y);
                    mma16816(accT[2 * j + 1], a, bT.z, bT.w);
                }
            }
        }
    }
    // epilogue P
    {
        int r0 = slab + (l >> 2);
        int c0l = (l & 3) * 2;
        int n0 = base + r0, n1 = base + r0 + 8;
        float amp0 = s_amp[r0], att0 = s_att[r0];
        float amp1 = s_amp[r0 + 8], att1 = s_att[r0 + 8];
        float* outp = out + (size_t)N * 64;
#pragma unroll
        for (int j = 0; j < 8; j++) {
            int col = 8 * j + c0l;
            float b0 = sbias[col], b1 = sbias[col + 1];
            float y00 = accI[j][0] + amp0 * accA[j][0] + att0 * accT[j][0] + b0;
            float y01 = accI[j][1] + amp0 * accA[j][1] + att0 * accT[j][1] + b1;
            float y10 = accI[j][2] + amp1 * accA[j][2] + att1 * accT[j][2] + b0;
            float y11 = accI[j][3] + amp1 * accA[j][3] + att1 * accT[j][3] + b1;
            if (n0 < N) *(float2*)&outp[(size_t)n0 * 64 + col] = make_float2(y00, y01);
            if (n1 < N) *(float2*)&outp[(size_t)n1 * 64 + col] = make_float2(y10, y11);
        }
    }
}

// ---------------- batchnorm apply (float4 vectorized) ----------------
__global__ void k_bnapply(float* __restrict__ out,
                          const float* __restrict__ gamma,
                          const float* __restrict__ beta) {
    int i = blockIdx.x * blockDim.x + threadIdx.x;
    if (i >= N * 16) return;
    int f = (i & 15) * 4;
    const float invN = 1.f / (float)N;
    float4 su = *(const float4*)&g_bnsum[f];
    float4 qu = *(const float4*)&g_bnsq[f];
    float4 ga = *(const float4*)&gamma[f];
    float4 be = *(const float4*)&beta[f];
    float4 mu = make_float4(su.x * invN, su.y * invN, su.z * invN, su.w * invN);
    float4 rs = make_float4(
        rsqrtf(qu.x * invN - mu.x * mu.x + EPS_BN),
        rsqrtf(qu.y * invN - mu.y * mu.y + EPS_BN),
        rsqrtf(qu.z * invN - mu.z * mu.z + EPS_BN),
        rsqrtf(qu.w * invN - mu.w * mu.w + EPS_BN));
    float4 x = *(float4*)&out[(size_t)i * 4];
    x.x = (x.x - mu.x) * rs.x * ga.x + be.x;
    x.y = (x.y - mu.y) * rs.y * ga.y + be.y;
    x.z = (x.z - mu.z) * rs.z * ga.z + be.z;
    x.w = (x.w - mu.w) * rs.w * ga.w + be.w;
    *(float4*)&out[(size_t)i * 4] = x;
}

} // namespace

extern "C" void kernel_launch(void* const* d_in, const int* in_sizes, int n_in,
                              void* d_out, int out_size) {
    const float* h     = (const float*)d_in[0];
    const float* p     = (const float*)d_in[1];
    const float* e     = (const float*)d_in[2];
    const int*   src   = (const int*)d_in[3];
    const int*   dst   = (const int*)d_in[4];
    const float* snorm = (const float*)d_in[5];
    const float* Wph   = (const float*)d_in[6];
    const float* bph   = (const float*)d_in[7];
    const float* Wpp   = (const float*)d_in[8];
    const float* bpp   = (const float*)d_in[9];
    const float* Woh   = (const float*)d_in[10];
    const float* boh   = (const float*)d_in[11];
    const float* Wop   = (const float*)d_in[12];
    const float* bop   = (const float*)d_in[13];
    const float* gamma = (const float*)d_in[14];
    const float* beta  = (const float*)d_in[15];
    float* out = (float*)d_out;

    static cudaStream_t s_pre = nullptr, s_edge = nullptr;
    static cudaEvent_t ev_fork = nullptr, ev_pre = nullptr, ev_edge = nullptr;
    if (s_pre == nullptr) {
        cudaStreamCreateWithFlags(&s_pre, cudaStreamNonBlocking);
        cudaStreamCreateWithFlags(&s_edge, cudaStreamNonBlocking);
        cudaEventCreateWithFlags(&ev_fork, cudaEventDisableTiming);
        cudaEventCreateWithFlags(&ev_pre, cudaEventDisableTiming);
        cudaEventCreateWithFlags(&ev_edge, cudaEventDisableTiming);
    }

    cudaEventRecord(ev_fork, 0);
    cudaStreamWaitEvent(s_pre, ev_fork, 0);
    cudaStreamWaitEvent(s_edge, ev_fork, 0);

    k_nodepre<<<(N + 127) / 128, 256, 0, s_pre>>>(h, p, Wph, Wpp);
    cudaEventRecord(ev_pre, s_pre);

    k_edgeE<<<E / 128, 256, 0, s_edge>>>(e, Wph, bph, Wpp, bpp);
    cudaEventRecord(ev_edge, s_edge);

    k_init<<<(N + 255) / 256, 256>>>();
    k_hist<<<(E + 255) / 256, 256>>>(dst);
    k_scan1<<<SCAN_BLOCKS, 1024>>>();
    k_scan2<<<1, 32>>>();
    k_scan3<<<SCAN_BLOCKS, 1024>>>();
    k_scatter<<<(E + 255) / 256, 256>>>(dst, src);

    cudaStreamWaitEvent(0, ev_pre, 0);
    cudaStreamWaitEvent(0, ev_edge, 0);
    k_agg<<<(N * 32 + 255) / 256, 256>>>();
    k_nodegemm<<<(N + 127) / 128, 256>>>(h, p, snorm, Woh, boh, Wop, bop, out);
    k_bnapply<<<(N * 16 + 255) / 256, 256>>>(out, gamma, beta);
}

// round 13
// speedup vs baseline: 2.0902x; 1.0740x over previous
#include <cuda_runtime.h>
#include <cuda_fp16.h>
#include <math.h>

namespace {

constexpr int N = 50000;
constexpr int E = 800000;
constexpr float AVG_D_LOG = 2.8332f;
constexpr float EPS_STD = 1e-5f;
constexpr float EPS_BN = 1e-5f;
constexpr float FLT_BIG = 3.402823466e+38f;
constexpr int SCAN_BLOCKS = (N + 1023) / 1024;   // 49

typedef unsigned long long ull;

__device__ __forceinline__ float4 ldh4(const __half* ptr) {
    uint2 u = *(const uint2*)ptr;
    __half2 lo = *reinterpret_cast<__half2*>(&u.x);
    __half2 hi = *reinterpret_cast<__half2*>(&u.y);
    float2 f01 = __half22float2(lo), f23 = __half22float2(hi);
    return make_float4(f01.x, f01.y, f23.x, f23.y);
}
__device__ __forceinline__ uint4 ldsm_x4(unsigned addr) {
    uint4 r;
    asm volatile("ldmatrix.sync.aligned.m8n8.x4.shared.b16 {%0,%1,%2,%3}, [%4];"
                 : "=r"(r.x), "=r"(r.y), "=r"(r.z), "=r"(r.w) : "r"(addr));
    return r;
}
__device__ __forceinline__ uint4 ldsm_x4_t(unsigned addr) {
    uint4 r;
    asm volatile("ldmatrix.sync.aligned.m8n8.x4.trans.shared.b16 {%0,%1,%2,%3}, [%4];"
                 : "=r"(r.x), "=r"(r.y), "=r"(r.z), "=r"(r.w) : "r"(addr));
    return r;
}
__device__ __forceinline__ void mma16816(float* d, uint4 a, unsigned b0, unsigned b1) {
    asm volatile(
        "mma.sync.aligned.m16n8k16.row.col.f32.f16.f16.f32 "
        "{%0,%1,%2,%3},{%4,%5,%6,%7},{%8,%9},{%0,%1,%2,%3};"
        : "+f"(d[0]), "+f"(d[1]), "+f"(d[2]), "+f"(d[3])
        : "r"(a.x), "r"(a.y), "r"(a.z), "r"(a.w), "r"(b0), "r"(b1));
}

// ---- scratch (device globals: allocation-free contract) ----
__device__ int g_deg[N];
__device__ int g_offs[N + 1];
__device__ int g_cursor[N];
__device__ int g_perm[E];
__device__ int g_srcs[E];
__device__ int g_btot[SCAN_BLOCKS];
__device__ int g_boff[SCAN_BLOCKS];
__device__ __align__(16) __half g_A[(size_t)N * 128];
__device__ __align__(16) __half g_B[(size_t)N * 128];
__device__ __align__(16) __half g_ce[(size_t)E * 128];   // ORIGINAL edge order
__device__ __align__(16) __half g_aggh[(size_t)N * 256]; // fp16 [mean|max|min|std]
__device__ __align__(16) __half g_aggp[(size_t)N * 256];
__device__ float g_amp[N];
__device__ float g_att[N];
__device__ float g_bnsum[64];
__device__ float g_bnsq[64];

// ---------------- init ----------------
__global__ void k_init() {
    int i = blockIdx.x * blockDim.x + threadIdx.x;
    if (i < N) g_deg[i] = 0;
    if (i < 64) { g_bnsum[i] = 0.f; g_bnsq[i] = 0.f; }
}

// ---------------- degree histogram ----------------
__global__ void k_hist(const int* __restrict__ dst) {
    int e = blockIdx.x * blockDim.x + threadIdx.x;
    if (e < E) atomicAdd(&g_deg[dst[e]], 1);
}

// ---------------- multi-block exclusive scan ----------------
__global__ void k_scan1() {
    __shared__ int ws[32];
    int t = threadIdx.x;
    int lane = t & 31, w = t >> 5;
    int base = blockIdx.x * 1024;
    int v = (base + t < N) ? g_deg[base + t] : 0;
    int x = v;
#pragma unroll
    for (int off = 1; off < 32; off <<= 1) {
        int y = __shfl_up_sync(0xffffffffu, x, off);
        if (lane >= off) x += y;
    }
    if (lane == 31) ws[w] = x;
    __syncthreads();
    if (w == 0) {
        int s = ws[lane];
#pragma unroll
        for (int off = 1; off < 32; off <<= 1) {
            int y = __shfl_up_sync(0xffffffffu, s, off);
            if (lane >= off) s += y;
        }
        ws[lane] = s;
    }
    __syncthreads();
    int incl = x + (w > 0 ? ws[w - 1] : 0);
    if (base + t < N) g_offs[base + t] = incl - v;
    if (t == 1023) g_btot[blockIdx.x] = incl;
}

__global__ void k_scan2() {
    if (threadIdx.x == 0) {
        int acc = 0;
        for (int i = 0; i < SCAN_BLOCKS; i++) {
            g_boff[i] = acc;
            acc += g_btot[i];
        }
    }
}

__global__ void k_scan3() {
    int t = threadIdx.x;
    int base = blockIdx.x * 1024;
    int off = g_boff[blockIdx.x];
    if (base + t < N) {
        int v = g_offs[base + t] + off;
        g_offs[base + t] = v;
        g_cursor[base + t] = v;
    }
    if (blockIdx.x == 0 && t == 0) g_offs[N] = E;
}

// ---------------- scatter: counting sort by dst ----------------
__global__ void k_scatter(const int* __restrict__ dst, const int* __restrict__ src) {
    int e = blockIdx.x * blockDim.x + threadIdx.x;
    if (e < E) {
        int pos = atomicAdd(&g_cursor[dst[e]], 1);
        g_perm[pos] = e;
        g_srcs[pos] = src[e];
    }
}

// ---------------- node pre-GEMMs via mma.sync -> fp16 g_A, g_B -------------------
// Block: 128 nodes. Phase h: C[128,128] = h[128,128] @ [W1|W2];  cols<64 -> A, >=64 -> B.
// Phase p: C[128,128] = p[128,64] @ [P1|P2]; same split, offset +64 in A/B rows.
constexpr int XP3 = 40;
constexpr int WP3 = 136;

__global__ void __launch_bounds__(256) k_nodepre(
    const float* __restrict__ h, const float* __restrict__ p,
    const float* __restrict__ Wh, const float* __restrict__ Wp)
{
    __shared__ __align__(16) __half Xs[128 * XP3];
    __shared__ __align__(16) __half Ws[32 * WP3];

    int tid = threadIdx.x;
    int base = blockIdx.x * 128;
    int w = tid >> 5;
    int l = tid & 31;
    int slab = w * 16;
    int r8 = l & 7;
    int mat = l >> 3;

    unsigned xsb = (unsigned)__cvta_generic_to_shared(Xs);
    unsigned wsb = (unsigned)__cvta_generic_to_shared(Ws);

    int xrow = tid >> 1;
    int xc0 = (tid & 1) * 16;
    int wk = tid >> 3;
    int wc0 = (tid & 7) * 16;

    float acc[16][4];

    // =========== phase h: K=128 (4 k-tiles) ===========
#pragma unroll
    for (int j = 0; j < 16; j++)
#pragma unroll
        for (int q = 0; q < 4; q++) acc[j][q] = 0.f;

    for (int t = 0; t < 4; t++) {
        int k0 = t * 32;
        if (t) __syncthreads();
        {
            int n0 = base + xrow;
            __half* xd = Xs + xrow * XP3 + xc0;
            if (n0 < N) {
                const float* rp = h + (size_t)n0 * 128 + k0 + xc0;
#pragma unroll
                for (int q = 0; q < 4; q++) {
                    float4 a = *(const float4*)(rp + q * 4);
                    *(__half2*)(xd + q * 4)     = __floats2half2_rn(a.x, a.y);
                    *(__half2*)(xd + q * 4 + 2) = __floats2half2_rn(a.z, a.w);
                }
            } else {
                uint4 z = make_uint4(0, 0, 0, 0);
                *(uint4*)xd = z; *(uint4*)(xd + 8) = z;
            }
        }
        {
            const float* wr = (wc0 < 64) ? (Wh + (size_t)(k0 + wk) * 64 + wc0)
                                         : (Wh + (size_t)(128 + k0 + wk) * 64 + (wc0 - 64));
            __half* wd = Ws + wk * WP3 + wc0;
#pragma unroll
            for (int q = 0; q < 4; q++) {
                float4 a = *(const float4*)(wr + q * 4);
                *(__half2*)(wd + q * 4)     = __floats2half2_rn(a.x, a.y);
                *(__half2*)(wd + q * 4 + 2) = __floats2half2_rn(a.z, a.w);
            }
        }
        __syncthreads();
#pragma unroll
        for (int kc = 0; kc < 2; kc++) {
            int arow = slab + r8 + ((mat & 1) ? 8 : 0);
            int acol = kc * 16 + ((mat & 2) ? 8 : 0);
            uint4 a = ldsm_x4(xsb + (unsigned)(arow * XP3 + acol) * 2u);
            int bk = kc * 16 + r8 + ((mat & 1) ? 8 : 0);
#pragma unroll
            for (int j = 0; j < 8; j++) {
                int bn = j * 16 + ((mat & 2) ? 8 : 0);
                uint4 b = ldsm_x4_t(wsb + (unsigned)(bk * WP3 + bn) * 2u);
                mma16816(acc[2 * j],     a, b.x, b.y);
                mma16816(acc[2 * j + 1], a, b.z, b.w);
            }
        }
    }
    {
        int r0 = slab + (l >> 2);
        int c0 = (l & 3) * 2;
        int n0 = base + r0, n1 = base + r0 + 8;
        bool v0 = n0 < N, v1 = n1 < N;
#pragma unroll
        for (int j = 0; j < 16; j++) {
            int col = 8 * j + c0;
            __half* d0;
            __half* d1;
            if (col < 64) {
                d0 = g_A + (size_t)n0 * 128 + col;
                d1 = g_A + (size_t)n1 * 128 + col;
            } else {
                d0 = g_B + (size_t)n0 * 128 + (col - 64);
                d1 = g_B + (size_t)n1 * 128 + (col - 64);
            }
            if (v0) *(__half2*)d0 = __floats2half2_rn(acc[j][0], acc[j][1]);
            if (v1) *(__half2*)d1 = __floats2half2_rn(acc[j][2], acc[j][3]);
        }
    }

    // =========== phase p: K=64 (2 k-tiles) ===========
#pragma unroll
    for (int j = 0; j < 16; j++)
#pragma unroll
        for (int q = 0; q < 4; q++) acc[j][q] = 0.f;

    for (int t = 0; t < 2; t++) {
        int k0 = t * 32;
        __syncthreads();
        {
            int n0 = base + xrow;
            __half* xd = Xs + xrow * XP3 + xc0;
            if (n0 < N) {
                const float* rp = p + (size_t)n0 * 64 + k0 + xc0;
#pragma unroll
                for (int q = 0; q < 4; q++) {
                    float4 a = *(const float4*)(rp + q * 4);
                    *(__half2*)(xd + q * 4)     = __floats2half2_rn(a.x, a.y);
                    *(__half2*)(xd + q * 4 + 2) = __floats2half2_rn(a.z, a.w);
                }
            } else {
                uint4 z = make_uint4(0, 0, 0, 0);
                *(uint4*)xd = z; *(uint4*)(xd + 8) = z;
            }
        }
        {
            const float* wr = (wc0 < 64) ? (Wp + (size_t)(k0 + wk) * 64 + wc0)
                                         : (Wp + (size_t)(64 + k0 + wk) * 64 + (wc0 - 64));
            __half* wd = Ws + wk * WP3 + wc0;
#pragma unroll
            for (int q = 0; q < 4; q++) {
                float4 a = *(const float4*)(wr + q * 4);
                *(__half2*)(wd + q * 4)     = __floats2half2_rn(a.x, a.y);
                *(__half2*)(wd + q * 4 + 2) = __floats2half2_rn(a.z, a.w);
            }
        }
        __syncthreads();
#pragma unroll
        for (int kc = 0; kc < 2; kc++) {
            int arow = slab + r8 + ((mat & 1) ? 8 : 0);
            int acol = kc * 16 + ((mat & 2) ? 8 : 0);
            uint4 a = ldsm_x4(xsb + (unsigned)(arow * XP3 + acol) * 2u);
            int bk = kc * 16 + r8 + ((mat & 1) ? 8 : 0);
#pragma unroll
            for (int j = 0; j < 8; j++) {
                int bn = j * 16 + ((mat & 2) ? 8 : 0);
                uint4 b = ldsm_x4_t(wsb + (unsigned)(bk * WP3 + bn) * 2u);
                mma16816(acc[2 * j],     a, b.x, b.y);
                mma16816(acc[2 * j + 1], a, b.z, b.w);
            }
        }
    }
    {
        int r0 = slab + (l >> 2);
        int c0 = (l & 3) * 2;
        int n0 = base + r0, n1 = base + r0 + 8;
        bool v0 = n0 < N, v1 = n1 < N;
#pragma unroll
        for (int j = 0; j < 16; j++) {
            int col = 8 * j + c0;
            __half* d0;
            __half* d1;
            if (col < 64) {
                d0 = g_A + (size_t)n0 * 128 + 64 + col;
                d1 = g_A + (size_t)n1 * 128 + 64 + col;
            } else {
                d0 = g_B + (size_t)n0 * 128 + col;       // 64 + (col-64)
                d1 = g_B + (size_t)n1 * 128 + col;
            }
            if (v0) *(__half2*)d0 = __floats2half2_rn(acc[j][0], acc[j][1]);
            if (v1) *(__half2*)d1 = __floats2half2_rn(acc[j][2], acc[j][3]);
        }
    }
}

// ---------------- edge-feature GEMM via mma.sync (tensor cores) ------------------
constexpr int XP = 40;
constexpr int WP = 136;

__global__ void __launch_bounds__(256) k_edgeE(
    const float* __restrict__ ef,
    const float* __restrict__ Wh, const float* __restrict__ bh,
    const float* __restrict__ Wp, const float* __restrict__ bp)
{
    __shared__ __align__(16) __half Xs[128 * XP];
    __shared__ __align__(16) __half Ws[32 * WP];
    __shared__ float bias[128];

    int tid = threadIdx.x;
    int base = blockIdx.x * 128;
    int w = tid >> 5;
    int l = tid & 31;

    {
        int row = tid >> 1;
        int c0 = (tid & 1) * 16;
        const float* rowp = ef + (size_t)(base + row) * 32 + c0;
        __half* xd = Xs + row * XP + c0;
#pragma unroll
        for (int q = 0; q < 4; q++) {
            float4 a = *(const float4*)(rowp + q * 4);
            *(__half2*)(xd + q * 4)     = __floats2half2_rn(a.x, a.y);
            *(__half2*)(xd + q * 4 + 2) = __floats2half2_rn(a.z, a.w);
        }
    }
    {
        int k = tid >> 3;
        int c0 = (tid & 7) * 16;
        const float* wr = (c0 < 64) ? (Wh + (size_t)(256 + k) * 64 + c0)
                                    : (Wp + (size_t)(128 + k) * 64 + (c0 - 64));
        __half* wd = Ws + k * WP + c0;
#pragma unroll
        for (int q = 0; q < 4; q++) {
            float4 a = *(const float4*)(wr + q * 4);
            *(__half2*)(wd + q * 4)     = __floats2half2_rn(a.x, a.y);
            *(__half2*)(wd + q * 4 + 2) = __floats2half2_rn(a.z, a.w);
        }
    }
    if (tid < 128) bias[tid] = (tid < 64) ? bh[tid] : bp[tid - 64];
    __syncthreads();

    float acc[16][4];
#pragma unroll
    for (int j = 0; j < 16; j++)
#pragma unroll
        for (int q = 0; q < 4; q++) acc[j][q] = 0.f;

    int slab = w * 16;
    int r8 = l & 7;
    int mat = l >> 3;

    unsigned xsbase = (unsigned)__cvta_generic_to_shared(Xs);
    unsigned wsbase = (unsigned)__cvta_generic_to_shared(Ws);

#pragma unroll
    for (int kc = 0; kc < 2; kc++) {
        int arow = slab + r8 + ((mat & 1) ? 8 : 0);
        int acol = kc * 16 + ((mat & 2) ? 8 : 0);
        uint4 a = ldsm_x4(xsbase + (unsigned)(arow * XP + acol) * 2u);
#pragma unroll
        for (int j = 0; j < 8; j++) {
            int bk = kc * 16 + r8 + ((mat & 1) ? 8 : 0);
            int bn = j * 16 + ((mat & 2) ? 8 : 0);
            uint4 b = ldsm_x4_t(wsbase + (unsigned)(bk * WP + bn) * 2u);
            mma16816(acc[2 * j],     a, b.x, b.y);
            mma16816(acc[2 * j + 1], a, b.z, b.w);
        }
    }

    int r0 = slab + (l >> 2);
    int c0 = (l & 3) * 2;
    __half* out0 = g_ce + (size_t)(base + r0) * 128;
    __half* out1 = g_ce + (size_t)(base + r0 + 8) * 128;
#pragma unroll
    for (int j = 0; j < 16; j++) {
        int col = 8 * j + c0;
        float bz0 = bias[col], bz1 = bias[col + 1];
        *(__half2*)(out0 + col) = __floats2half2_rn(acc[j][0] + bz0, acc[j][1] + bz1);
        *(__half2*)(out1 + col) = __floats2half2_rn(acc[j][2] + bz0, acc[j][3] + bz1);
    }
}

// ---------------- fused message + PNA aggregation (fp16 agg out) ----------------
__global__ void k_agg() {
    int warp = (blockIdx.x * blockDim.x + threadIdx.x) >> 5;
    int l = threadIdx.x & 31;
    if (warp >= N) return;
    int n = warp;
    int s0 = g_offs[n];
    int s1 = g_offs[n + 1];
    int d = s1 - s0;

    int off4 = 4 * l;
    float4 bv = ldh4(g_B + (size_t)n * 128 + off4);

    float4 sm = make_float4(0.f, 0.f, 0.f, 0.f);
    float4 sq = make_float4(0.f, 0.f, 0.f, 0.f);
    float4 mx = make_float4(-FLT_BIG, -FLT_BIG, -FLT_BIG, -FLT_BIG);
    float4 mn = make_float4(FLT_BIG, FLT_BIG, FLT_BIG, FLT_BIG);

#define AGG_ACC(CV, AV)                                                          \
    do {                                                                         \
        float v0 = (CV).x + (AV).x + bv.x;                                       \
        float v1 = (CV).y + (AV).y + bv.y;                                       \
        float v2 = (CV).z + (AV).z + bv.z;                                       \
        float v3 = (CV).w + (AV).w + bv.w;                                       \
        sm.x += v0; sq.x += v0 * v0; mx.x = fmaxf(mx.x, v0); mn.x = fminf(mn.x, v0); \
        sm.y += v1; sq.y += v1 * v1; mx.y = fmaxf(mx.y, v1); mn.y = fminf(mn.y, v1); \
        sm.z += v2; sq.z += v2 * v2; mx.z = fmaxf(mx.z, v2); mn.z = fminf(mn.z, v2); \
        sm.w += v3; sq.w += v3 * v3; mx.w = fmaxf(mx.w, v3); mn.w = fminf(mn.w, v3); \
    } while (0)

    int i = s0;
    if ((s1 - s0) & 1) {
        int s = g_srcs[i];
        int eid = g_perm[i];
        float4 cv = ldh4(g_ce + (size_t)eid * 128 + off4);
        float4 av = ldh4(g_A + (size_t)s * 128 + off4);
        AGG_ACC(cv, av);
        i++;
    }
    for (; i < s1; i += 2) {
        int sA = g_srcs[i],   sB = g_srcs[i + 1];
        int eA = g_perm[i],   eB = g_perm[i + 1];
        uint2 uCA = *(const uint2*)(g_ce + (size_t)eA * 128 + off4);
        uint2 uAA = *(const uint2*)(g_A + (size_t)sA * 128 + off4);
        uint2 uCB = *(const uint2*)(g_ce + (size_t)eB * 128 + off4);
        uint2 uAB = *(const uint2*)(g_A + (size_t)sB * 128 + off4);
        {
            __half2 lo = *reinterpret_cast<__half2*>(&uCA.x);
            __half2 hi = *reinterpret_cast<__half2*>(&uCA.y);
            float2 c01 = __half22float2(lo), c23 = __half22float2(hi);
            lo = *reinterpret_cast<__half2*>(&uAA.x);
            hi = *reinterpret_cast<__half2*>(&uAA.y);
            float2 a01 = __half22float2(lo), a23 = __half22float2(hi);
            float4 cv = make_float4(c01.x, c01.y, c23.x, c23.y);
            float4 av = make_float4(a01.x, a01.y, a23.x, a23.y);
            AGG_ACC(cv, av);
        }
        {
            __half2 lo = *reinterpret_cast<__half2*>(&uCB.x);
            __half2 hi = *reinterpret_cast<__half2*>(&uCB.y);
            float2 c01 = __half22float2(lo), c23 = __half22float2(hi);
            lo = *reinterpret_cast<__half2*>(&uAB.x);
            hi = *reinterpret_cast<__half2*>(&uAB.y);
            float2 a01 = __half22float2(lo), a23 = __half22float2(hi);
            float4 cv = make_float4(c01.x, c01.y, c23.x, c23.y);
            float4 av = make_float4(a01.x, a01.y, a23.x, a23.y);
            AGG_ACC(cv, av);
        }
    }
#undef AGG_ACC

    float degc = fmaxf((float)d, 1.f);
    float inv = 1.f / degc;
    bool has = d > 0;
    float logd = has ? logf((float)d + 1.f) : 1.f;
    float amp = logd / AVG_D_LOG;
    float att = AVG_D_LOG / logd;
    if (l == 0) { g_amp[n] = amp; g_att[n] = att; }

    __half* o = (off4 < 64) ? (g_aggh + (size_t)n * 256) : (g_aggp + (size_t)n * 256);
    int f = off4 & 63;

    float4 mean = make_float4(sm.x * inv, sm.y * inv, sm.z * inv, sm.w * inv);
    float4 var = make_float4(fmaxf(sq.x * inv - mean.x * mean.x, 0.f),
                             fmaxf(sq.y * inv - mean.y * mean.y, 0.f),
                             fmaxf(sq.z * inv - mean.z * mean.z, 0.f),
                             fmaxf(sq.w * inv - mean.w * mean.w, 0.f));
    float4 sd = make_float4(sqrtf(var.x + EPS_STD), sqrtf(var.y + EPS_STD),
                            sqrtf(var.z + EPS_STD), sqrtf(var.w + EPS_STD));
    float4 MX = has ? mx : make_float4(0.f, 0.f, 0.f, 0.f);
    float4 MN = has ? mn : make_float4(0.f, 0.f, 0.f, 0.f);
    *(__half2*)(o + f)       = __floats2half2_rn(mean.x, mean.y);
    *(__half2*)(o + f + 2)   = __floats2half2_rn(mean.z, mean.w);
    *(__half2*)(o + 64 + f)     = __floats2half2_rn(MX.x, MX.y);
    *(__half2*)(o + 64 + f + 2) = __floats2half2_rn(MX.z, MX.w);
    *(__half2*)(o + 128 + f)     = __floats2half2_rn(MN.x, MN.y);
    *(__half2*)(o + 128 + f + 2) = __floats2half2_rn(MN.z, MN.w);
    *(__half2*)(o + 192 + f)     = __floats2half2_rn(sd.x, sd.y);
    *(__half2*)(o + 192 + f + 2) = __floats2half2_rn(sd.z, sd.w);
}

// ---------------- node GEMMs via mma.sync: 3 rails + fused BN stats -------------
constexpr int XP2 = 40;
constexpr int WP2 = 72;

__global__ void __launch_bounds__(256) k_nodegemm(
    const float* __restrict__ h, const float* __restrict__ p,
    const float* __restrict__ snorm,
    const float* __restrict__ Woh, const float* __restrict__ boh,
    const float* __restrict__ Wop, const float* __restrict__ bop,
    float* __restrict__ out)
{
    __shared__ __align__(16) __half Xs[128 * XP2];
    __shared__ __align__(16) __half Ws[3][32 * WP2];
    __shared__ float sbias[64];
    __shared__ float s_amp[128], s_att[128], s_sn[128];
    __shared__ float sbn[64], sbq[64];

    int tid = threadIdx.x;
    int base = blockIdx.x * 128;
    int w = tid >> 5;
    int l = tid & 31;
    int slab = w * 16;
    int r8 = l & 7;
    int mat = l >> 3;

    if (tid < 128) {
        int n0 = base + tid;
        bool ok = n0 < N;
        s_amp[tid] = ok ? g_amp[n0] : 0.f;
        s_att[tid] = ok ? g_att[n0] : 0.f;
        s_sn[tid]  = ok ? snorm[n0] : 0.f;
    }
    if (tid < 64) { sbn[tid] = 0.f; sbq[tid] = 0.f; sbias[tid] = boh[tid]; }

    unsigned xsb = (unsigned)__cvta_generic_to_shared(Xs);
    unsigned wsb0 = (unsigned)__cvta_generic_to_shared(&Ws[0][0]);
    unsigned wsb1 = (unsigned)__cvta_generic_to_shared(&Ws[1][0]);
    unsigned wsb2 = (unsigned)__cvta_generic_to_shared(&Ws[2][0]);

    float accI[8][4], accA[8][4], accT[8][4];

    int xrow = tid >> 1;
    int xc0 = (tid & 1) * 16;
    int wk = (tid * 8) >> 6;
    int wn = (tid * 8) & 63;

    // ================= phase H =================
#pragma unroll
    for (int j = 0; j < 8; j++)
#pragma unroll
        for (int q = 0; q < 4; q++) { accI[j][q] = 0.f; accA[j][q] = 0.f; accT[j][q] = 0.f; }

    for (int t = 0; t < 12; t++) {
        int k0 = t * 32;
        bool isAgg = (t >= 4);
        __syncthreads();
        {
            int n0 = base + xrow;
            __half* xd = Xs + xrow * XP2 + xc0;
            if (n0 < N) {
                if (!isAgg) {
                    const float* rp = h + (size_t)n0 * 128 + k0 + xc0;
#pragma unroll
                    for (int q = 0; q < 4; q++) {
                        float4 a = *(const float4*)(rp + q * 4);
                        *(__half2*)(xd + q * 4)     = __floats2half2_rn(a.x, a.y);
                        *(__half2*)(xd + q * 4 + 2) = __floats2half2_rn(a.z, a.w);
                    }
                } else {
                    const __half* rp = g_aggh + (size_t)n0 * 256 + (k0 - 128) + xc0;
                    *(uint4*)xd       = *(const uint4*)rp;
                    *(uint4*)(xd + 8) = *(const uint4*)(rp + 8);
                }
            } else {
                uint4 z = make_uint4(0, 0, 0, 0);
                *(uint4*)xd = z; *(uint4*)(xd + 8) = z;
            }
        }
        {
            if (isAgg) {
                int aggk = k0 - 128;
                const float* wI = Woh + (size_t)(128 + aggk + wk) * 64 + wn;
                const float* wA = Woh + (size_t)(384 + aggk + wk) * 64 + wn;
                const float* wT = Woh + (size_t)(640 + aggk + wk) * 64 + wn;
                __half* dI = &Ws[0][wk * WP2 + wn];
                __half* dA = &Ws[1][wk * WP2 + wn];
                __half* dT = &Ws[2][wk * WP2 + wn];
#pragma unroll
                for (int q = 0; q < 2; q++) {
                    float4 a = *(const float4*)(wI + q * 4);
                    *(__half2*)(dI + q * 4)     = __floats2half2_rn(a.x, a.y);
                    *(__half2*)(dI + q * 4 + 2) = __floats2half2_rn(a.z, a.w);
                    a = *(const float4*)(wA + q * 4);
                    *(__half2*)(dA + q * 4)     = __floats2half2_rn(a.x, a.y);
                    *(__half2*)(dA + q * 4 + 2) = __floats2half2_rn(a.z, a.w);
                    a = *(const float4*)(wT + q * 4);
                    *(__half2*)(dT + q * 4)     = __floats2half2_rn(a.x, a.y);
                    *(__half2*)(dT + q * 4 + 2) = __floats2half2_rn(a.z, a.w);
                }
            } else {
                const float* wI = Woh + (size_t)(k0 + wk) * 64 + wn;
                __half* dI = &Ws[0][wk * WP2 + wn];
#pragma unroll
                for (int q = 0; q < 2; q++) {
                    float4 a = *(const float4*)(wI + q * 4);
                    *(__half2*)(dI + q * 4)     = __floats2half2_rn(a.x, a.y);
                    *(__half2*)(dI + q * 4 + 2) = __floats2half2_rn(a.z, a.w);
                }
            }
        }
        __syncthreads();
#pragma unroll
        for (int kc = 0; kc < 2; kc++) {
            int arow = slab + r8 + ((mat & 1) ? 8 : 0);
            int acol = kc * 16 + ((mat & 2) ? 8 : 0);
            uint4 a = ldsm_x4(xsb + (unsigned)(arow * XP2 + acol) * 2u);
            int bk = kc * 16 + r8 + ((mat & 1) ? 8 : 0);
#pragma unroll
            for (int j = 0; j < 4; j++) {
                int bn = j * 16 + ((mat & 2) ? 8 : 0);
                unsigned boff = (unsigned)(bk * WP2 + bn) * 2u;
                uint4 bI = ldsm_x4_t(wsb0 + boff);
                mma16816(accI[2 * j],     a, bI.x, bI.y);
                mma16816(accI[2 * j + 1], a, bI.z, bI.w);
                if (isAgg) {
                    uint4 bA = ldsm_x4_t(wsb1 + boff);
                    mma16816(accA[2 * j],     a, bA.x, bA.y);
                    mma16816(accA[2 * j + 1], a, bA.z, bA.w);
                    uint4 bT = ldsm_x4_t(wsb2 + boff);
                    mma16816(accT[2 * j],     a, bT.x, bT.y);
                    mma16816(accT[2 * j + 1], a, bT.z, bT.w);
                }
            }
        }
    }
    {
        int r0 = slab + (l >> 2);
        int c0l = (l & 3) * 2;
        int n0 = base + r0, n1 = base + r0 + 8;
        bool v0 = n0 < N, v1 = n1 < N;
        float amp0 = s_amp[r0], att0 = s_att[r0], sn0 = s_sn[r0];
        float amp1 = s_amp[r0 + 8], att1 = s_att[r0 + 8], sn1 = s_sn[r0 + 8];
#pragma unroll
        for (int j = 0; j < 8; j++) {
            int col = 8 * j + c0l;
            float b0 = sbias[col], b1 = sbias[col + 1];
            float y00 = (accI[j][0] + amp0 * accA[j][0] + att0 * accT[j][0] + b0) * sn0;
            float y01 = (accI[j][1] + amp0 * accA[j][1] + att0 * accT[j][1] + b1) * sn0;
            float y10 = (accI[j][2] + amp1 * accA[j][2] + att1 * accT[j][2] + b0) * sn1;
            float y11 = (accI[j][3] + amp1 * accA[j][3] + att1 * accT[j][3] + b1) * sn1;
            float ss0 = 0.f, ss1 = 0.f, qq0 = 0.f, qq1 = 0.f;
            if (v0) {
                *(float2*)&out[(size_t)n0 * 64 + col] = make_float2(y00, y01);
                ss0 += y00; ss1 += y01; qq0 += y00 * y00; qq1 += y01 * y01;
            }
            if (v1) {
                *(float2*)&out[(size_t)n1 * 64 + col] = make_float2(y10, y11);
                ss0 += y10; ss1 += y11; qq0 += y10 * y10; qq1 += y11 * y11;
            }
            atomicAdd(&sbn[col], ss0); atomicAdd(&sbn[col + 1], ss1);
            atomicAdd(&sbq[col], qq0); atomicAdd(&sbq[col + 1], qq1);
        }
    }
    __syncthreads();
    if (tid < 64) {
        atomicAdd(&g_bnsum[tid], sbn[tid]);
        atomicAdd(&g_bnsq[tid], sbq[tid]);
        sbias[tid] = bop[tid];
    }

    // ================= phase P =================
#pragma unroll
    for (int j = 0; j < 8; j++)
#pragma unroll
        for (int q = 0; q < 4; q++) { accI[j][q] = 0.f; accA[j][q] = 0.f; accT[j][q] = 0.f; }

    for (int t = 0; t < 10; t++) {
        int k0 = t * 32;
        bool isAgg = (t >= 2);
        __syncthreads();
        {
            int n0 = base + xrow;
            __half* xd = Xs + xrow * XP2 + xc0;
            if (n0 < N) {
                if (!isAgg) {
                    const float* rp = p + (size_t)n0 * 64 + k0 + xc0;
#pragma unroll
                    for (int q = 0; q < 4; q++) {
                        float4 a = *(const float4*)(rp + q * 4);
                        *(__half2*)(xd + q * 4)     = __floats2half2_rn(a.x, a.y);
                        *(__half2*)(xd + q * 4 + 2) = __floats2half2_rn(a.z, a.w);
                    }
                } else {
                    const __half* rp = g_aggp + (size_t)n0 * 256 + (k0 - 64) + xc0;
                    *(uint4*)xd       = *(const uint4*)rp;
                    *(uint4*)(xd + 8) = *(const uint4*)(rp + 8);
                }
            } else {
                uint4 z = make_uint4(0, 0, 0, 0);
                *(uint4*)xd = z; *(uint4*)(xd + 8) = z;
            }
        }
        {
            if (isAgg) {
                int aggk = k0 - 64;
                const float* wI = Wop + (size_t)(64 + aggk + wk) * 64 + wn;
                const float* wA = Wop + (size_t)(320 + aggk + wk) * 64 + wn;
                const float* wT = Wop + (size_t)(576 + aggk + wk) * 64 + wn;
                __half* dI = &Ws[0][wk * WP2 + wn];
                __half* dA = &Ws[1][wk * WP2 + wn];
                __half* dT = &Ws[2][wk * WP2 + wn];
#pragma unroll
                for (int q = 0; q < 2; q++) {
                    float4 a = *(const float4*)(wI + q * 4);
                    *(__half2*)(dI + q * 4)     = __floats2half2_rn(a.x, a.y);
                    *(__half2*)(dI + q * 4 + 2) = __floats2half2_rn(a.z, a.w);
                    a = *(const float4*)(wA + q * 4);
                    *(__half2*)(dA + q * 4)     = __floats2half2_rn(a.x, a.y);
                    *(__half2*)(dA + q * 4 + 2) = __floats2half2_rn(a.z, a.w);
                    a = *(const float4*)(wT + q * 4);
                    *(__half2*)(dT + q * 4)     = __floats2half2_rn(a.x, a.y);
                    *(__half2*)(dT + q * 4 + 2) = __floats2half2_rn(a.z, a.w);
                }
            } else {
                const float* wI = Wop + (size_t)(k0 + wk) * 64 + wn;
                __half* dI = &Ws[0][wk * WP2 + wn];
#pragma unroll
                for (int q = 0; q < 2; q++) {
                    float4 a = *(const float4*)(wI + q * 4);
                    *(__half2*)(dI + q * 4)     = __floats2half2_rn(a.x, a.y);
                    *(__half2*)(dI + q * 4 + 2) = __floats2half2_rn(a.z, a.w);
                }
            }
        }
        __syncthreads();
#pragma unroll
        for (int kc = 0; kc < 2; kc++) {
            int arow = slab + r8 + ((mat & 1) ? 8 : 0);
            int acol = kc * 16 + ((mat & 2) ? 8 : 0);
            uint4 a = ldsm_x4(xsb + (unsigned)(arow * XP2 + acol) * 2u);
            int bk = kc * 16 + r8 + ((mat & 1) ? 8 : 0);
#pragma unroll
            for (int j = 0; j < 4; j++) {
                int bn = j * 16 + ((mat & 2) ? 8 : 0);
                unsigned boff = (unsigned)(bk * WP2 + bn) * 2u;
                uint4 bI = ldsm_x4_t(wsb0 + boff);
                mma16816(accI[2 * j],     a, bI.x, bI.y);
                mma16816(accI[2 * j + 1], a, bI.z, bI.w);
                if (isAgg) {
                    uint4 bA = ldsm_x4_t(wsb1 + boff);
                    mma16816(accA[2 * j],     a, bA.x, bA.y);
                    mma16816(accA[2 * j + 1], a, bA.z, bA.w);
                    uint4 bT = ldsm_x4_t(wsb2 + boff);
                    mma16816(accT[2 * j],     a, bT.x, bT.y);
                    mma16816(accT[2 * j + 1], a, bT.z, bT.w);
                }
            }
        }
    }
    {
        int r0 = slab + (l >> 2);
        int c0l = (l & 3) * 2;
        int n0 = base + r0, n1 = base + r0 + 8;
        float amp0 = s_amp[r0], att0 = s_att[r0];
        float amp1 = s_amp[r0 + 8], att1 = s_att[r0 + 8];
        float* outp = out + (size_t)N * 64;
#pragma unroll
        for (int j = 0; j < 8; j++) {
            int col = 8 * j + c0l;
            float b0 = sbias[col], b1 = sbias[col + 1];
            float y00 = accI[j][0] + amp0 * accA[j][0] + att0 * accT[j][0] + b0;
            float y01 = accI[j][1] + amp0 * accA[j][1] + att0 * accT[j][1] + b1;
            float y10 = accI[j][2] + amp1 * accA[j][2] + att1 * accT[j][2] + b0;
            float y11 = accI[j][3] + amp1 * accA[j][3] + att1 * accT[j][3] + b1;
            if (n0 < N) *(float2*)&outp[(size_t)n0 * 64 + col] = make_float2(y00, y01);
            if (n1 < N) *(float2*)&outp[(size_t)n1 * 64 + col] = make_float2(y10, y11);
        }
    }
}

// ---------------- batchnorm apply (float4 vectorized) ----------------
__global__ void k_bnapply(float* __restrict__ out,
                          const float* __restrict__ gamma,
                          const float* __restrict__ beta) {
    int i = blockIdx.x * blockDim.x + threadIdx.x;
    if (i >= N * 16) return;
    int f = (i & 15) * 4;
    const float invN = 1.f / (float)N;
    float4 su = *(const float4*)&g_bnsum[f];
    float4 qu = *(const float4*)&g_bnsq[f];
    float4 ga = *(const float4*)&gamma[f];
    float4 be = *(const float4*)&beta[f];
    float4 mu = make_float4(su.x * invN, su.y * invN, su.z * invN, su.w * invN);
    float4 rs = make_float4(
        rsqrtf(qu.x * invN - mu.x * mu.x + EPS_BN),
        rsqrtf(qu.y * invN - mu.y * mu.y + EPS_BN),
        rsqrtf(qu.z * invN - mu.z * mu.z + EPS_BN),
        rsqrtf(qu.w * invN - mu.w * mu.w + EPS_BN));
    float4 x = *(float4*)&out[(size_t)i * 4];
    x.x = (x.x - mu.x) * rs.x * ga.x + be.x;
    x.y = (x.y - mu.y) * rs.y * ga.y + be.y;
    x.z = (x.z - mu.z) * rs.z * ga.z + be.z;
    x.w = (x.w - mu.w) * rs.w * ga.w + be.w;
    *(float4*)&out[(size_t)i * 4] = x;
}

} // namespace

extern "C" void kernel_launch(void* const* d_in, const int* in_sizes, int n_in,
                              void* d_out, int out_size) {
    const float* h     = (const float*)d_in[0];
    const float* p     = (const float*)d_in[1];
    const float* e     = (const float*)d_in[2];
    const int*   src   = (const int*)d_in[3];
    const int*   dst   = (const int*)d_in[4];
    const float* snorm = (const float*)d_in[5];
    const float* Wph   = (const float*)d_in[6];
    const float* bph   = (const float*)d_in[7];
    const float* Wpp   = (const float*)d_in[8];
    const float* bpp   = (const float*)d_in[9];
    const float* Woh   = (const float*)d_in[10];
    const float* boh   = (const float*)d_in[11];
    const float* Wop   = (const float*)d_in[12];
    const float* bop   = (const float*)d_in[13];
    const float* gamma = (const float*)d_in[14];
    const float* beta  = (const float*)d_in[15];
    float* out = (float*)d_out;

    static cudaStream_t s_pre = nullptr, s_edge = nullptr;
    static cudaEvent_t ev_fork = nullptr, ev_pre = nullptr, ev_edge = nullptr;
    if (s_pre == nullptr) {
        cudaStreamCreateWithFlags(&s_pre, cudaStreamNonBlocking);
        cudaStreamCreateWithFlags(&s_edge, cudaStreamNonBlocking);
        cudaEventCreateWithFlags(&ev_fork, cudaEventDisableTiming);
        cudaEventCreateWithFlags(&ev_pre, cudaEventDisableTiming);
        cudaEventCreateWithFlags(&ev_edge, cudaEventDisableTiming);
    }

    cudaEventRecord(ev_fork, 0);
    cudaStreamWaitEvent(s_pre, ev_fork, 0);
    cudaStreamWaitEvent(s_edge, ev_fork, 0);

    k_nodepre<<<(N + 127) / 128, 256, 0, s_pre>>>(h, p, Wph, Wpp);
    cudaEventRecord(ev_pre, s_pre);

    k_edgeE<<<E / 128, 256, 0, s_edge>>>(e, Wph, bph, Wpp, bpp);
    cudaEventRecord(ev_edge, s_edge);

    k_init<<<(N + 255) / 256, 256>>>();
    k_hist<<<(E + 255) / 256, 256>>>(dst);
    k_scan1<<<SCAN_BLOCKS, 1024>>>();
    k_scan2<<<1, 32>>>();
    k_scan3<<<SCAN_BLOCKS, 1024>>>();
    k_scatter<<<(E + 255) / 256, 256>>>(dst, src);

    cudaStreamWaitEvent(0, ev_pre, 0);
    cudaStreamWaitEvent(0, ev_edge, 0);
    k_agg<<<(N * 32 + 255) / 256, 256>>>();
    k_nodegemm<<<(N + 127) / 128, 256>>>(h, p, snorm, Woh, boh, Wop, bop, out);
    k_bnapply<<<(N * 16 + 255) / 256, 256>>>(out, gamma, beta);
}